// round 8
// baseline (speedup 1.0000x reference)
#include <cuda_runtime.h>
#include <cuda_bf16.h>
#include <math.h>
#include <stdint.h>

// Problem constants
#define BB 8
#define MM 4096
#define DD 1024
#define NEXP 64
#define NP 128            // NEXP * PP
#define BM (BB * MM)      // 32768 tokens
#define LOG2E 1.4426950408889634f

static __device__ __constant__ float c_eps = 1e-12f;

// ---- scratch (device globals; no allocation allowed) ----
__device__ __align__(16) __nv_bfloat16 g_phinth[NP * DD];   // phin^T hi [np][d]
__device__ __align__(16) __nv_bfloat16 g_phintl[NP * DD];   // phin^T lo [np][d]
__device__ __align__(16) __nv_bfloat16 g_xh[(size_t)BM * DD];   // x hi [tok][d]
__device__ __align__(16) __nv_bfloat16 g_xl[(size_t)BM * DD];   // x lo
__device__ __align__(16) __nv_bfloat16 g_Eh[(size_t)BM * NP];   // E hi [tok][np]
__device__ __align__(16) __nv_bfloat16 g_El[(size_t)BM * NP];   // E lo
__device__ __align__(16) __nv_bfloat16 g_ysh[BB * NP * DD];     // ys hi [b*NP+np][d]
__device__ __align__(16) __nv_bfloat16 g_ysl[BB * NP * DD];     // ys lo
__device__ float g_part[256 * NP];        // per-mtile column partial sums
__device__ float g_colsum[BB * NP];       // dispatch softmax denominators
__device__ float g_rsinv[BM];             // 1/rowsum (combine denominators)
__device__ float g_xsp[4 * BB * NP * DD]; // partial slot inputs (4 m-segments)

// ============================ helpers =====================================
__device__ __forceinline__ uint32_t smem_u32(const void* p) {
    uint32_t a;
    asm("{ .reg .u64 t; cvta.to.shared.u64 t, %1; cvt.u32.u64 %0, t; }"
        : "=r"(a) : "l"(p));
    return a;
}
__device__ __forceinline__ void cp_async16(uint32_t saddr, const void* gptr) {
    asm volatile("cp.async.cg.shared.global [%0], [%1], 16;"
                 :: "r"(saddr), "l"(gptr));
}
#define CP_COMMIT() asm volatile("cp.async.commit_group;" ::: "memory")
#define CP_WAIT1()  asm volatile("cp.async.wait_group 1;" ::: "memory")
__device__ __forceinline__ void ldsm_x4(uint32_t& r0, uint32_t& r1, uint32_t& r2,
                                        uint32_t& r3, uint32_t a) {
    asm volatile("ldmatrix.sync.aligned.m8n8.x4.shared.b16 {%0,%1,%2,%3}, [%4];"
                 : "=r"(r0), "=r"(r1), "=r"(r2), "=r"(r3) : "r"(a));
}
__device__ __forceinline__ void ldsm_x4t(uint32_t& r0, uint32_t& r1, uint32_t& r2,
                                         uint32_t& r3, uint32_t a) {
    asm volatile("ldmatrix.sync.aligned.m8n8.x4.trans.shared.b16 {%0,%1,%2,%3}, [%4];"
                 : "=r"(r0), "=r"(r1), "=r"(r2), "=r"(r3) : "r"(a));
}
__device__ __forceinline__ void mma_bf16(float* d, const uint32_t* a, const uint32_t* b) {
    asm volatile(
        "mma.sync.aligned.m16n8k16.row.col.f32.bf16.bf16.f32 "
        "{%0,%1,%2,%3}, {%4,%5,%6,%7}, {%8,%9}, {%0,%1,%2,%3};"
        : "+f"(d[0]), "+f"(d[1]), "+f"(d[2]), "+f"(d[3])
        : "r"(a[0]), "r"(a[1]), "r"(a[2]), "r"(a[3]), "r"(b[0]), "r"(b[1]));
}
__device__ __forceinline__ void split1(float v, __nv_bfloat16& h, __nv_bfloat16& l) {
    h = __float2bfloat16_rn(v);
    l = __float2bfloat16_rn(v - __bfloat162float(h));
}
__device__ __forceinline__ float ex2f(float x) {
    float r;
    asm("ex2.approx.f32 %0, %1;" : "=f"(r) : "f"(x));
    return r;
}
__device__ __forceinline__ float warpReduceSum(float v) {
    v += __shfl_down_sync(0xffffffffu, v, 16);
    v += __shfl_down_sync(0xffffffffu, v, 8);
    v += __shfl_down_sync(0xffffffffu, v, 4);
    v += __shfl_down_sync(0xffffffffu, v, 2);
    v += __shfl_down_sync(0xffffffffu, v, 1);
    return v;
}

// ===========================================================================
// K1: phin^T hi/lo
__global__ void k_phinorm(const float* __restrict__ phi, const float* __restrict__ scale) {
    int np = blockIdx.x;
    int t = threadIdx.x;
    float s = 0.f;
    for (int d = t; d < DD; d += 256) {
        float v = phi[d * NP + np];
        s += v * v;
    }
    __shared__ float red[8];
    s = warpReduceSum(s);
    if ((t & 31) == 0) red[t >> 5] = s;
    __syncthreads();
    if (t < 32) {
        float v = (t < 8) ? red[t] : 0.f;
        v = warpReduceSum(v);
        if (t == 0) red[0] = scale[0] / fmaxf(sqrtf(v), c_eps);
    }
    __syncthreads();
    float rn = red[0];
    for (int d = t; d < DD; d += 256) {
        float v = phi[d * NP + np] * rn;
        __nv_bfloat16 h, l;
        split1(v, h, l);
        g_phinth[np * DD + d] = h;
        g_phintl[np * DD + d] = l;
    }
}

// ===========================================================================
// K3 (mma, fused): loads x fp32, converts hi/lo (smem tiles + gmem for k_xs),
// computes per-token rinv in-kernel, E = exp2(dot * rinv * log2e) hi/lo out,
// fused rowsum + column partials. CTA 128m x 128n, K chunks of 32.
#define LDA 40
#define LDXF 36
#define L_XF_ST (128 * LDXF)          // floats per x-fp32 stage
#define L_B_ST (2 * 128 * LDA)        // bf16 per phin stage (hi+lo)
__global__ __launch_bounds__(256, 2) void k_logits_mma(const float* __restrict__ x) {
    extern __shared__ char sm_raw[];
    float* sXf = reinterpret_cast<float*>(sm_raw);                       // 2 stages
    __nv_bfloat16* sB = reinterpret_cast<__nv_bfloat16*>(sm_raw + 2 * L_XF_ST * 4);
    __nv_bfloat16* sAh = sB + 2 * L_B_ST;                                // single buf
    __nv_bfloat16* sAl = sAh + 128 * LDA;
    int t = threadIdx.x, lane = t & 31, wid = t >> 5;
    int tok0 = blockIdx.x * 128;
    int wm = wid & 1, wn = wid >> 1;
    float acc[4][4][4];
    #pragma unroll
    for (int a = 0; a < 4; a++)
        #pragma unroll
        for (int n = 0; n < 4; n++)
            #pragma unroll
            for (int q = 0; q < 4; q++) acc[a][n][q] = 0.f;

    int a_row = lane & 15;
    int a_col = (lane >> 4) * 8;
    int b_row = (lane & 7) + ((lane >> 4) << 3);
    int b_col = ((lane >> 3) & 1) * 8;

    int cr = t >> 1, ch = t & 1;      // conversion: row, 16-elem half
    float sumsq = 0.f;

    #define L_LOAD(c, s) do { \
        float* xdst = sXf + (s) * L_XF_ST; \
        __nv_bfloat16* bdst = sB + (s) * L_B_ST; \
        _Pragma("unroll") \
        for (int i = 0; i < 4; i++) { \
            int idx = t + i * 256; \
            int row = idx >> 3, q = idx & 7; \
            cp_async16(smem_u32(xdst + row * LDXF + q * 4), \
                       &x[(size_t)(tok0 + row) * DD + (c) * 32 + q * 4]); \
        } \
        _Pragma("unroll") \
        for (int i = 0; i < 2; i++) { \
            int idx = t + i * 256; \
            int row = idx >> 2, q = idx & 3; \
            size_t gb = (size_t)row * DD + (c) * 32 + q * 8; \
            cp_async16(smem_u32(bdst + row * LDA + q * 8), &g_phinth[gb]); \
            cp_async16(smem_u32(bdst + 128 * LDA + row * LDA + q * 8), &g_phintl[gb]); \
        } \
    } while (0)

    L_LOAD(0, 0);
    CP_COMMIT();
    for (int c = 0; c < 32; c++) {
        if (c < 31) L_LOAD(c + 1, (c + 1) & 1);
        CP_COMMIT();
        CP_WAIT1();
        __syncthreads();
        // convert x fp32 -> hi/lo: smem A tiles + gmem xh/xl; accumulate sumsq
        {
            const float* xf = sXf + (c & 1) * L_XF_ST + cr * LDXF + ch * 16;
            size_t go = (size_t)(tok0 + cr) * DD + c * 32 + ch * 16;
            #pragma unroll
            for (int g = 0; g < 2; g++) {
                float4 v0 = *reinterpret_cast<const float4*>(xf + g * 8);
                float4 v1 = *reinterpret_cast<const float4*>(xf + g * 8 + 4);
                float v[8] = {v0.x, v0.y, v0.z, v0.w, v1.x, v1.y, v1.z, v1.w};
                uint32_t hs[8], ls[8];
                #pragma unroll
                for (int j = 0; j < 8; j++) {
                    sumsq += v[j] * v[j];
                    __nv_bfloat16 h, l;
                    split1(v[j], h, l);
                    hs[j] = (uint32_t)__bfloat16_as_ushort(h);
                    ls[j] = (uint32_t)__bfloat16_as_ushort(l);
                }
                uint4 hi = {hs[0] | (hs[1] << 16), hs[2] | (hs[3] << 16),
                            hs[4] | (hs[5] << 16), hs[6] | (hs[7] << 16)};
                uint4 lo = {ls[0] | (ls[1] << 16), ls[2] | (ls[3] << 16),
                            ls[4] | (ls[5] << 16), ls[6] | (ls[7] << 16)};
                int so = cr * LDA + ch * 16 + g * 8;
                *reinterpret_cast<uint4*>(&sAh[so]) = hi;
                *reinterpret_cast<uint4*>(&sAl[so]) = lo;
                *reinterpret_cast<uint4*>(&g_xh[go + g * 8]) = hi;
                *reinterpret_cast<uint4*>(&g_xl[go + g * 8]) = lo;
            }
        }
        __syncthreads();
        __nv_bfloat16* sBh = sB + (c & 1) * L_B_ST;
        __nv_bfloat16* sBl = sBh + 128 * LDA;
        #pragma unroll
        for (int ks = 0; ks < 2; ks++) {
            uint32_t ah[4][4], al[4][4], bh[4][2], bl[4][2];
            #pragma unroll
            for (int a = 0; a < 4; a++) {
                int off = (wm * 64 + a * 16 + a_row) * LDA + ks * 16 + a_col;
                ldsm_x4(ah[a][0], ah[a][1], ah[a][2], ah[a][3], smem_u32(&sAh[off]));
                ldsm_x4(al[a][0], al[a][1], al[a][2], al[a][3], smem_u32(&sAl[off]));
            }
            #pragma unroll
            for (int p = 0; p < 2; p++) {
                int off = (wn * 32 + p * 16 + b_row) * LDA + ks * 16 + b_col;
                uint32_t r0, r1, r2, r3;
                ldsm_x4(r0, r1, r2, r3, smem_u32(&sBh[off]));
                bh[p * 2][0] = r0; bh[p * 2][1] = r1;
                bh[p * 2 + 1][0] = r2; bh[p * 2 + 1][1] = r3;
                ldsm_x4(r0, r1, r2, r3, smem_u32(&sBl[off]));
                bl[p * 2][0] = r0; bl[p * 2][1] = r1;
                bl[p * 2 + 1][0] = r2; bl[p * 2 + 1][1] = r3;
            }
            #pragma unroll
            for (int a = 0; a < 4; a++)
                #pragma unroll
                for (int n = 0; n < 4; n++) {
                    mma_bf16(acc[a][n], ah[a], bh[n]);
                    mma_bf16(acc[a][n], ah[a], bl[n]);
                    mma_bf16(acc[a][n], al[a], bh[n]);
                }
        }
        __syncthreads();
    }
    // finalize rinv (2 threads per row)
    float s2 = sumsq + __shfl_xor_sync(0xffffffffu, sumsq, 1);
    __syncthreads();
    float* srinv = reinterpret_cast<float*>(sm_raw);   // [128]
    float* srow = srinv + 128;                          // [4*128]
    float* scol = srow + 512;                           // [2*128]
    if (ch == 0) srinv[cr] = (10.0f / fmaxf(sqrtf(s2), 1e-12f)) * LOG2E;
    __syncthreads();

    // epilogue: exp2, split to bf16 hi/lo; accumulate row/col sums
    int r0 = lane >> 2, c0 = (lane & 3) * 2;
    float rsum[4][2];
    float csum[4][2];
    #pragma unroll
    for (int a = 0; a < 4; a++) { rsum[a][0] = 0.f; rsum[a][1] = 0.f; }
    #pragma unroll
    for (int n = 0; n < 4; n++) { csum[n][0] = 0.f; csum[n][1] = 0.f; }
    #pragma unroll
    for (int a = 0; a < 4; a++) {
        int loc = wm * 64 + a * 16 + r0;
        int row = tok0 + loc;
        float rv0 = srinv[loc];
        float rv1 = srinv[loc + 8];
        #pragma unroll
        for (int n = 0; n < 4; n++) {
            int col = wn * 32 + n * 8 + c0;
            float e0 = ex2f(acc[a][n][0] * rv0), e1 = ex2f(acc[a][n][1] * rv0);
            float e2 = ex2f(acc[a][n][2] * rv1), e3 = ex2f(acc[a][n][3] * rv1);
            rsum[a][0] += e0 + e1;
            rsum[a][1] += e2 + e3;
            csum[n][0] += e0 + e2;
            csum[n][1] += e1 + e3;
            __nv_bfloat16 h0, l0, h1, l1, h2, l2, h3, l3;
            split1(e0, h0, l0); split1(e1, h1, l1);
            split1(e2, h2, l2); split1(e3, h3, l3);
            *reinterpret_cast<__nv_bfloat162*>(&g_Eh[(size_t)row * NP + col]) =
                __halves2bfloat162(h0, h1);
            *reinterpret_cast<__nv_bfloat162*>(&g_El[(size_t)row * NP + col]) =
                __halves2bfloat162(l0, l1);
            *reinterpret_cast<__nv_bfloat162*>(&g_Eh[(size_t)(row + 8) * NP + col]) =
                __halves2bfloat162(h2, h3);
            *reinterpret_cast<__nv_bfloat162*>(&g_El[(size_t)(row + 8) * NP + col]) =
                __halves2bfloat162(l2, l3);
        }
    }
    __syncthreads();
    #pragma unroll
    for (int a = 0; a < 4; a++)
        #pragma unroll
        for (int h = 0; h < 2; h++) {
            float v = rsum[a][h];
            v += __shfl_xor_sync(0xffffffffu, v, 1);
            v += __shfl_xor_sync(0xffffffffu, v, 2);
            if ((lane & 3) == 0)
                srow[wn * 128 + wm * 64 + a * 16 + h * 8 + r0] = v;
        }
    #pragma unroll
    for (int n = 0; n < 4; n++)
        #pragma unroll
        for (int q1 = 0; q1 < 2; q1++) {
            float v = csum[n][q1];
            v += __shfl_xor_sync(0xffffffffu, v, 4);
            v += __shfl_xor_sync(0xffffffffu, v, 8);
            v += __shfl_xor_sync(0xffffffffu, v, 16);
            if (lane < 4)
                scol[wm * 128 + wn * 32 + n * 8 + lane * 2 + q1] = v;
        }
    __syncthreads();
    if (t < 128) {
        float rs = srow[t] + srow[128 + t] + srow[256 + t] + srow[384 + t];
        g_rsinv[tok0 + t] = 1.0f / rs;
        g_part[blockIdx.x * NP + t] = scol[t] + scol[128 + t];
    }
}

// K4: final column sums per batch (32 m-tiles each)
__global__ void k_colsum() {
    int b = blockIdx.x;
    int np = threadIdx.x;
    float s = 0.f;
    #pragma unroll
    for (int i = 0; i < 32; i++)
        s += g_part[(b * 32 + i) * NP + np];
    g_colsum[b * NP + np] = s;
}

// ===========================================================================
// K5 (mma, cp.async 2-stage): xsp[seg][b][np][d] = sum_{m in seg} E[m][np]*x[m][d]
#define LDE 136
#define X_AST (32 * LDE)
#define X_SST (4 * X_AST)
__global__ __launch_bounds__(256) void k_xs_mma() {
    extern __shared__ __nv_bfloat16 sm_x[];
    int t = threadIdx.x, lane = t & 31, wid = t >> 5;
    int d0 = blockIdx.x * 128;
    int b = blockIdx.y;
    int seg = blockIdx.z;
    int base = b * MM + seg * 1024;
    int wm = wid & 1, wn = wid >> 1;
    float acc[4][4][4];
    #pragma unroll
    for (int a = 0; a < 4; a++)
        #pragma unroll
        for (int n = 0; n < 4; n++)
            #pragma unroll
            for (int q = 0; q < 4; q++) acc[a][n][q] = 0.f;

    int aA_col = ((lane >> 3) & 1) * 8;
    int aA_row = (lane & 7) + (lane >> 4) * 8;
    int aB_row = (lane & 7) + ((lane >> 3) & 1) * 8;
    int aB_col = (lane >> 4) * 8;

    #define X_LOAD(c, s) do { \
        __nv_bfloat16* bb_ = sm_x + (s) * X_SST; \
        _Pragma("unroll") \
        for (int i = 0; i < 2; i++) { \
            int idx = t + i * 256; \
            int row = idx >> 4, q = idx & 15; \
            size_t ge = (size_t)(base + (c) * 32 + row) * NP + q * 8; \
            size_t gx = (size_t)(base + (c) * 32 + row) * DD + d0 + q * 8; \
            int so = row * LDE + q * 8; \
            cp_async16(smem_u32(bb_ + so), &g_Eh[ge]); \
            cp_async16(smem_u32(bb_ + X_AST + so), &g_El[ge]); \
            cp_async16(smem_u32(bb_ + 2 * X_AST + so), &g_xh[gx]); \
            cp_async16(smem_u32(bb_ + 3 * X_AST + so), &g_xl[gx]); \
        } \
    } while (0)

    X_LOAD(0, 0);
    CP_COMMIT();
    for (int c = 0; c < 32; c++) {
        if (c < 31) X_LOAD(c + 1, (c + 1) & 1);
        CP_COMMIT();
        CP_WAIT1();
        __syncthreads();
        __nv_bfloat16* sEh = sm_x + (c & 1) * X_SST;
        __nv_bfloat16* sEl = sEh + X_AST;
        __nv_bfloat16* sXh = sEl + X_AST;
        __nv_bfloat16* sXl = sXh + X_AST;
        #pragma unroll
        for (int ks = 0; ks < 2; ks++) {
            uint32_t ah[4][4], al[4][4], bh[4][2], bl[4][2];
            #pragma unroll
            for (int a = 0; a < 4; a++) {
                int npb = wm * 64 + a * 16 + aA_col;
                int off = (ks * 16 + aA_row) * LDE + npb;
                ldsm_x4t(ah[a][0], ah[a][1], ah[a][2], ah[a][3], smem_u32(&sEh[off]));
                ldsm_x4t(al[a][0], al[a][1], al[a][2], al[a][3], smem_u32(&sEl[off]));
            }
            #pragma unroll
            for (int p = 0; p < 2; p++) {
                int nb = wn * 32 + p * 16 + aB_col;
                int off = (ks * 16 + aB_row) * LDE + nb;
                uint32_t r0, r1, r2, r3;
                ldsm_x4t(r0, r1, r2, r3, smem_u32(&sXh[off]));
                bh[p * 2][0] = r0; bh[p * 2][1] = r1;
                bh[p * 2 + 1][0] = r2; bh[p * 2 + 1][1] = r3;
                ldsm_x4t(r0, r1, r2, r3, smem_u32(&sXl[off]));
                bl[p * 2][0] = r0; bl[p * 2][1] = r1;
                bl[p * 2 + 1][0] = r2; bl[p * 2 + 1][1] = r3;
            }
            #pragma unroll
            for (int a = 0; a < 4; a++)
                #pragma unroll
                for (int n = 0; n < 4; n++) {
                    mma_bf16(acc[a][n], ah[a], bh[n]);
                    mma_bf16(acc[a][n], ah[a], bl[n]);
                    mma_bf16(acc[a][n], al[a], bh[n]);
                }
        }
        __syncthreads();
    }
    int r0 = lane >> 2, c0 = (lane & 3) * 2;
    #pragma unroll
    for (int a = 0; a < 4; a++) {
        int np = wm * 64 + a * 16 + r0;
        #pragma unroll
        for (int n = 0; n < 4; n++) {
            int d = d0 + wn * 32 + n * 8 + c0;
            float* dst0 = &g_xsp[(((size_t)seg * BB + b) * NP + np) * DD + d];
            float* dst1 = &g_xsp[(((size_t)seg * BB + b) * NP + np + 8) * DD + d];
            *reinterpret_cast<float2*>(dst0) = make_float2(acc[a][n][0], acc[a][n][1]);
            *reinterpret_cast<float2*>(dst1) = make_float2(acc[a][n][2], acc[a][n][3]);
        }
    }
}

// ===========================================================================
// K6 (mma): ys[(b,p)][e] = sum_d xs[(b,p)][d] * W[n][d][e] + bias[n][e]
// A built in-kernel from 4-segment xsp sum * 1/colsum.
#define LDW 264
#define LDK 72
__global__ __launch_bounds__(256) void k_ys_mma(const float* __restrict__ W,
                                                const float* __restrict__ bias) {
    extern __shared__ __nv_bfloat16 sm_y[];
    __nv_bfloat16* sWh = sm_y;                 // [64 k][LDW]
    __nv_bfloat16* sWl = sWh + 64 * LDW;
    __nv_bfloat16* sAh = sWl + 64 * LDW;       // [16 m][LDK]
    __nv_bfloat16* sAl = sAh + 16 * LDK;
    int t = threadIdx.x, lane = t & 31, wid = t >> 5;
    int nexp = blockIdx.y;
    int e0 = blockIdx.x * 256;
    float acc[4][4];
    #pragma unroll
    for (int n = 0; n < 4; n++)
        #pragma unroll
        for (int q = 0; q < 4; q++) acc[n][q] = 0.f;

    int a_row = lane & 15;
    int a_col = (lane >> 4) * 8;
    int aB_row = (lane & 7) + ((lane >> 3) & 1) * 8;
    int aB_col = (lane >> 4) * 8;

    int arow = t >> 3, aq = t & 7;
    int abb = arow >> 1, ap = arow & 1;
    float ainv = (t < 128) ? 1.0f / g_colsum[abb * NP + nexp * 2 + ap] : 0.f;
    size_t abase = ((size_t)abb * NP + nexp * 2 + ap) * DD + aq * 8;

    for (int c = 0; c < 16; c++) {
        int k0 = c * 64;
        if (t < 128) {
            float v[8];
            {
                const float* s0 = &g_xsp[abase + k0];
                float4 v0 = *reinterpret_cast<const float4*>(s0);
                float4 v1 = *reinterpret_cast<const float4*>(s0 + 4);
                #pragma unroll
                for (int seg = 1; seg < 4; seg++) {
                    const float* ss = &g_xsp[(size_t)seg * BB * NP * DD + abase + k0];
                    float4 w0 = *reinterpret_cast<const float4*>(ss);
                    float4 w1 = *reinterpret_cast<const float4*>(ss + 4);
                    v0.x += w0.x; v0.y += w0.y; v0.z += w0.z; v0.w += w0.w;
                    v1.x += w1.x; v1.y += w1.y; v1.z += w1.z; v1.w += w1.w;
                }
                v[0] = v0.x * ainv; v[1] = v0.y * ainv; v[2] = v0.z * ainv; v[3] = v0.w * ainv;
                v[4] = v1.x * ainv; v[5] = v1.y * ainv; v[6] = v1.z * ainv; v[7] = v1.w * ainv;
            }
            uint32_t hs[8], ls[8];
            #pragma unroll
            for (int j = 0; j < 8; j++) {
                __nv_bfloat16 h, l;
                split1(v[j], h, l);
                hs[j] = (uint32_t)__bfloat16_as_ushort(h);
                ls[j] = (uint32_t)__bfloat16_as_ushort(l);
            }
            uint4 hi = {hs[0] | (hs[1] << 16), hs[2] | (hs[3] << 16),
                        hs[4] | (hs[5] << 16), hs[6] | (hs[7] << 16)};
            uint4 lo = {ls[0] | (ls[1] << 16), ls[2] | (ls[3] << 16),
                        ls[4] | (ls[5] << 16), ls[6] | (ls[7] << 16)};
            *reinterpret_cast<uint4*>(&sAh[arow * LDK + aq * 8]) = hi;
            *reinterpret_cast<uint4*>(&sAl[arow * LDK + aq * 8]) = lo;
        }
        #pragma unroll
        for (int i = 0; i < 8; i++) {
            int idx = t + i * 256;
            int row = idx >> 5, q = idx & 31;
            const float* src = &W[((size_t)nexp * DD + k0 + row) * DD + e0 + q * 8];
            float4 v0 = *reinterpret_cast<const float4*>(src);
            float4 v1 = *reinterpret_cast<const float4*>(src + 4);
            float v[8] = {v0.x, v0.y, v0.z, v0.w, v1.x, v1.y, v1.z, v1.w};
            uint32_t hs[8], ls[8];
            #pragma unroll
            for (int j = 0; j < 8; j++) {
                __nv_bfloat16 h, l;
                split1(v[j], h, l);
                hs[j] = (uint32_t)__bfloat16_as_ushort(h);
                ls[j] = (uint32_t)__bfloat16_as_ushort(l);
            }
            uint4 hi = {hs[0] | (hs[1] << 16), hs[2] | (hs[3] << 16),
                        hs[4] | (hs[5] << 16), hs[6] | (hs[7] << 16)};
            uint4 lo = {ls[0] | (ls[1] << 16), ls[2] | (ls[3] << 16),
                        ls[4] | (ls[5] << 16), ls[6] | (ls[7] << 16)};
            *reinterpret_cast<uint4*>(&sWh[row * LDW + q * 8]) = hi;
            *reinterpret_cast<uint4*>(&sWl[row * LDW + q * 8]) = lo;
        }
        __syncthreads();
        #pragma unroll
        for (int ks = 0; ks < 4; ks++) {
            uint32_t ah[4], al[4], bh[4][2], bl[4][2];
            {
                int off = a_row * LDK + ks * 16 + a_col;
                ldsm_x4(ah[0], ah[1], ah[2], ah[3], smem_u32(&sAh[off]));
                ldsm_x4(al[0], al[1], al[2], al[3], smem_u32(&sAl[off]));
            }
            #pragma unroll
            for (int p = 0; p < 2; p++) {
                int nb = wid * 32 + p * 16 + aB_col;
                int off = (ks * 16 + aB_row) * LDW + nb;
                uint32_t r0, r1, r2, r3;
                ldsm_x4t(r0, r1, r2, r3, smem_u32(&sWh[off]));
                bh[p * 2][0] = r0; bh[p * 2][1] = r1;
                bh[p * 2 + 1][0] = r2; bh[p * 2 + 1][1] = r3;
                ldsm_x4t(r0, r1, r2, r3, smem_u32(&sWl[off]));
                bl[p * 2][0] = r0; bl[p * 2][1] = r1;
                bl[p * 2 + 1][0] = r2; bl[p * 2 + 1][1] = r3;
            }
            #pragma unroll
            for (int n = 0; n < 4; n++) {
                mma_bf16(acc[n], ah, bh[n]);
                mma_bf16(acc[n], ah, bl[n]);
                mma_bf16(acc[n], al, bh[n]);
            }
        }
        __syncthreads();
    }
    int r0 = lane >> 2, c0 = (lane & 3) * 2;
    #pragma unroll
    for (int n = 0; n < 4; n++) {
        int e = e0 + wid * 32 + n * 8 + c0;
        float2 bv = *reinterpret_cast<const float2*>(&bias[nexp * DD + e]);
        #pragma unroll
        for (int h = 0; h < 2; h++) {
            int row = r0 + h * 8;
            int bb = row >> 1, p = row & 1;
            float v0 = acc[n][h * 2 + 0] + bv.x;
            float v1 = acc[n][h * 2 + 1] + bv.y;
            __nv_bfloat16 h0, l0, h1, l1;
            split1(v0, h0, l0); split1(v1, h1, l1);
            size_t o = ((size_t)bb * NP + nexp * 2 + p) * DD + e;
            *reinterpret_cast<__nv_bfloat162*>(&g_ysh[o]) = __halves2bfloat162(h0, h1);
            *reinterpret_cast<__nv_bfloat162*>(&g_ysl[o]) = __halves2bfloat162(l0, l1);
        }
    }
}

// ===========================================================================
// K7 (mma, cp.async 2-stage): y[m][d] = rsinv[m]*sum_np E[m][np]*ys[np][d] + x[m][d]
#define C_ASZ (128 * LDA)
#define C_BSZ (32 * LDE)
#define C_SST (2 * C_ASZ + 2 * C_BSZ)
__global__ __launch_bounds__(256) void k_combine_mma(const float* __restrict__ x,
                                                     float* __restrict__ y) {
    extern __shared__ __nv_bfloat16 sm_c[];
    int t = threadIdx.x, lane = t & 31, wid = t >> 5;
    int b = blockIdx.z;
    int tokbase = b * MM + blockIdx.x * 128;
    int d0 = blockIdx.y * 128;
    int wm = wid & 1, wn = wid >> 1;
    float acc[4][4][4];
    #pragma unroll
    for (int a = 0; a < 4; a++)
        #pragma unroll
        for (int n = 0; n < 4; n++)
            #pragma unroll
            for (int q = 0; q < 4; q++) acc[a][n][q] = 0.f;

    int a_row = lane & 15;
    int a_col = (lane >> 4) * 8;
    int aB_row = (lane & 7) + ((lane >> 3) & 1) * 8;
    int aB_col = (lane >> 4) * 8;

    #define C_LOAD(c, s) do { \
        __nv_bfloat16* base = sm_c + (s) * C_SST; \
        _Pragma("unroll") \
        for (int i = 0; i < 2; i++) { \
            int idx = t + i * 256; \
            int row = idx >> 2, q = idx & 3; \
            size_t ge = (size_t)(tokbase + row) * NP + (c) * 32 + q * 8; \
            int so = row * LDA + q * 8; \
            cp_async16(smem_u32(base + so), &g_Eh[ge]); \
            cp_async16(smem_u32(base + C_ASZ + so), &g_El[ge]); \
            int rowb = idx >> 4, qb = idx & 15; \
            size_t gy = ((size_t)b * NP + (c) * 32 + rowb) * DD + d0 + qb * 8; \
            int sob = rowb * LDE + qb * 8; \
            cp_async16(smem_u32(base + 2 * C_ASZ + sob), &g_ysh[gy]); \
            cp_async16(smem_u32(base + 2 * C_ASZ + C_BSZ + sob), &g_ysl[gy]); \
        } \
    } while (0)

    C_LOAD(0, 0);
    CP_COMMIT();
    for (int c = 0; c < 4; c++) {
        if (c < 3) C_LOAD(c + 1, (c + 1) & 1);
        CP_COMMIT();
        CP_WAIT1();
        __syncthreads();
        __nv_bfloat16* sAh = sm_c + (c & 1) * C_SST;
        __nv_bfloat16* sAl = sAh + C_ASZ;
        __nv_bfloat16* sBh = sAl + C_ASZ;
        __nv_bfloat16* sBl = sBh + C_BSZ;
        #pragma unroll
        for (int ks = 0; ks < 2; ks++) {
            uint32_t ah[4][4], al[4][4], bh[4][2], bl[4][2];
            #pragma unroll
            for (int a = 0; a < 4; a++) {
                int off = (wm * 64 + a * 16 + a_row) * LDA + ks * 16 + a_col;
                ldsm_x4(ah[a][0], ah[a][1], ah[a][2], ah[a][3], smem_u32(&sAh[off]));
                ldsm_x4(al[a][0], al[a][1], al[a][2], al[a][3], smem_u32(&sAl[off]));
            }
            #pragma unroll
            for (int p = 0; p < 2; p++) {
                int nb = wn * 32 + p * 16 + aB_col;
                int off = (ks * 16 + aB_row) * LDE + nb;
                uint32_t r0, r1, r2, r3;
                ldsm_x4t(r0, r1, r2, r3, smem_u32(&sBh[off]));
                bh[p * 2][0] = r0; bh[p * 2][1] = r1;
                bh[p * 2 + 1][0] = r2; bh[p * 2 + 1][1] = r3;
                ldsm_x4t(r0, r1, r2, r3, smem_u32(&sBl[off]));
                bl[p * 2][0] = r0; bl[p * 2][1] = r1;
                bl[p * 2 + 1][0] = r2; bl[p * 2 + 1][1] = r3;
            }
            #pragma unroll
            for (int a = 0; a < 4; a++)
                #pragma unroll
                for (int n = 0; n < 4; n++) {
                    mma_bf16(acc[a][n], ah[a], bh[n]);
                    mma_bf16(acc[a][n], ah[a], bl[n]);
                    mma_bf16(acc[a][n], al[a], bh[n]);
                }
        }
        __syncthreads();
    }
    int r0 = lane >> 2, c0 = (lane & 3) * 2;
    #pragma unroll
    for (int a = 0; a < 4; a++) {
        int m0 = tokbase + wm * 64 + a * 16 + r0;
        float rs0 = g_rsinv[m0];
        float rs1 = g_rsinv[m0 + 8];
        #pragma unroll
        for (int n = 0; n < 4; n++) {
            int d = d0 + wn * 32 + n * 8 + c0;
            size_t i0 = (size_t)m0 * DD + d;
            size_t i1 = (size_t)(m0 + 8) * DD + d;
            float2 xv0 = *reinterpret_cast<const float2*>(&x[i0]);
            float2 xv1 = *reinterpret_cast<const float2*>(&x[i1]);
            *reinterpret_cast<float2*>(&y[i0]) =
                make_float2(acc[a][n][0] * rs0 + xv0.x, acc[a][n][1] * rs0 + xv0.y);
            *reinterpret_cast<float2*>(&y[i1]) =
                make_float2(acc[a][n][2] * rs1 + xv1.x, acc[a][n][3] * rs1 + xv1.y);
        }
    }
}

// ---------------------------------------------------------------------------
extern "C" void kernel_launch(void* const* d_in, const int* in_sizes, int n_in,
                              void* d_out, int out_size) {
    const float* x     = (const float*)d_in[0];  // [8,4096,1024]
    const float* phi   = (const float*)d_in[1];  // [1024,64,2]
    const float* scale = (const float*)d_in[2];  // [1]
    const float* W     = (const float*)d_in[3];  // [64,1024,1024]
    const float* bias  = (const float*)d_in[4];  // [64,1024]
    float* y = (float*)d_out;                    // [8,4096,1024]

    const int smem_logits  = 2 * L_XF_ST * 4 + 2 * L_B_ST * 2 + 2 * 128 * LDA * 2;  // 98304
    const int smem_xs      = 2 * X_SST * 2;                         // 69632
    const int smem_ys      = 2 * 64 * LDW * 2 + 2 * 16 * LDK * 2;   // 72192
    const int smem_combine = 2 * C_SST * 2;                         // 75776
    cudaFuncSetAttribute(k_logits_mma, cudaFuncAttributeMaxDynamicSharedMemorySize, smem_logits);
    cudaFuncSetAttribute(k_xs_mma, cudaFuncAttributeMaxDynamicSharedMemorySize, smem_xs);
    cudaFuncSetAttribute(k_ys_mma, cudaFuncAttributeMaxDynamicSharedMemorySize, smem_ys);
    cudaFuncSetAttribute(k_combine_mma, cudaFuncAttributeMaxDynamicSharedMemorySize, smem_combine);

    k_phinorm<<<NP, 256>>>(phi, scale);
    k_logits_mma<<<BM / 128, 256, smem_logits>>>(x);
    k_colsum<<<BB, NP>>>();
    k_xs_mma<<<dim3(8, BB, 4), 256, smem_xs>>>();
    k_ys_mma<<<dim3(4, NEXP), 256, smem_ys>>>(W, bias);
    k_combine_mma<<<dim3(32, 8, BB), 256, smem_combine>>>(x, y);
}

// round 9
// speedup vs baseline: 1.0065x; 1.0065x over previous
#include <cuda_runtime.h>
#include <cuda_bf16.h>
#include <math.h>
#include <stdint.h>

// Problem constants
#define BB 8
#define MM 4096
#define DD 1024
#define NEXP 64
#define NP 128            // NEXP * PP
#define BM (BB * MM)      // 32768 tokens
#define LOG2E 1.4426950408889634f

static __device__ __constant__ float c_eps = 1e-12f;

// ---- scratch (device globals; no allocation allowed) ----
__device__ __align__(16) __nv_bfloat16 g_phinth[NP * DD];   // phin^T hi [np][d]
__device__ __align__(16) __nv_bfloat16 g_phintl[NP * DD];   // phin^T lo [np][d]
__device__ __align__(16) __nv_bfloat16 g_xh[(size_t)BM * DD];   // x hi [tok][d]
__device__ __align__(16) __nv_bfloat16 g_xl[(size_t)BM * DD];   // x lo
__device__ __align__(16) __nv_bfloat16 g_Eh[(size_t)BM * NP];   // E hi [tok][np]
__device__ __align__(16) __nv_bfloat16 g_El[(size_t)BM * NP];   // E lo
__device__ __align__(16) __nv_bfloat16 g_ysh[BB * NP * DD];     // ys hi [b*NP+np][d]
__device__ __align__(16) __nv_bfloat16 g_ysl[BB * NP * DD];     // ys lo
__device__ float g_rinv[BM];              // per-token (1/TEMP)/max(||x||,eps)
__device__ float g_part[256 * NP];        // per-mtile column partial sums
__device__ float g_colsum[BB * NP];       // dispatch softmax denominators
__device__ float g_rsinv[BM];             // 1/rowsum (combine denominators)
__device__ float g_xsp[4 * BB * NP * DD]; // partial slot inputs (4 m-segments)

// ============================ helpers =====================================
__device__ __forceinline__ uint32_t smem_u32(const void* p) {
    uint32_t a;
    asm("{ .reg .u64 t; cvta.to.shared.u64 t, %1; cvt.u32.u64 %0, t; }"
        : "=r"(a) : "l"(p));
    return a;
}
__device__ __forceinline__ void cp_async16(uint32_t saddr, const void* gptr) {
    asm volatile("cp.async.cg.shared.global [%0], [%1], 16;"
                 :: "r"(saddr), "l"(gptr));
}
#define CP_COMMIT() asm volatile("cp.async.commit_group;" ::: "memory")
#define CP_WAIT1()  asm volatile("cp.async.wait_group 1;" ::: "memory")
__device__ __forceinline__ void ldsm_x4(uint32_t& r0, uint32_t& r1, uint32_t& r2,
                                        uint32_t& r3, uint32_t a) {
    asm volatile("ldmatrix.sync.aligned.m8n8.x4.shared.b16 {%0,%1,%2,%3}, [%4];"
                 : "=r"(r0), "=r"(r1), "=r"(r2), "=r"(r3) : "r"(a));
}
__device__ __forceinline__ void ldsm_x4t(uint32_t& r0, uint32_t& r1, uint32_t& r2,
                                         uint32_t& r3, uint32_t a) {
    asm volatile("ldmatrix.sync.aligned.m8n8.x4.trans.shared.b16 {%0,%1,%2,%3}, [%4];"
                 : "=r"(r0), "=r"(r1), "=r"(r2), "=r"(r3) : "r"(a));
}
__device__ __forceinline__ void mma_bf16(float* d, const uint32_t* a, const uint32_t* b) {
    asm volatile(
        "mma.sync.aligned.m16n8k16.row.col.f32.bf16.bf16.f32 "
        "{%0,%1,%2,%3}, {%4,%5,%6,%7}, {%8,%9}, {%0,%1,%2,%3};"
        : "+f"(d[0]), "+f"(d[1]), "+f"(d[2]), "+f"(d[3])
        : "r"(a[0]), "r"(a[1]), "r"(a[2]), "r"(a[3]), "r"(b[0]), "r"(b[1]));
}
__device__ __forceinline__ void split1(float v, __nv_bfloat16& h, __nv_bfloat16& l) {
    h = __float2bfloat16_rn(v);
    l = __float2bfloat16_rn(v - __bfloat162float(h));
}
__device__ __forceinline__ float ex2f(float x) {
    float r;
    asm("ex2.approx.f32 %0, %1;" : "=f"(r) : "f"(x));
    return r;
}
__device__ __forceinline__ float warpReduceSum(float v) {
    v += __shfl_down_sync(0xffffffffu, v, 16);
    v += __shfl_down_sync(0xffffffffu, v, 8);
    v += __shfl_down_sync(0xffffffffu, v, 4);
    v += __shfl_down_sync(0xffffffffu, v, 2);
    v += __shfl_down_sync(0xffffffffu, v, 1);
    return v;
}

// ===========================================================================
// K1: phin^T hi/lo
__global__ void k_phinorm(const float* __restrict__ phi, const float* __restrict__ scale) {
    int np = blockIdx.x;
    int t = threadIdx.x;
    float s = 0.f;
    for (int d = t; d < DD; d += 256) {
        float v = phi[d * NP + np];
        s += v * v;
    }
    __shared__ float red[8];
    s = warpReduceSum(s);
    if ((t & 31) == 0) red[t >> 5] = s;
    __syncthreads();
    if (t < 32) {
        float v = (t < 8) ? red[t] : 0.f;
        v = warpReduceSum(v);
        if (t == 0) red[0] = scale[0] / fmaxf(sqrtf(v), c_eps);
    }
    __syncthreads();
    float rn = red[0];
    for (int d = t; d < DD; d += 256) {
        float v = phi[d * NP + np] * rn;
        __nv_bfloat16 h, l;
        split1(v, h, l);
        g_phinth[np * DD + d] = h;
        g_phintl[np * DD + d] = l;
    }
}

// K2: row norms + x -> bf16 hi/lo. Warp per token.
__global__ void k_rinv(const float* __restrict__ x) {
    int w = threadIdx.x >> 5;
    int lane = threadIdx.x & 31;
    int tok = blockIdx.x * 8 + w;
    const float4* xr = reinterpret_cast<const float4*>(x + (size_t)tok * DD);
    float s = 0.f;
    #pragma unroll
    for (int i = 0; i < 8; i++) {
        float4 v = xr[lane + i * 32];
        s += v.x * v.x + v.y * v.y + v.z * v.z + v.w * v.w;
        __nv_bfloat16 h0, l0, h1, l1, h2, l2, h3, l3;
        split1(v.x, h0, l0); split1(v.y, h1, l1);
        split1(v.z, h2, l2); split1(v.w, h3, l3);
        size_t off = (size_t)tok * DD + (lane + i * 32) * 4;
        *reinterpret_cast<__nv_bfloat162*>(&g_xh[off])     = __halves2bfloat162(h0, h1);
        *reinterpret_cast<__nv_bfloat162*>(&g_xh[off + 2]) = __halves2bfloat162(h2, h3);
        *reinterpret_cast<__nv_bfloat162*>(&g_xl[off])     = __halves2bfloat162(l0, l1);
        *reinterpret_cast<__nv_bfloat162*>(&g_xl[off + 2]) = __halves2bfloat162(l2, l3);
    }
    s = warpReduceSum(s);
    if (lane == 0) g_rinv[tok] = 10.0f / fmaxf(sqrtf(s), c_eps);  // 1/TEMP
}

// ===========================================================================
// K3 (mma, cp.async 2-stage): E = exp2((x . phin) * rinv * log2e), hi/lo out.
// CTA 128m x 128n, K chunks of 32. Fused rowsum + column partials.
#define LDA 40
#define L_AST (128 * LDA)
#define L_SST (4 * L_AST)
__global__ __launch_bounds__(256) void k_logits_mma() {
    extern __shared__ __nv_bfloat16 sm_l[];
    int t = threadIdx.x, lane = t & 31, wid = t >> 5;
    int tok0 = blockIdx.x * 128;
    int wm = wid & 1, wn = wid >> 1;
    float acc[4][4][4];
    #pragma unroll
    for (int a = 0; a < 4; a++)
        #pragma unroll
        for (int n = 0; n < 4; n++)
            #pragma unroll
            for (int q = 0; q < 4; q++) acc[a][n][q] = 0.f;

    int a_row = lane & 15;
    int a_col = (lane >> 4) * 8;
    int b_row = (lane & 7) + ((lane >> 4) << 3);
    int b_col = ((lane >> 3) & 1) * 8;

    int l_row0 = t >> 2, l_q0 = t & 3;
    int l_row1 = (t + 256) >> 2, l_q1 = (t + 256) & 3;

    #define L_LOAD(c, s) do { \
        __nv_bfloat16* base = sm_l + (s) * L_SST; \
        int rows[2] = {l_row0, l_row1}; \
        int qs[2] = {l_q0, l_q1}; \
        _Pragma("unroll") \
        for (int i = 0; i < 2; i++) { \
            int row = rows[i], q = qs[i]; \
            size_t ga = (size_t)(tok0 + row) * DD + (c) * 32 + q * 8; \
            size_t gb = (size_t)row * DD + (c) * 32 + q * 8; \
            int so = row * LDA + q * 8; \
            cp_async16(smem_u32(base + so), &g_xh[ga]); \
            cp_async16(smem_u32(base + L_AST + so), &g_xl[ga]); \
            cp_async16(smem_u32(base + 2 * L_AST + so), &g_phinth[gb]); \
            cp_async16(smem_u32(base + 3 * L_AST + so), &g_phintl[gb]); \
        } \
    } while (0)

    L_LOAD(0, 0);
    CP_COMMIT();
    for (int c = 0; c < 32; c++) {
        if (c < 31) L_LOAD(c + 1, (c + 1) & 1);
        CP_COMMIT();
        CP_WAIT1();
        __syncthreads();
        __nv_bfloat16* sAh = sm_l + (c & 1) * L_SST;
        __nv_bfloat16* sAl = sAh + L_AST;
        __nv_bfloat16* sBh = sAl + L_AST;
        __nv_bfloat16* sBl = sBh + L_AST;
        #pragma unroll
        for (int ks = 0; ks < 2; ks++) {
            uint32_t ah[4][4], al[4][4], bh[4][2], bl[4][2];
            #pragma unroll
            for (int a = 0; a < 4; a++) {
                int off = (wm * 64 + a * 16 + a_row) * LDA + ks * 16 + a_col;
                ldsm_x4(ah[a][0], ah[a][1], ah[a][2], ah[a][3], smem_u32(&sAh[off]));
                ldsm_x4(al[a][0], al[a][1], al[a][2], al[a][3], smem_u32(&sAl[off]));
            }
            #pragma unroll
            for (int p = 0; p < 2; p++) {
                int off = (wn * 32 + p * 16 + b_row) * LDA + ks * 16 + b_col;
                uint32_t r0, r1, r2, r3;
                ldsm_x4(r0, r1, r2, r3, smem_u32(&sBh[off]));
                bh[p * 2][0] = r0; bh[p * 2][1] = r1;
                bh[p * 2 + 1][0] = r2; bh[p * 2 + 1][1] = r3;
                ldsm_x4(r0, r1, r2, r3, smem_u32(&sBl[off]));
                bl[p * 2][0] = r0; bl[p * 2][1] = r1;
                bl[p * 2 + 1][0] = r2; bl[p * 2 + 1][1] = r3;
            }
            #pragma unroll
            for (int a = 0; a < 4; a++)
                #pragma unroll
                for (int n = 0; n < 4; n++) {
                    mma_bf16(acc[a][n], ah[a], bh[n]);
                    mma_bf16(acc[a][n], ah[a], bl[n]);
                    mma_bf16(acc[a][n], al[a], bh[n]);
                }
        }
        __syncthreads();
    }
    // epilogue: exp2, split to bf16 hi/lo; accumulate row/col sums
    int r0 = lane >> 2, c0 = (lane & 3) * 2;
    float rsum[4][2];
    float csum[4][2];
    #pragma unroll
    for (int a = 0; a < 4; a++) { rsum[a][0] = 0.f; rsum[a][1] = 0.f; }
    #pragma unroll
    for (int n = 0; n < 4; n++) { csum[n][0] = 0.f; csum[n][1] = 0.f; }
    #pragma unroll
    for (int a = 0; a < 4; a++) {
        int row = tok0 + wm * 64 + a * 16 + r0;
        float rv0 = g_rinv[row] * LOG2E;
        float rv1 = g_rinv[row + 8] * LOG2E;
        #pragma unroll
        for (int n = 0; n < 4; n++) {
            int col = wn * 32 + n * 8 + c0;
            float e0 = ex2f(acc[a][n][0] * rv0), e1 = ex2f(acc[a][n][1] * rv0);
            float e2 = ex2f(acc[a][n][2] * rv1), e3 = ex2f(acc[a][n][3] * rv1);
            rsum[a][0] += e0 + e1;
            rsum[a][1] += e2 + e3;
            csum[n][0] += e0 + e2;
            csum[n][1] += e1 + e3;
            __nv_bfloat16 h0, l0, h1, l1, h2, l2, h3, l3;
            split1(e0, h0, l0); split1(e1, h1, l1);
            split1(e2, h2, l2); split1(e3, h3, l3);
            *reinterpret_cast<__nv_bfloat162*>(&g_Eh[(size_t)row * NP + col]) =
                __halves2bfloat162(h0, h1);
            *reinterpret_cast<__nv_bfloat162*>(&g_El[(size_t)row * NP + col]) =
                __halves2bfloat162(l0, l1);
            *reinterpret_cast<__nv_bfloat162*>(&g_Eh[(size_t)(row + 8) * NP + col]) =
                __halves2bfloat162(h2, h3);
            *reinterpret_cast<__nv_bfloat162*>(&g_El[(size_t)(row + 8) * NP + col]) =
                __halves2bfloat162(l2, l3);
        }
    }
    float* srow = reinterpret_cast<float*>(sm_l);   // [4 wn][128 rows]
    float* scol = srow + 4 * 128;                   // [2 wm][128 cols]
    __syncthreads();
    #pragma unroll
    for (int a = 0; a < 4; a++)
        #pragma unroll
        for (int h = 0; h < 2; h++) {
            float v = rsum[a][h];
            v += __shfl_xor_sync(0xffffffffu, v, 1);
            v += __shfl_xor_sync(0xffffffffu, v, 2);
            if ((lane & 3) == 0)
                srow[wn * 128 + wm * 64 + a * 16 + h * 8 + r0] = v;
        }
    #pragma unroll
    for (int n = 0; n < 4; n++)
        #pragma unroll
        for (int q1 = 0; q1 < 2; q1++) {
            float v = csum[n][q1];
            v += __shfl_xor_sync(0xffffffffu, v, 4);
            v += __shfl_xor_sync(0xffffffffu, v, 8);
            v += __shfl_xor_sync(0xffffffffu, v, 16);
            if (lane < 4)
                scol[wm * 128 + wn * 32 + n * 8 + lane * 2 + q1] = v;
        }
    __syncthreads();
    if (t < 128) {
        float rs = srow[t] + srow[128 + t] + srow[256 + t] + srow[384 + t];
        g_rsinv[tok0 + t] = 1.0f / rs;
        g_part[blockIdx.x * NP + t] = scol[t] + scol[128 + t];
    }
}

// K4: final column sums per batch (32 m-tiles each)
__global__ void k_colsum() {
    int b = blockIdx.x;
    int np = threadIdx.x;
    float s = 0.f;
    #pragma unroll
    for (int i = 0; i < 32; i++)
        s += g_part[(b * 32 + i) * NP + np];
    g_colsum[b * NP + np] = s;
}

// ===========================================================================
// K5 (mma, cp.async 3-stage, single barrier/iter):
// xsp[seg][b][np][d] = sum_{m in seg} E[m][np]*x[m][d]
#define LDE 136
#define X_AST (32 * LDE)
#define X_SST (4 * X_AST)
__global__ __launch_bounds__(256, 2) void k_xs_mma() {
    extern __shared__ __nv_bfloat16 sm_x[];
    int t = threadIdx.x, lane = t & 31, wid = t >> 5;
    int d0 = blockIdx.x * 128;
    int b = blockIdx.y;
    int seg = blockIdx.z;
    int base = b * MM + seg * 1024;
    int wm = wid & 1, wn = wid >> 1;
    float acc[4][4][4];
    #pragma unroll
    for (int a = 0; a < 4; a++)
        #pragma unroll
        for (int n = 0; n < 4; n++)
            #pragma unroll
            for (int q = 0; q < 4; q++) acc[a][n][q] = 0.f;

    int aA_col = ((lane >> 3) & 1) * 8;
    int aA_row = (lane & 7) + (lane >> 4) * 8;
    int aB_row = (lane & 7) + ((lane >> 3) & 1) * 8;
    int aB_col = (lane >> 4) * 8;

    #define X_LOAD(c, s) do { \
        __nv_bfloat16* bb_ = sm_x + (s) * X_SST; \
        _Pragma("unroll") \
        for (int i = 0; i < 2; i++) { \
            int idx = t + i * 256; \
            int row = idx >> 4, q = idx & 15; \
            size_t ge = (size_t)(base + (c) * 32 + row) * NP + q * 8; \
            size_t gx = (size_t)(base + (c) * 32 + row) * DD + d0 + q * 8; \
            int so = row * LDE + q * 8; \
            cp_async16(smem_u32(bb_ + so), &g_Eh[ge]); \
            cp_async16(smem_u32(bb_ + X_AST + so), &g_El[ge]); \
            cp_async16(smem_u32(bb_ + 2 * X_AST + so), &g_xh[gx]); \
            cp_async16(smem_u32(bb_ + 3 * X_AST + so), &g_xl[gx]); \
        } \
    } while (0)

    X_LOAD(0, 0);
    CP_COMMIT();
    X_LOAD(1, 1);
    CP_COMMIT();
    for (int c = 0; c < 32; c++) {
        CP_WAIT1();
        __syncthreads();
        if (c + 2 < 32) X_LOAD(c + 2, (c + 2) % 3);
        CP_COMMIT();
        __nv_bfloat16* sEh = sm_x + (c % 3) * X_SST;
        __nv_bfloat16* sEl = sEh + X_AST;
        __nv_bfloat16* sXh = sEl + X_AST;
        __nv_bfloat16* sXl = sXh + X_AST;
        #pragma unroll
        for (int ks = 0; ks < 2; ks++) {
            uint32_t ah[4][4], al[4][4], bh[4][2], bl[4][2];
            #pragma unroll
            for (int a = 0; a < 4; a++) {
                int npb = wm * 64 + a * 16 + aA_col;
                int off = (ks * 16 + aA_row) * LDE + npb;
                ldsm_x4t(ah[a][0], ah[a][1], ah[a][2], ah[a][3], smem_u32(&sEh[off]));
                ldsm_x4t(al[a][0], al[a][1], al[a][2], al[a][3], smem_u32(&sEl[off]));
            }
            #pragma unroll
            for (int p = 0; p < 2; p++) {
                int nb = wn * 32 + p * 16 + aB_col;
                int off = (ks * 16 + aB_row) * LDE + nb;
                uint32_t r0, r1, r2, r3;
                ldsm_x4t(r0, r1, r2, r3, smem_u32(&sXh[off]));
                bh[p * 2][0] = r0; bh[p * 2][1] = r1;
                bh[p * 2 + 1][0] = r2; bh[p * 2 + 1][1] = r3;
                ldsm_x4t(r0, r1, r2, r3, smem_u32(&sXl[off]));
                bl[p * 2][0] = r0; bl[p * 2][1] = r1;
                bl[p * 2 + 1][0] = r2; bl[p * 2 + 1][1] = r3;
            }
            #pragma unroll
            for (int a = 0; a < 4; a++)
                #pragma unroll
                for (int n = 0; n < 4; n++) {
                    mma_bf16(acc[a][n], ah[a], bh[n]);
                    mma_bf16(acc[a][n], ah[a], bl[n]);
                    mma_bf16(acc[a][n], al[a], bh[n]);
                }
        }
    }
    int r0 = lane >> 2, c0 = (lane & 3) * 2;
    #pragma unroll
    for (int a = 0; a < 4; a++) {
        int np = wm * 64 + a * 16 + r0;
        #pragma unroll
        for (int n = 0; n < 4; n++) {
            int d = d0 + wn * 32 + n * 8 + c0;
            float* dst0 = &g_xsp[(((size_t)seg * BB + b) * NP + np) * DD + d];
            float* dst1 = &g_xsp[(((size_t)seg * BB + b) * NP + np + 8) * DD + d];
            *reinterpret_cast<float2*>(dst0) = make_float2(acc[a][n][0], acc[a][n][1]);
            *reinterpret_cast<float2*>(dst1) = make_float2(acc[a][n][2], acc[a][n][3]);
        }
    }
}

// ===========================================================================
// K6 (mma): ys[(b,p)][e] = sum_d xs[(b,p)][d] * W[n][d][e] + bias[n][e]
// A built in-kernel from 4-segment xsp sum * 1/colsum.
#define LDW 264
#define LDK 72
__global__ __launch_bounds__(256) void k_ys_mma(const float* __restrict__ W,
                                                const float* __restrict__ bias) {
    extern __shared__ __nv_bfloat16 sm_y[];
    __nv_bfloat16* sWh = sm_y;                 // [64 k][LDW]
    __nv_bfloat16* sWl = sWh + 64 * LDW;
    __nv_bfloat16* sAh = sWl + 64 * LDW;       // [16 m][LDK]
    __nv_bfloat16* sAl = sAh + 16 * LDK;
    int t = threadIdx.x, lane = t & 31, wid = t >> 5;
    int nexp = blockIdx.y;
    int e0 = blockIdx.x * 256;
    float acc[4][4];
    #pragma unroll
    for (int n = 0; n < 4; n++)
        #pragma unroll
        for (int q = 0; q < 4; q++) acc[n][q] = 0.f;

    int a_row = lane & 15;
    int a_col = (lane >> 4) * 8;
    int aB_row = (lane & 7) + ((lane >> 3) & 1) * 8;
    int aB_col = (lane >> 4) * 8;

    int arow = t >> 3, aq = t & 7;
    int abb = arow >> 1, ap = arow & 1;
    float ainv = (t < 128) ? 1.0f / g_colsum[abb * NP + nexp * 2 + ap] : 0.f;
    size_t abase = ((size_t)abb * NP + nexp * 2 + ap) * DD + aq * 8;

    for (int c = 0; c < 16; c++) {
        int k0 = c * 64;
        if (t < 128) {
            float v[8];
            {
                const float* s0 = &g_xsp[abase + k0];
                float4 v0 = *reinterpret_cast<const float4*>(s0);
                float4 v1 = *reinterpret_cast<const float4*>(s0 + 4);
                #pragma unroll
                for (int seg = 1; seg < 4; seg++) {
                    const float* ss = &g_xsp[(size_t)seg * BB * NP * DD + abase + k0];
                    float4 w0 = *reinterpret_cast<const float4*>(ss);
                    float4 w1 = *reinterpret_cast<const float4*>(ss + 4);
                    v0.x += w0.x; v0.y += w0.y; v0.z += w0.z; v0.w += w0.w;
                    v1.x += w1.x; v1.y += w1.y; v1.z += w1.z; v1.w += w1.w;
                }
                v[0] = v0.x * ainv; v[1] = v0.y * ainv; v[2] = v0.z * ainv; v[3] = v0.w * ainv;
                v[4] = v1.x * ainv; v[5] = v1.y * ainv; v[6] = v1.z * ainv; v[7] = v1.w * ainv;
            }
            uint32_t hs[8], ls[8];
            #pragma unroll
            for (int j = 0; j < 8; j++) {
                __nv_bfloat16 h, l;
                split1(v[j], h, l);
                hs[j] = (uint32_t)__bfloat16_as_ushort(h);
                ls[j] = (uint32_t)__bfloat16_as_ushort(l);
            }
            uint4 hi = {hs[0] | (hs[1] << 16), hs[2] | (hs[3] << 16),
                        hs[4] | (hs[5] << 16), hs[6] | (hs[7] << 16)};
            uint4 lo = {ls[0] | (ls[1] << 16), ls[2] | (ls[3] << 16),
                        ls[4] | (ls[5] << 16), ls[6] | (ls[7] << 16)};
            *reinterpret_cast<uint4*>(&sAh[arow * LDK + aq * 8]) = hi;
            *reinterpret_cast<uint4*>(&sAl[arow * LDK + aq * 8]) = lo;
        }
        #pragma unroll
        for (int i = 0; i < 8; i++) {
            int idx = t + i * 256;
            int row = idx >> 5, q = idx & 31;
            const float* src = &W[((size_t)nexp * DD + k0 + row) * DD + e0 + q * 8];
            float4 v0 = *reinterpret_cast<const float4*>(src);
            float4 v1 = *reinterpret_cast<const float4*>(src + 4);
            float v[8] = {v0.x, v0.y, v0.z, v0.w, v1.x, v1.y, v1.z, v1.w};
            uint32_t hs[8], ls[8];
            #pragma unroll
            for (int j = 0; j < 8; j++) {
                __nv_bfloat16 h, l;
                split1(v[j], h, l);
                hs[j] = (uint32_t)__bfloat16_as_ushort(h);
                ls[j] = (uint32_t)__bfloat16_as_ushort(l);
            }
            uint4 hi = {hs[0] | (hs[1] << 16), hs[2] | (hs[3] << 16),
                        hs[4] | (hs[5] << 16), hs[6] | (hs[7] << 16)};
            uint4 lo = {ls[0] | (ls[1] << 16), ls[2] | (ls[3] << 16),
                        ls[4] | (ls[5] << 16), ls[6] | (ls[7] << 16)};
            *reinterpret_cast<uint4*>(&sWh[row * LDW + q * 8]) = hi;
            *reinterpret_cast<uint4*>(&sWl[row * LDW + q * 8]) = lo;
        }
        __syncthreads();
        #pragma unroll
        for (int ks = 0; ks < 4; ks++) {
            uint32_t ah[4], al[4], bh[4][2], bl[4][2];
            {
                int off = a_row * LDK + ks * 16 + a_col;
                ldsm_x4(ah[0], ah[1], ah[2], ah[3], smem_u32(&sAh[off]));
                ldsm_x4(al[0], al[1], al[2], al[3], smem_u32(&sAl[off]));
            }
            #pragma unroll
            for (int p = 0; p < 2; p++) {
                int nb = wid * 32 + p * 16 + aB_col;
                int off = (ks * 16 + aB_row) * LDW + nb;
                uint32_t r0, r1, r2, r3;
                ldsm_x4t(r0, r1, r2, r3, smem_u32(&sWh[off]));
                bh[p * 2][0] = r0; bh[p * 2][1] = r1;
                bh[p * 2 + 1][0] = r2; bh[p * 2 + 1][1] = r3;
                ldsm_x4t(r0, r1, r2, r3, smem_u32(&sWl[off]));
                bl[p * 2][0] = r0; bl[p * 2][1] = r1;
                bl[p * 2 + 1][0] = r2; bl[p * 2 + 1][1] = r3;
            }
            #pragma unroll
            for (int n = 0; n < 4; n++) {
                mma_bf16(acc[n], ah, bh[n]);
                mma_bf16(acc[n], ah, bl[n]);
                mma_bf16(acc[n], al, bh[n]);
            }
        }
        __syncthreads();
    }
    int r0 = lane >> 2, c0 = (lane & 3) * 2;
    #pragma unroll
    for (int n = 0; n < 4; n++) {
        int e = e0 + wid * 32 + n * 8 + c0;
        float2 bv = *reinterpret_cast<const float2*>(&bias[nexp * DD + e]);
        #pragma unroll
        for (int h = 0; h < 2; h++) {
            int row = r0 + h * 8;
            int bb = row >> 1, p = row & 1;
            float v0 = acc[n][h * 2 + 0] + bv.x;
            float v1 = acc[n][h * 2 + 1] + bv.y;
            __nv_bfloat16 h0, l0, h1, l1;
            split1(v0, h0, l0); split1(v1, h1, l1);
            size_t o = ((size_t)bb * NP + nexp * 2 + p) * DD + e;
            *reinterpret_cast<__nv_bfloat162*>(&g_ysh[o]) = __halves2bfloat162(h0, h1);
            *reinterpret_cast<__nv_bfloat162*>(&g_ysl[o]) = __halves2bfloat162(l0, l1);
        }
    }
}

// ===========================================================================
// K7 (mma, cp.async 3-stage, single barrier/iter):
// y[m][d] = rsinv[m]*sum_np E[m][np]*ys[np][d] + x[m][d]
#define C_ASZ (128 * LDA)
#define C_BSZ (32 * LDE)
#define C_SST (2 * C_ASZ + 2 * C_BSZ)
__global__ __launch_bounds__(256, 2) void k_combine_mma(const float* __restrict__ x,
                                                        float* __restrict__ y) {
    extern __shared__ __nv_bfloat16 sm_c[];
    int t = threadIdx.x, lane = t & 31, wid = t >> 5;
    int b = blockIdx.z;
    int tokbase = b * MM + blockIdx.x * 128;
    int d0 = blockIdx.y * 128;
    int wm = wid & 1, wn = wid >> 1;
    float acc[4][4][4];
    #pragma unroll
    for (int a = 0; a < 4; a++)
        #pragma unroll
        for (int n = 0; n < 4; n++)
            #pragma unroll
            for (int q = 0; q < 4; q++) acc[a][n][q] = 0.f;

    int a_row = lane & 15;
    int a_col = (lane >> 4) * 8;
    int aB_row = (lane & 7) + ((lane >> 3) & 1) * 8;
    int aB_col = (lane >> 4) * 8;

    #define C_LOAD(c, s) do { \
        __nv_bfloat16* base = sm_c + (s) * C_SST; \
        _Pragma("unroll") \
        for (int i = 0; i < 2; i++) { \
            int idx = t + i * 256; \
            int row = idx >> 2, q = idx & 3; \
            size_t ge = (size_t)(tokbase + row) * NP + (c) * 32 + q * 8; \
            int so = row * LDA + q * 8; \
            cp_async16(smem_u32(base + so), &g_Eh[ge]); \
            cp_async16(smem_u32(base + C_ASZ + so), &g_El[ge]); \
            int rowb = idx >> 4, qb = idx & 15; \
            size_t gy = ((size_t)b * NP + (c) * 32 + rowb) * DD + d0 + qb * 8; \
            int sob = rowb * LDE + qb * 8; \
            cp_async16(smem_u32(base + 2 * C_ASZ + sob), &g_ysh[gy]); \
            cp_async16(smem_u32(base + 2 * C_ASZ + C_BSZ + sob), &g_ysl[gy]); \
        } \
    } while (0)

    C_LOAD(0, 0);
    CP_COMMIT();
    C_LOAD(1, 1);
    CP_COMMIT();
    for (int c = 0; c < 4; c++) {
        CP_WAIT1();
        __syncthreads();
        if (c + 2 < 4) C_LOAD(c + 2, (c + 2) % 3);
        CP_COMMIT();
        __nv_bfloat16* sAh = sm_c + (c % 3) * C_SST;
        __nv_bfloat16* sAl = sAh + C_ASZ;
        __nv_bfloat16* sBh = sAl + C_ASZ;
        __nv_bfloat16* sBl = sBh + C_BSZ;
        #pragma unroll
        for (int ks = 0; ks < 2; ks++) {
            uint32_t ah[4][4], al[4][4], bh[4][2], bl[4][2];
            #pragma unroll
            for (int a = 0; a < 4; a++) {
                int off = (wm * 64 + a * 16 + a_row) * LDA + ks * 16 + a_col;
                ldsm_x4(ah[a][0], ah[a][1], ah[a][2], ah[a][3], smem_u32(&sAh[off]));
                ldsm_x4(al[a][0], al[a][1], al[a][2], al[a][3], smem_u32(&sAl[off]));
            }
            #pragma unroll
            for (int p = 0; p < 2; p++) {
                int nb = wn * 32 + p * 16 + aB_col;
                int off = (ks * 16 + aB_row) * LDE + nb;
                uint32_t r0, r1, r2, r3;
                ldsm_x4t(r0, r1, r2, r3, smem_u32(&sBh[off]));
                bh[p * 2][0] = r0; bh[p * 2][1] = r1;
                bh[p * 2 + 1][0] = r2; bh[p * 2 + 1][1] = r3;
                ldsm_x4t(r0, r1, r2, r3, smem_u32(&sBl[off]));
                bl[p * 2][0] = r0; bl[p * 2][1] = r1;
                bl[p * 2 + 1][0] = r2; bl[p * 2 + 1][1] = r3;
            }
            #pragma unroll
            for (int a = 0; a < 4; a++)
                #pragma unroll
                for (int n = 0; n < 4; n++) {
                    mma_bf16(acc[a][n], ah[a], bh[n]);
                    mma_bf16(acc[a][n], ah[a], bl[n]);
                    mma_bf16(acc[a][n], al[a], bh[n]);
                }
        }
    }
    int r0 = lane >> 2, c0 = (lane & 3) * 2;
    #pragma unroll
    for (int a = 0; a < 4; a++) {
        int m0 = tokbase + wm * 64 + a * 16 + r0;
        float rs0 = g_rsinv[m0];
        float rs1 = g_rsinv[m0 + 8];
        #pragma unroll
        for (int n = 0; n < 4; n++) {
            int d = d0 + wn * 32 + n * 8 + c0;
            size_t i0 = (size_t)m0 * DD + d;
            size_t i1 = (size_t)(m0 + 8) * DD + d;
            float2 xv0 = *reinterpret_cast<const float2*>(&x[i0]);
            float2 xv1 = *reinterpret_cast<const float2*>(&x[i1]);
            *reinterpret_cast<float2*>(&y[i0]) =
                make_float2(acc[a][n][0] * rs0 + xv0.x, acc[a][n][1] * rs0 + xv0.y);
            *reinterpret_cast<float2*>(&y[i1]) =
                make_float2(acc[a][n][2] * rs1 + xv1.x, acc[a][n][3] * rs1 + xv1.y);
        }
    }
}

// ---------------------------------------------------------------------------
extern "C" void kernel_launch(void* const* d_in, const int* in_sizes, int n_in,
                              void* d_out, int out_size) {
    const float* x     = (const float*)d_in[0];  // [8,4096,1024]
    const float* phi   = (const float*)d_in[1];  // [1024,64,2]
    const float* scale = (const float*)d_in[2];  // [1]
    const float* W     = (const float*)d_in[3];  // [64,1024,1024]
    const float* bias  = (const float*)d_in[4];  // [64,1024]
    float* y = (float*)d_out;                    // [8,4096,1024]

    const int smem_logits  = 2 * L_SST * 2;                         // 81920
    const int smem_xs      = 3 * X_SST * 2;                         // 104448
    const int smem_ys      = 2 * 64 * LDW * 2 + 2 * 16 * LDK * 2;   // 72192
    const int smem_combine = 3 * C_SST * 2;                         // 113664
    cudaFuncSetAttribute(k_logits_mma, cudaFuncAttributeMaxDynamicSharedMemorySize, smem_logits);
    cudaFuncSetAttribute(k_xs_mma, cudaFuncAttributeMaxDynamicSharedMemorySize, smem_xs);
    cudaFuncSetAttribute(k_ys_mma, cudaFuncAttributeMaxDynamicSharedMemorySize, smem_ys);
    cudaFuncSetAttribute(k_combine_mma, cudaFuncAttributeMaxDynamicSharedMemorySize, smem_combine);

    k_phinorm<<<NP, 256>>>(phi, scale);
    k_rinv<<<BM / 8, 256>>>(x);
    k_logits_mma<<<BM / 128, 256, smem_logits>>>();
    k_colsum<<<BB, NP>>>();
    k_xs_mma<<<dim3(8, BB, 4), 256, smem_xs>>>();
    k_ys_mma<<<dim3(4, NEXP), 256, smem_ys>>>(W, bias);
    k_combine_mma<<<dim3(32, 8, BB), 256, smem_combine>>>(x, y);
}

// round 10
// speedup vs baseline: 1.5508x; 1.5408x over previous
#include <cuda_runtime.h>
#include <cuda_bf16.h>
#include <math.h>
#include <stdint.h>

// Problem constants
#define BB 8
#define MM 4096
#define DD 1024
#define NEXP 64
#define NP 128            // NEXP * PP
#define BM (BB * MM)      // 32768 tokens
#define LOG2E 1.4426950408889634f

static __device__ __constant__ float c_eps = 1e-12f;

// ---- scratch (device globals; no allocation allowed) ----
__device__ __align__(16) __nv_bfloat16 g_phinth[NP * DD];       // phin^T [np][d]
__device__ __align__(16) __nv_bfloat16 g_xh[(size_t)BM * DD];   // x bf16 [tok][d]
__device__ __align__(16) __nv_bfloat16 g_Eh[(size_t)BM * NP];   // E bf16 [tok][np]
__device__ __align__(16) __nv_bfloat16 g_ysh[BB * NP * DD];     // ys bf16 [b*NP+np][d]
__device__ float g_rinv[BM];              // per-token (1/TEMP)/max(||x||,eps)
__device__ float g_part[256 * NP];        // per-mtile column partial sums
__device__ float g_colsum[BB * NP];       // dispatch softmax denominators
__device__ float g_rsinv[BM];             // 1/rowsum (combine denominators)
__device__ float g_xsp[4 * BB * NP * DD]; // partial slot inputs (4 m-segments)

// ============================ helpers =====================================
__device__ __forceinline__ uint32_t smem_u32(const void* p) {
    uint32_t a;
    asm("{ .reg .u64 t; cvta.to.shared.u64 t, %1; cvt.u32.u64 %0, t; }"
        : "=r"(a) : "l"(p));
    return a;
}
__device__ __forceinline__ void cp_async16(uint32_t saddr, const void* gptr) {
    asm volatile("cp.async.cg.shared.global [%0], [%1], 16;"
                 :: "r"(saddr), "l"(gptr));
}
#define CP_COMMIT() asm volatile("cp.async.commit_group;" ::: "memory")
#define CP_WAIT1()  asm volatile("cp.async.wait_group 1;" ::: "memory")
__device__ __forceinline__ void ldsm_x4(uint32_t& r0, uint32_t& r1, uint32_t& r2,
                                        uint32_t& r3, uint32_t a) {
    asm volatile("ldmatrix.sync.aligned.m8n8.x4.shared.b16 {%0,%1,%2,%3}, [%4];"
                 : "=r"(r0), "=r"(r1), "=r"(r2), "=r"(r3) : "r"(a));
}
__device__ __forceinline__ void ldsm_x4t(uint32_t& r0, uint32_t& r1, uint32_t& r2,
                                         uint32_t& r3, uint32_t a) {
    asm volatile("ldmatrix.sync.aligned.m8n8.x4.trans.shared.b16 {%0,%1,%2,%3}, [%4];"
                 : "=r"(r0), "=r"(r1), "=r"(r2), "=r"(r3) : "r"(a));
}
__device__ __forceinline__ void mma_bf16(float* d, const uint32_t* a, const uint32_t* b) {
    asm volatile(
        "mma.sync.aligned.m16n8k16.row.col.f32.bf16.bf16.f32 "
        "{%0,%1,%2,%3}, {%4,%5,%6,%7}, {%8,%9}, {%0,%1,%2,%3};"
        : "+f"(d[0]), "+f"(d[1]), "+f"(d[2]), "+f"(d[3])
        : "r"(a[0]), "r"(a[1]), "r"(a[2]), "r"(a[3]), "r"(b[0]), "r"(b[1]));
}
__device__ __forceinline__ float ex2f(float x) {
    float r;
    asm("ex2.approx.f32 %0, %1;" : "=f"(r) : "f"(x));
    return r;
}
__device__ __forceinline__ float warpReduceSum(float v) {
    v += __shfl_down_sync(0xffffffffu, v, 16);
    v += __shfl_down_sync(0xffffffffu, v, 8);
    v += __shfl_down_sync(0xffffffffu, v, 4);
    v += __shfl_down_sync(0xffffffffu, v, 2);
    v += __shfl_down_sync(0xffffffffu, v, 1);
    return v;
}

// ===========================================================================
// K1: phin^T bf16
__global__ void k_phinorm(const float* __restrict__ phi, const float* __restrict__ scale) {
    int np = blockIdx.x;
    int t = threadIdx.x;
    float s = 0.f;
    for (int d = t; d < DD; d += 256) {
        float v = phi[d * NP + np];
        s += v * v;
    }
    __shared__ float red[8];
    s = warpReduceSum(s);
    if ((t & 31) == 0) red[t >> 5] = s;
    __syncthreads();
    if (t < 32) {
        float v = (t < 8) ? red[t] : 0.f;
        v = warpReduceSum(v);
        if (t == 0) red[0] = scale[0] / fmaxf(sqrtf(v), c_eps);
    }
    __syncthreads();
    float rn = red[0];
    for (int d = t; d < DD; d += 256)
        g_phinth[np * DD + d] = __float2bfloat16_rn(phi[d * NP + np] * rn);
}

// K2: row norms + x -> bf16. Warp per token.
__global__ void k_rinv(const float* __restrict__ x) {
    int w = threadIdx.x >> 5;
    int lane = threadIdx.x & 31;
    int tok = blockIdx.x * 8 + w;
    const float4* xr = reinterpret_cast<const float4*>(x + (size_t)tok * DD);
    float s = 0.f;
    #pragma unroll
    for (int i = 0; i < 8; i++) {
        float4 v = xr[lane + i * 32];
        s += v.x * v.x + v.y * v.y + v.z * v.z + v.w * v.w;
        __nv_bfloat162 p0 = __halves2bfloat162(__float2bfloat16_rn(v.x), __float2bfloat16_rn(v.y));
        __nv_bfloat162 p1 = __halves2bfloat162(__float2bfloat16_rn(v.z), __float2bfloat16_rn(v.w));
        size_t off = (size_t)tok * DD + (lane + i * 32) * 4;
        *reinterpret_cast<__nv_bfloat162*>(&g_xh[off])     = p0;
        *reinterpret_cast<__nv_bfloat162*>(&g_xh[off + 2]) = p1;
    }
    s = warpReduceSum(s);
    if (lane == 0) g_rinv[tok] = 10.0f / fmaxf(sqrtf(s), c_eps);  // 1/TEMP
}

// ===========================================================================
// K3 (mma, cp.async 3-stage): E = exp2((x . phin) * rinv * log2e), bf16 out.
// CTA 128m x 128n, K chunks of 32. Fused rowsum + column partials.
#define LDA 40
#define L_AST (128 * LDA)
#define L_SST (2 * L_AST)
__global__ __launch_bounds__(256) void k_logits_mma() {
    extern __shared__ __nv_bfloat16 sm_l[];
    int t = threadIdx.x, lane = t & 31, wid = t >> 5;
    int tok0 = blockIdx.x * 128;
    int wm = wid & 1, wn = wid >> 1;
    float acc[4][4][4];
    #pragma unroll
    for (int a = 0; a < 4; a++)
        #pragma unroll
        for (int n = 0; n < 4; n++)
            #pragma unroll
            for (int q = 0; q < 4; q++) acc[a][n][q] = 0.f;

    int a_row = lane & 15;
    int a_col = (lane >> 4) * 8;
    int b_row = (lane & 7) + ((lane >> 4) << 3);
    int b_col = ((lane >> 3) & 1) * 8;

    #define L_LOAD(c, s) do { \
        __nv_bfloat16* base = sm_l + (s) * L_SST; \
        _Pragma("unroll") \
        for (int i = 0; i < 2; i++) { \
            int idx = t + i * 256; \
            int row = idx >> 2, q = idx & 3; \
            size_t ga = (size_t)(tok0 + row) * DD + (c) * 32 + q * 8; \
            size_t gb = (size_t)row * DD + (c) * 32 + q * 8; \
            int so = row * LDA + q * 8; \
            cp_async16(smem_u32(base + so), &g_xh[ga]); \
            cp_async16(smem_u32(base + L_AST + so), &g_phinth[gb]); \
        } \
    } while (0)

    L_LOAD(0, 0);
    CP_COMMIT();
    L_LOAD(1, 1);
    CP_COMMIT();
    for (int c = 0; c < 32; c++) {
        CP_WAIT1();
        __syncthreads();
        if (c + 2 < 32) L_LOAD(c + 2, (c + 2) % 3);
        CP_COMMIT();
        __nv_bfloat16* sAh = sm_l + (c % 3) * L_SST;
        __nv_bfloat16* sBh = sAh + L_AST;
        #pragma unroll
        for (int ks = 0; ks < 2; ks++) {
            uint32_t ah[4][4], bh[4][2];
            #pragma unroll
            for (int a = 0; a < 4; a++) {
                int off = (wm * 64 + a * 16 + a_row) * LDA + ks * 16 + a_col;
                ldsm_x4(ah[a][0], ah[a][1], ah[a][2], ah[a][3], smem_u32(&sAh[off]));
            }
            #pragma unroll
            for (int p = 0; p < 2; p++) {
                int off = (wn * 32 + p * 16 + b_row) * LDA + ks * 16 + b_col;
                uint32_t r0, r1, r2, r3;
                ldsm_x4(r0, r1, r2, r3, smem_u32(&sBh[off]));
                bh[p * 2][0] = r0; bh[p * 2][1] = r1;
                bh[p * 2 + 1][0] = r2; bh[p * 2 + 1][1] = r3;
            }
            #pragma unroll
            for (int a = 0; a < 4; a++)
                #pragma unroll
                for (int n = 0; n < 4; n++)
                    mma_bf16(acc[a][n], ah[a], bh[n]);
        }
    }
    // epilogue: exp2, store bf16; accumulate row/col sums (fp32, pre-rounding)
    int r0 = lane >> 2, c0 = (lane & 3) * 2;
    float rsum[4][2];
    float csum[4][2];
    #pragma unroll
    for (int a = 0; a < 4; a++) { rsum[a][0] = 0.f; rsum[a][1] = 0.f; }
    #pragma unroll
    for (int n = 0; n < 4; n++) { csum[n][0] = 0.f; csum[n][1] = 0.f; }
    __syncthreads();
    #pragma unroll
    for (int a = 0; a < 4; a++) {
        int row = tok0 + wm * 64 + a * 16 + r0;
        float rv0 = g_rinv[row] * LOG2E;
        float rv1 = g_rinv[row + 8] * LOG2E;
        #pragma unroll
        for (int n = 0; n < 4; n++) {
            int col = wn * 32 + n * 8 + c0;
            float e0 = ex2f(acc[a][n][0] * rv0), e1 = ex2f(acc[a][n][1] * rv0);
            float e2 = ex2f(acc[a][n][2] * rv1), e3 = ex2f(acc[a][n][3] * rv1);
            rsum[a][0] += e0 + e1;
            rsum[a][1] += e2 + e3;
            csum[n][0] += e0 + e2;
            csum[n][1] += e1 + e3;
            *reinterpret_cast<__nv_bfloat162*>(&g_Eh[(size_t)row * NP + col]) =
                __halves2bfloat162(__float2bfloat16_rn(e0), __float2bfloat16_rn(e1));
            *reinterpret_cast<__nv_bfloat162*>(&g_Eh[(size_t)(row + 8) * NP + col]) =
                __halves2bfloat162(__float2bfloat16_rn(e2), __float2bfloat16_rn(e3));
        }
    }
    float* srow = reinterpret_cast<float*>(sm_l);   // [4 wn][128 rows]
    float* scol = srow + 4 * 128;                   // [2 wm][128 cols]
    __syncthreads();
    #pragma unroll
    for (int a = 0; a < 4; a++)
        #pragma unroll
        for (int h = 0; h < 2; h++) {
            float v = rsum[a][h];
            v += __shfl_xor_sync(0xffffffffu, v, 1);
            v += __shfl_xor_sync(0xffffffffu, v, 2);
            if ((lane & 3) == 0)
                srow[wn * 128 + wm * 64 + a * 16 + h * 8 + r0] = v;
        }
    #pragma unroll
    for (int n = 0; n < 4; n++)
        #pragma unroll
        for (int q1 = 0; q1 < 2; q1++) {
            float v = csum[n][q1];
            v += __shfl_xor_sync(0xffffffffu, v, 4);
            v += __shfl_xor_sync(0xffffffffu, v, 8);
            v += __shfl_xor_sync(0xffffffffu, v, 16);
            if (lane < 4)
                scol[wm * 128 + wn * 32 + n * 8 + lane * 2 + q1] = v;
        }
    __syncthreads();
    if (t < 128) {
        float rs = srow[t] + srow[128 + t] + srow[256 + t] + srow[384 + t];
        g_rsinv[tok0 + t] = 1.0f / rs;
        g_part[blockIdx.x * NP + t] = scol[t] + scol[128 + t];
    }
}

// K4: final column sums per batch (32 m-tiles each)
__global__ void k_colsum() {
    int b = blockIdx.x;
    int np = threadIdx.x;
    float s = 0.f;
    #pragma unroll
    for (int i = 0; i < 32; i++)
        s += g_part[(b * 32 + i) * NP + np];
    g_colsum[b * NP + np] = s;
}

// ===========================================================================
// K5 (mma, cp.async 3-stage): xsp[seg][b][np][d] = sum_{m in seg} E[m][np]*x[m][d]
#define LDE 136
#define X_AST (32 * LDE)
#define X_SST (2 * X_AST)
__global__ __launch_bounds__(256) void k_xs_mma() {
    extern __shared__ __nv_bfloat16 sm_x[];
    int t = threadIdx.x, lane = t & 31, wid = t >> 5;
    int d0 = blockIdx.x * 128;
    int b = blockIdx.y;
    int seg = blockIdx.z;
    int base = b * MM + seg * 1024;
    int wm = wid & 1, wn = wid >> 1;
    float acc[4][4][4];
    #pragma unroll
    for (int a = 0; a < 4; a++)
        #pragma unroll
        for (int n = 0; n < 4; n++)
            #pragma unroll
            for (int q = 0; q < 4; q++) acc[a][n][q] = 0.f;

    int aA_col = ((lane >> 3) & 1) * 8;
    int aA_row = (lane & 7) + (lane >> 4) * 8;
    int aB_row = (lane & 7) + ((lane >> 3) & 1) * 8;
    int aB_col = (lane >> 4) * 8;

    #define X_LOAD(c, s) do { \
        __nv_bfloat16* bb_ = sm_x + (s) * X_SST; \
        _Pragma("unroll") \
        for (int i = 0; i < 2; i++) { \
            int idx = t + i * 256; \
            int row = idx >> 4, q = idx & 15; \
            size_t ge = (size_t)(base + (c) * 32 + row) * NP + q * 8; \
            size_t gx = (size_t)(base + (c) * 32 + row) * DD + d0 + q * 8; \
            int so = row * LDE + q * 8; \
            cp_async16(smem_u32(bb_ + so), &g_Eh[ge]); \
            cp_async16(smem_u32(bb_ + X_AST + so), &g_xh[gx]); \
        } \
    } while (0)

    X_LOAD(0, 0);
    CP_COMMIT();
    X_LOAD(1, 1);
    CP_COMMIT();
    for (int c = 0; c < 32; c++) {
        CP_WAIT1();
        __syncthreads();
        if (c + 2 < 32) X_LOAD(c + 2, (c + 2) % 3);
        CP_COMMIT();
        __nv_bfloat16* sEh = sm_x + (c % 3) * X_SST;
        __nv_bfloat16* sXh = sEh + X_AST;
        #pragma unroll
        for (int ks = 0; ks < 2; ks++) {
            uint32_t ah[4][4], bh[4][2];
            #pragma unroll
            for (int a = 0; a < 4; a++) {
                int npb = wm * 64 + a * 16 + aA_col;
                int off = (ks * 16 + aA_row) * LDE + npb;
                ldsm_x4t(ah[a][0], ah[a][1], ah[a][2], ah[a][3], smem_u32(&sEh[off]));
            }
            #pragma unroll
            for (int p = 0; p < 2; p++) {
                int nb = wn * 32 + p * 16 + aB_col;
                int off = (ks * 16 + aB_row) * LDE + nb;
                uint32_t r0, r1, r2, r3;
                ldsm_x4t(r0, r1, r2, r3, smem_u32(&sXh[off]));
                bh[p * 2][0] = r0; bh[p * 2][1] = r1;
                bh[p * 2 + 1][0] = r2; bh[p * 2 + 1][1] = r3;
            }
            #pragma unroll
            for (int a = 0; a < 4; a++)
                #pragma unroll
                for (int n = 0; n < 4; n++)
                    mma_bf16(acc[a][n], ah[a], bh[n]);
        }
    }
    int r0 = lane >> 2, c0 = (lane & 3) * 2;
    #pragma unroll
    for (int a = 0; a < 4; a++) {
        int np = wm * 64 + a * 16 + r0;
        #pragma unroll
        for (int n = 0; n < 4; n++) {
            int d = d0 + wn * 32 + n * 8 + c0;
            float* dst0 = &g_xsp[(((size_t)seg * BB + b) * NP + np) * DD + d];
            float* dst1 = &g_xsp[(((size_t)seg * BB + b) * NP + np + 8) * DD + d];
            *reinterpret_cast<float2*>(dst0) = make_float2(acc[a][n][0], acc[a][n][1]);
            *reinterpret_cast<float2*>(dst1) = make_float2(acc[a][n][2], acc[a][n][3]);
        }
    }
}

// ===========================================================================
// K6 (mma): ys[(b,p)][e] = sum_d xs[(b,p)][d] * W[n][d][e] + bias[n][e]
// A built in-kernel from 4-segment xsp sum * 1/colsum.
#define LDW 264
#define LDK 72
__global__ __launch_bounds__(256) void k_ys_mma(const float* __restrict__ W,
                                                const float* __restrict__ bias) {
    extern __shared__ __nv_bfloat16 sm_y[];
    __nv_bfloat16* sWh = sm_y;                 // [64 k][LDW]
    __nv_bfloat16* sAh = sWh + 64 * LDW;       // [16 m][LDK]
    int t = threadIdx.x, lane = t & 31, wid = t >> 5;
    int nexp = blockIdx.y;
    int e0 = blockIdx.x * 256;
    float acc[4][4];
    #pragma unroll
    for (int n = 0; n < 4; n++)
        #pragma unroll
        for (int q = 0; q < 4; q++) acc[n][q] = 0.f;

    int a_row = lane & 15;
    int a_col = (lane >> 4) * 8;
    int aB_row = (lane & 7) + ((lane >> 3) & 1) * 8;
    int aB_col = (lane >> 4) * 8;

    int arow = t >> 3, aq = t & 7;
    int abb = arow >> 1, ap = arow & 1;
    float ainv = (t < 128) ? 1.0f / g_colsum[abb * NP + nexp * 2 + ap] : 0.f;
    size_t abase = ((size_t)abb * NP + nexp * 2 + ap) * DD + aq * 8;

    for (int c = 0; c < 16; c++) {
        int k0 = c * 64;
        if (t < 128) {
            const float* s0 = &g_xsp[abase + k0];
            float4 v0 = *reinterpret_cast<const float4*>(s0);
            float4 v1 = *reinterpret_cast<const float4*>(s0 + 4);
            #pragma unroll
            for (int seg = 1; seg < 4; seg++) {
                const float* ss = &g_xsp[(size_t)seg * BB * NP * DD + abase + k0];
                float4 w0 = *reinterpret_cast<const float4*>(ss);
                float4 w1 = *reinterpret_cast<const float4*>(ss + 4);
                v0.x += w0.x; v0.y += w0.y; v0.z += w0.z; v0.w += w0.w;
                v1.x += w1.x; v1.y += w1.y; v1.z += w1.z; v1.w += w1.w;
            }
            float v[8] = {v0.x * ainv, v0.y * ainv, v0.z * ainv, v0.w * ainv,
                          v1.x * ainv, v1.y * ainv, v1.z * ainv, v1.w * ainv};
            uint32_t hs[8];
            #pragma unroll
            for (int j = 0; j < 8; j++)
                hs[j] = (uint32_t)__bfloat16_as_ushort(__float2bfloat16_rn(v[j]));
            uint4 hi = {hs[0] | (hs[1] << 16), hs[2] | (hs[3] << 16),
                        hs[4] | (hs[5] << 16), hs[6] | (hs[7] << 16)};
            *reinterpret_cast<uint4*>(&sAh[arow * LDK + aq * 8]) = hi;
        }
        #pragma unroll
        for (int i = 0; i < 8; i++) {
            int idx = t + i * 256;
            int row = idx >> 5, q = idx & 31;
            const float* src = &W[((size_t)nexp * DD + k0 + row) * DD + e0 + q * 8];
            float4 v0 = *reinterpret_cast<const float4*>(src);
            float4 v1 = *reinterpret_cast<const float4*>(src + 4);
            float v[8] = {v0.x, v0.y, v0.z, v0.w, v1.x, v1.y, v1.z, v1.w};
            uint32_t hs[8];
            #pragma unroll
            for (int j = 0; j < 8; j++)
                hs[j] = (uint32_t)__bfloat16_as_ushort(__float2bfloat16_rn(v[j]));
            uint4 hi = {hs[0] | (hs[1] << 16), hs[2] | (hs[3] << 16),
                        hs[4] | (hs[5] << 16), hs[6] | (hs[7] << 16)};
            *reinterpret_cast<uint4*>(&sWh[row * LDW + q * 8]) = hi;
        }
        __syncthreads();
        #pragma unroll
        for (int ks = 0; ks < 4; ks++) {
            uint32_t ah[4], bh[4][2];
            {
                int off = a_row * LDK + ks * 16 + a_col;
                ldsm_x4(ah[0], ah[1], ah[2], ah[3], smem_u32(&sAh[off]));
            }
            #pragma unroll
            for (int p = 0; p < 2; p++) {
                int nb = wid * 32 + p * 16 + aB_col;
                int off = (ks * 16 + aB_row) * LDW + nb;
                uint32_t r0, r1, r2, r3;
                ldsm_x4t(r0, r1, r2, r3, smem_u32(&sWh[off]));
                bh[p * 2][0] = r0; bh[p * 2][1] = r1;
                bh[p * 2 + 1][0] = r2; bh[p * 2 + 1][1] = r3;
            }
            #pragma unroll
            for (int n = 0; n < 4; n++)
                mma_bf16(acc[n], ah, bh[n]);
        }
        __syncthreads();
    }
    int r0 = lane >> 2, c0 = (lane & 3) * 2;
    #pragma unroll
    for (int n = 0; n < 4; n++) {
        int e = e0 + wid * 32 + n * 8 + c0;
        float2 bv = *reinterpret_cast<const float2*>(&bias[nexp * DD + e]);
        #pragma unroll
        for (int h = 0; h < 2; h++) {
            int row = r0 + h * 8;
            int bb = row >> 1, p = row & 1;
            float v0 = acc[n][h * 2 + 0] + bv.x;
            float v1 = acc[n][h * 2 + 1] + bv.y;
            size_t o = ((size_t)bb * NP + nexp * 2 + p) * DD + e;
            *reinterpret_cast<__nv_bfloat162*>(&g_ysh[o]) =
                __halves2bfloat162(__float2bfloat16_rn(v0), __float2bfloat16_rn(v1));
        }
    }
}

// ===========================================================================
// K7 (mma, cp.async 3-stage): y[m][d] = rsinv[m]*sum_np E[m][np]*ys[np][d] + x[m][d]
#define C_ASZ (128 * LDA)
#define C_BSZ (32 * LDE)
#define C_SST (C_ASZ + C_BSZ)
__global__ __launch_bounds__(256) void k_combine_mma(const float* __restrict__ x,
                                                     float* __restrict__ y) {
    extern __shared__ __nv_bfloat16 sm_c[];
    int t = threadIdx.x, lane = t & 31, wid = t >> 5;
    int b = blockIdx.z;
    int tokbase = b * MM + blockIdx.x * 128;
    int d0 = blockIdx.y * 128;
    int wm = wid & 1, wn = wid >> 1;
    float acc[4][4][4];
    #pragma unroll
    for (int a = 0; a < 4; a++)
        #pragma unroll
        for (int n = 0; n < 4; n++)
            #pragma unroll
            for (int q = 0; q < 4; q++) acc[a][n][q] = 0.f;

    int a_row = lane & 15;
    int a_col = (lane >> 4) * 8;
    int aB_row = (lane & 7) + ((lane >> 3) & 1) * 8;
    int aB_col = (lane >> 4) * 8;

    #define C_LOAD(c, s) do { \
        __nv_bfloat16* base = sm_c + (s) * C_SST; \
        _Pragma("unroll") \
        for (int i = 0; i < 2; i++) { \
            int idx = t + i * 256; \
            int row = idx >> 2, q = idx & 3; \
            size_t ge = (size_t)(tokbase + row) * NP + (c) * 32 + q * 8; \
            cp_async16(smem_u32(base + row * LDA + q * 8), &g_Eh[ge]); \
            int rowb = idx >> 4, qb = idx & 15; \
            size_t gy = ((size_t)b * NP + (c) * 32 + rowb) * DD + d0 + qb * 8; \
            cp_async16(smem_u32(base + C_ASZ + rowb * LDE + qb * 8), &g_ysh[gy]); \
        } \
    } while (0)

    C_LOAD(0, 0);
    CP_COMMIT();
    C_LOAD(1, 1);
    CP_COMMIT();
    for (int c = 0; c < 4; c++) {
        CP_WAIT1();
        __syncthreads();
        if (c + 2 < 4) C_LOAD(c + 2, (c + 2) % 3);
        CP_COMMIT();
        __nv_bfloat16* sAh = sm_c + (c % 3) * C_SST;
        __nv_bfloat16* sBh = sAh + C_ASZ;
        #pragma unroll
        for (int ks = 0; ks < 2; ks++) {
            uint32_t ah[4][4], bh[4][2];
            #pragma unroll
            for (int a = 0; a < 4; a++) {
                int off = (wm * 64 + a * 16 + a_row) * LDA + ks * 16 + a_col;
                ldsm_x4(ah[a][0], ah[a][1], ah[a][2], ah[a][3], smem_u32(&sAh[off]));
            }
            #pragma unroll
            for (int p = 0; p < 2; p++) {
                int nb = wn * 32 + p * 16 + aB_col;
                int off = (ks * 16 + aB_row) * LDE + nb;
                uint32_t r0, r1, r2, r3;
                ldsm_x4t(r0, r1, r2, r3, smem_u32(&sBh[off]));
                bh[p * 2][0] = r0; bh[p * 2][1] = r1;
                bh[p * 2 + 1][0] = r2; bh[p * 2 + 1][1] = r3;
            }
            #pragma unroll
            for (int a = 0; a < 4; a++)
                #pragma unroll
                for (int n = 0; n < 4; n++)
                    mma_bf16(acc[a][n], ah[a], bh[n]);
        }
    }
    int r0 = lane >> 2, c0 = (lane & 3) * 2;
    #pragma unroll
    for (int a = 0; a < 4; a++) {
        int m0 = tokbase + wm * 64 + a * 16 + r0;
        float rs0 = g_rsinv[m0];
        float rs1 = g_rsinv[m0 + 8];
        #pragma unroll
        for (int n = 0; n < 4; n++) {
            int d = d0 + wn * 32 + n * 8 + c0;
            size_t i0 = (size_t)m0 * DD + d;
            size_t i1 = (size_t)(m0 + 8) * DD + d;
            float2 xv0 = *reinterpret_cast<const float2*>(&x[i0]);
            float2 xv1 = *reinterpret_cast<const float2*>(&x[i1]);
            *reinterpret_cast<float2*>(&y[i0]) =
                make_float2(acc[a][n][0] * rs0 + xv0.x, acc[a][n][1] * rs0 + xv0.y);
            *reinterpret_cast<float2*>(&y[i1]) =
                make_float2(acc[a][n][2] * rs1 + xv1.x, acc[a][n][3] * rs1 + xv1.y);
        }
    }
}

// ---------------------------------------------------------------------------
extern "C" void kernel_launch(void* const* d_in, const int* in_sizes, int n_in,
                              void* d_out, int out_size) {
    const float* x     = (const float*)d_in[0];  // [8,4096,1024]
    const float* phi   = (const float*)d_in[1];  // [1024,64,2]
    const float* scale = (const float*)d_in[2];  // [1]
    const float* W     = (const float*)d_in[3];  // [64,1024,1024]
    const float* bias  = (const float*)d_in[4];  // [64,1024]
    float* y = (float*)d_out;                    // [8,4096,1024]

    const int smem_logits  = 3 * L_SST * 2;                    // 61440
    const int smem_xs      = 3 * X_SST * 2;                    // 52224
    const int smem_ys      = (64 * LDW + 16 * LDK) * 2;        // 36096
    const int smem_combine = 3 * C_SST * 2;                    // 56832
    cudaFuncSetAttribute(k_logits_mma, cudaFuncAttributeMaxDynamicSharedMemorySize, smem_logits);
    cudaFuncSetAttribute(k_xs_mma, cudaFuncAttributeMaxDynamicSharedMemorySize, smem_xs);
    cudaFuncSetAttribute(k_ys_mma, cudaFuncAttributeMaxDynamicSharedMemorySize, smem_ys);
    cudaFuncSetAttribute(k_combine_mma, cudaFuncAttributeMaxDynamicSharedMemorySize, smem_combine);

    k_phinorm<<<NP, 256>>>(phi, scale);
    k_rinv<<<BM / 8, 256>>>(x);
    k_logits_mma<<<BM / 128, 256, smem_logits>>>();
    k_colsum<<<BB, NP>>>();
    k_xs_mma<<<dim3(8, BB, 4), 256, smem_xs>>>();
    k_ys_mma<<<dim3(4, NEXP), 256, smem_ys>>>(W, bias);
    k_combine_mma<<<dim3(32, 8, BB), 256, smem_combine>>>(x, y);
}

// round 11
// speedup vs baseline: 1.5818x; 1.0199x over previous
#include <cuda_runtime.h>
#include <cuda_bf16.h>
#include <math.h>
#include <stdint.h>

// Problem constants
#define BB 8
#define MM 4096
#define DD 1024
#define NEXP 64
#define NP 128            // NEXP * PP
#define BM (BB * MM)      // 32768 tokens
#define LOG2E 1.4426950408889634f

static __device__ __constant__ float c_eps = 1e-12f;

// ---- scratch (device globals; no allocation allowed) ----
__device__ __align__(16) __nv_bfloat16 g_phinth[NP * DD];       // phin^T [np][d]
__device__ __align__(16) __nv_bfloat16 g_xh[(size_t)BM * DD];   // x bf16 [tok][d]
__device__ __align__(16) __nv_bfloat16 g_Eh[(size_t)BM * NP];   // E bf16 [tok][np]
__device__ __align__(16) __nv_bfloat16 g_ysh[BB * NP * DD];     // ys bf16 [b*NP+np][d]
__device__ float g_rinv[BM];              // per-token (1/TEMP)/max(||x||,eps)
__device__ float g_part[256 * NP];        // per-mtile column partial sums
__device__ float g_rsinv[BM];             // 1/rowsum (combine denominators)
__device__ float g_xsp[4 * BB * NP * DD]; // partial slot inputs (4 m-segments)

// ============================ helpers =====================================
__device__ __forceinline__ uint32_t smem_u32(const void* p) {
    uint32_t a;
    asm("{ .reg .u64 t; cvta.to.shared.u64 t, %1; cvt.u32.u64 %0, t; }"
        : "=r"(a) : "l"(p));
    return a;
}
__device__ __forceinline__ void cp_async16(uint32_t saddr, const void* gptr) {
    asm volatile("cp.async.cg.shared.global [%0], [%1], 16;"
                 :: "r"(saddr), "l"(gptr));
}
#define CP_COMMIT() asm volatile("cp.async.commit_group;" ::: "memory")
#define CP_WAIT1()  asm volatile("cp.async.wait_group 1;" ::: "memory")
__device__ __forceinline__ void ldsm_x4(uint32_t& r0, uint32_t& r1, uint32_t& r2,
                                        uint32_t& r3, uint32_t a) {
    asm volatile("ldmatrix.sync.aligned.m8n8.x4.shared.b16 {%0,%1,%2,%3}, [%4];"
                 : "=r"(r0), "=r"(r1), "=r"(r2), "=r"(r3) : "r"(a));
}
__device__ __forceinline__ void ldsm_x4t(uint32_t& r0, uint32_t& r1, uint32_t& r2,
                                         uint32_t& r3, uint32_t a) {
    asm volatile("ldmatrix.sync.aligned.m8n8.x4.trans.shared.b16 {%0,%1,%2,%3}, [%4];"
                 : "=r"(r0), "=r"(r1), "=r"(r2), "=r"(r3) : "r"(a));
}
__device__ __forceinline__ void mma_bf16(float* d, const uint32_t* a, const uint32_t* b) {
    asm volatile(
        "mma.sync.aligned.m16n8k16.row.col.f32.bf16.bf16.f32 "
        "{%0,%1,%2,%3}, {%4,%5,%6,%7}, {%8,%9}, {%0,%1,%2,%3};"
        : "+f"(d[0]), "+f"(d[1]), "+f"(d[2]), "+f"(d[3])
        : "r"(a[0]), "r"(a[1]), "r"(a[2]), "r"(a[3]), "r"(b[0]), "r"(b[1]));
}
__device__ __forceinline__ float ex2f(float x) {
    float r;
    asm("ex2.approx.f32 %0, %1;" : "=f"(r) : "f"(x));
    return r;
}
__device__ __forceinline__ float warpReduceSum(float v) {
    v += __shfl_down_sync(0xffffffffu, v, 16);
    v += __shfl_down_sync(0xffffffffu, v, 8);
    v += __shfl_down_sync(0xffffffffu, v, 4);
    v += __shfl_down_sync(0xffffffffu, v, 2);
    v += __shfl_down_sync(0xffffffffu, v, 1);
    return v;
}

// ===========================================================================
// K1: phin^T bf16
__global__ void k_phinorm(const float* __restrict__ phi, const float* __restrict__ scale) {
    int np = blockIdx.x;
    int t = threadIdx.x;
    float s = 0.f;
    for (int d = t; d < DD; d += 256) {
        float v = phi[d * NP + np];
        s += v * v;
    }
    __shared__ float red[8];
    s = warpReduceSum(s);
    if ((t & 31) == 0) red[t >> 5] = s;
    __syncthreads();
    if (t < 32) {
        float v = (t < 8) ? red[t] : 0.f;
        v = warpReduceSum(v);
        if (t == 0) red[0] = scale[0] / fmaxf(sqrtf(v), c_eps);
    }
    __syncthreads();
    float rn = red[0];
    for (int d = t; d < DD; d += 256)
        g_phinth[np * DD + d] = __float2bfloat16_rn(phi[d * NP + np] * rn);
}

// K2: row norms + x -> bf16. Warp per token.
__global__ void k_rinv(const float* __restrict__ x) {
    int w = threadIdx.x >> 5;
    int lane = threadIdx.x & 31;
    int tok = blockIdx.x * 8 + w;
    const float4* xr = reinterpret_cast<const float4*>(x + (size_t)tok * DD);
    float s = 0.f;
    #pragma unroll
    for (int i = 0; i < 8; i++) {
        float4 v = xr[lane + i * 32];
        s += v.x * v.x + v.y * v.y + v.z * v.z + v.w * v.w;
        __nv_bfloat162 p0 = __halves2bfloat162(__float2bfloat16_rn(v.x), __float2bfloat16_rn(v.y));
        __nv_bfloat162 p1 = __halves2bfloat162(__float2bfloat16_rn(v.z), __float2bfloat16_rn(v.w));
        size_t off = (size_t)tok * DD + (lane + i * 32) * 4;
        *reinterpret_cast<__nv_bfloat162*>(&g_xh[off])     = p0;
        *reinterpret_cast<__nv_bfloat162*>(&g_xh[off + 2]) = p1;
    }
    s = warpReduceSum(s);
    if (lane == 0) g_rinv[tok] = 10.0f / fmaxf(sqrtf(s), c_eps);  // 1/TEMP
}

// ===========================================================================
// K3 (mma, cp.async 3-stage): E = exp2((x . phin) * rinv * log2e), bf16 out.
// CTA 128m x 128n, K chunks of 32. Fused rowsum + column partials.
#define LDA 40
#define L_AST (128 * LDA)
#define L_SST (2 * L_AST)
__global__ __launch_bounds__(256) void k_logits_mma() {
    extern __shared__ __nv_bfloat16 sm_l[];
    int t = threadIdx.x, lane = t & 31, wid = t >> 5;
    int tok0 = blockIdx.x * 128;
    int wm = wid & 1, wn = wid >> 1;
    float acc[4][4][4];
    #pragma unroll
    for (int a = 0; a < 4; a++)
        #pragma unroll
        for (int n = 0; n < 4; n++)
            #pragma unroll
            for (int q = 0; q < 4; q++) acc[a][n][q] = 0.f;

    int a_row = lane & 15;
    int a_col = (lane >> 4) * 8;
    int b_row = (lane & 7) + ((lane >> 4) << 3);
    int b_col = ((lane >> 3) & 1) * 8;

    #define L_LOAD(c, s) do { \
        __nv_bfloat16* base = sm_l + (s) * L_SST; \
        _Pragma("unroll") \
        for (int i = 0; i < 2; i++) { \
            int idx = t + i * 256; \
            int row = idx >> 2, q = idx & 3; \
            size_t ga = (size_t)(tok0 + row) * DD + (c) * 32 + q * 8; \
            size_t gb = (size_t)row * DD + (c) * 32 + q * 8; \
            int so = row * LDA + q * 8; \
            cp_async16(smem_u32(base + so), &g_xh[ga]); \
            cp_async16(smem_u32(base + L_AST + so), &g_phinth[gb]); \
        } \
    } while (0)

    L_LOAD(0, 0);
    CP_COMMIT();
    L_LOAD(1, 1);
    CP_COMMIT();
    for (int c = 0; c < 32; c++) {
        CP_WAIT1();
        __syncthreads();
        if (c + 2 < 32) L_LOAD(c + 2, (c + 2) % 3);
        CP_COMMIT();
        __nv_bfloat16* sAh = sm_l + (c % 3) * L_SST;
        __nv_bfloat16* sBh = sAh + L_AST;
        #pragma unroll
        for (int ks = 0; ks < 2; ks++) {
            uint32_t ah[4][4], bh[4][2];
            #pragma unroll
            for (int a = 0; a < 4; a++) {
                int off = (wm * 64 + a * 16 + a_row) * LDA + ks * 16 + a_col;
                ldsm_x4(ah[a][0], ah[a][1], ah[a][2], ah[a][3], smem_u32(&sAh[off]));
            }
            #pragma unroll
            for (int p = 0; p < 2; p++) {
                int off = (wn * 32 + p * 16 + b_row) * LDA + ks * 16 + b_col;
                uint32_t r0, r1, r2, r3;
                ldsm_x4(r0, r1, r2, r3, smem_u32(&sBh[off]));
                bh[p * 2][0] = r0; bh[p * 2][1] = r1;
                bh[p * 2 + 1][0] = r2; bh[p * 2 + 1][1] = r3;
            }
            #pragma unroll
            for (int a = 0; a < 4; a++)
                #pragma unroll
                for (int n = 0; n < 4; n++)
                    mma_bf16(acc[a][n], ah[a], bh[n]);
        }
    }
    // epilogue: exp2, store bf16; accumulate row/col sums (fp32, pre-rounding)
    int r0 = lane >> 2, c0 = (lane & 3) * 2;
    float rsum[4][2];
    float csum[4][2];
    #pragma unroll
    for (int a = 0; a < 4; a++) { rsum[a][0] = 0.f; rsum[a][1] = 0.f; }
    #pragma unroll
    for (int n = 0; n < 4; n++) { csum[n][0] = 0.f; csum[n][1] = 0.f; }
    __syncthreads();
    #pragma unroll
    for (int a = 0; a < 4; a++) {
        int row = tok0 + wm * 64 + a * 16 + r0;
        float rv0 = g_rinv[row] * LOG2E;
        float rv1 = g_rinv[row + 8] * LOG2E;
        #pragma unroll
        for (int n = 0; n < 4; n++) {
            int col = wn * 32 + n * 8 + c0;
            float e0 = ex2f(acc[a][n][0] * rv0), e1 = ex2f(acc[a][n][1] * rv0);
            float e2 = ex2f(acc[a][n][2] * rv1), e3 = ex2f(acc[a][n][3] * rv1);
            rsum[a][0] += e0 + e1;
            rsum[a][1] += e2 + e3;
            csum[n][0] += e0 + e2;
            csum[n][1] += e1 + e3;
            *reinterpret_cast<__nv_bfloat162*>(&g_Eh[(size_t)row * NP + col]) =
                __halves2bfloat162(__float2bfloat16_rn(e0), __float2bfloat16_rn(e1));
            *reinterpret_cast<__nv_bfloat162*>(&g_Eh[(size_t)(row + 8) * NP + col]) =
                __halves2bfloat162(__float2bfloat16_rn(e2), __float2bfloat16_rn(e3));
        }
    }
    float* srow = reinterpret_cast<float*>(sm_l);   // [4 wn][128 rows]
    float* scol = srow + 4 * 128;                   // [2 wm][128 cols]
    __syncthreads();
    #pragma unroll
    for (int a = 0; a < 4; a++)
        #pragma unroll
        for (int h = 0; h < 2; h++) {
            float v = rsum[a][h];
            v += __shfl_xor_sync(0xffffffffu, v, 1);
            v += __shfl_xor_sync(0xffffffffu, v, 2);
            if ((lane & 3) == 0)
                srow[wn * 128 + wm * 64 + a * 16 + h * 8 + r0] = v;
        }
    #pragma unroll
    for (int n = 0; n < 4; n++)
        #pragma unroll
        for (int q1 = 0; q1 < 2; q1++) {
            float v = csum[n][q1];
            v += __shfl_xor_sync(0xffffffffu, v, 4);
            v += __shfl_xor_sync(0xffffffffu, v, 8);
            v += __shfl_xor_sync(0xffffffffu, v, 16);
            if (lane < 4)
                scol[wm * 128 + wn * 32 + n * 8 + lane * 2 + q1] = v;
        }
    __syncthreads();
    if (t < 128) {
        float rs = srow[t] + srow[128 + t] + srow[256 + t] + srow[384 + t];
        g_rsinv[tok0 + t] = 1.0f / rs;
        g_part[blockIdx.x * NP + t] = scol[t] + scol[128 + t];
    }
}

// ===========================================================================
// K5 (mma, cp.async 3-stage): xsp[seg][b][np][d] = sum_{m in seg} E[m][np]*x[m][d]
#define LDE 136
#define X_AST (32 * LDE)
#define X_SST (2 * X_AST)
__global__ __launch_bounds__(256) void k_xs_mma() {
    extern __shared__ __nv_bfloat16 sm_x[];
    int t = threadIdx.x, lane = t & 31, wid = t >> 5;
    int d0 = blockIdx.x * 128;
    int b = blockIdx.y;
    int seg = blockIdx.z;
    int base = b * MM + seg * 1024;
    int wm = wid & 1, wn = wid >> 1;
    float acc[4][4][4];
    #pragma unroll
    for (int a = 0; a < 4; a++)
        #pragma unroll
        for (int n = 0; n < 4; n++)
            #pragma unroll
            for (int q = 0; q < 4; q++) acc[a][n][q] = 0.f;

    int aA_col = ((lane >> 3) & 1) * 8;
    int aA_row = (lane & 7) + (lane >> 4) * 8;
    int aB_row = (lane & 7) + ((lane >> 3) & 1) * 8;
    int aB_col = (lane >> 4) * 8;

    #define X_LOAD(c, s) do { \
        __nv_bfloat16* bb_ = sm_x + (s) * X_SST; \
        _Pragma("unroll") \
        for (int i = 0; i < 2; i++) { \
            int idx = t + i * 256; \
            int row = idx >> 4, q = idx & 15; \
            size_t ge = (size_t)(base + (c) * 32 + row) * NP + q * 8; \
            size_t gx = (size_t)(base + (c) * 32 + row) * DD + d0 + q * 8; \
            int so = row * LDE + q * 8; \
            cp_async16(smem_u32(bb_ + so), &g_Eh[ge]); \
            cp_async16(smem_u32(bb_ + X_AST + so), &g_xh[gx]); \
        } \
    } while (0)

    X_LOAD(0, 0);
    CP_COMMIT();
    X_LOAD(1, 1);
    CP_COMMIT();
    for (int c = 0; c < 32; c++) {
        CP_WAIT1();
        __syncthreads();
        if (c + 2 < 32) X_LOAD(c + 2, (c + 2) % 3);
        CP_COMMIT();
        __nv_bfloat16* sEh = sm_x + (c % 3) * X_SST;
        __nv_bfloat16* sXh = sEh + X_AST;
        #pragma unroll
        for (int ks = 0; ks < 2; ks++) {
            uint32_t ah[4][4], bh[4][2];
            #pragma unroll
            for (int a = 0; a < 4; a++) {
                int npb = wm * 64 + a * 16 + aA_col;
                int off = (ks * 16 + aA_row) * LDE + npb;
                ldsm_x4t(ah[a][0], ah[a][1], ah[a][2], ah[a][3], smem_u32(&sEh[off]));
            }
            #pragma unroll
            for (int p = 0; p < 2; p++) {
                int nb = wn * 32 + p * 16 + aB_col;
                int off = (ks * 16 + aB_row) * LDE + nb;
                uint32_t r0, r1, r2, r3;
                ldsm_x4t(r0, r1, r2, r3, smem_u32(&sXh[off]));
                bh[p * 2][0] = r0; bh[p * 2][1] = r1;
                bh[p * 2 + 1][0] = r2; bh[p * 2 + 1][1] = r3;
            }
            #pragma unroll
            for (int a = 0; a < 4; a++)
                #pragma unroll
                for (int n = 0; n < 4; n++)
                    mma_bf16(acc[a][n], ah[a], bh[n]);
        }
    }
    int r0 = lane >> 2, c0 = (lane & 3) * 2;
    #pragma unroll
    for (int a = 0; a < 4; a++) {
        int np = wm * 64 + a * 16 + r0;
        #pragma unroll
        for (int n = 0; n < 4; n++) {
            int d = d0 + wn * 32 + n * 8 + c0;
            float* dst0 = &g_xsp[(((size_t)seg * BB + b) * NP + np) * DD + d];
            float* dst1 = &g_xsp[(((size_t)seg * BB + b) * NP + np + 8) * DD + d];
            *reinterpret_cast<float2*>(dst0) = make_float2(acc[a][n][0], acc[a][n][1]);
            *reinterpret_cast<float2*>(dst1) = make_float2(acc[a][n][2], acc[a][n][3]);
        }
    }
}

// ===========================================================================
// K6 (mma, cp.async W staging): ys[(b,p)][e] = sum_d xs*W + bias.
// K chunks of 32; W staged fp32 via cp.async (2 stages), converted from smem.
// Colsum reduce folded in (reads g_part directly).
#define LDW 264
#define LDK 40
#define YLDWF 264                         // fp32 stage row stride (floats)
#define Y_FST (32 * YLDWF)                // floats per W stage
#define Y_WT (32 * LDW)                   // bf16 elems per W tile
#define Y_AT (16 * LDK)                   // bf16 elems per A tile
__global__ __launch_bounds__(256) void k_ys_mma(const float* __restrict__ W,
                                                const float* __restrict__ bias) {
    extern __shared__ char sm_raw_y[];
    float* sWf = reinterpret_cast<float*>(sm_raw_y);                 // 2 stages fp32
    __nv_bfloat16* sWh = reinterpret_cast<__nv_bfloat16*>(sm_raw_y + 2 * Y_FST * 4); // 2 tiles
    __nv_bfloat16* sAh = sWh + 2 * Y_WT;                             // 2 tiles
    int t = threadIdx.x, lane = t & 31, wid = t >> 5;
    int nexp = blockIdx.y;
    int e0 = blockIdx.x * 256;
    float acc[4][4];
    #pragma unroll
    for (int n = 0; n < 4; n++)
        #pragma unroll
        for (int q = 0; q < 4; q++) acc[n][q] = 0.f;

    int a_row = lane & 15;
    int a_col = (lane >> 4) * 8;
    int aB_row = (lane & 7) + ((lane >> 3) & 1) * 8;
    int aB_col = (lane >> 4) * 8;

    // folded colsum: per-thread A row state (t<128)
    int arow = t >> 3, aq = t & 7;        // row 0..15, col-group 0..7 (4 floats)
    int abb = arow >> 1, ap = arow & 1;
    float ainv = 0.f;
    if (t < 128) {
        int npi = nexp * 2 + ap;
        float cs = 0.f;
        #pragma unroll
        for (int i = 0; i < 32; i++)
            cs += g_part[(abb * 32 + i) * NP + npi];
        ainv = 1.0f / cs;
    }
    size_t abase = ((size_t)abb * NP + nexp * 2 + ap) * DD + aq * 4;

    // W stage load: 32 k-rows x 256 e = 2048 float4; 8 per thread
    #define Y_LOAD(c, s) do { \
        float* dst = sWf + (s) * Y_FST; \
        _Pragma("unroll") \
        for (int i = 0; i < 8; i++) { \
            int idx = t + i * 256; \
            int row = idx >> 6, q = idx & 63; \
            cp_async16(smem_u32(dst + row * YLDWF + q * 4), \
                       &W[((size_t)nexp * DD + (c) * 32 + row) * DD + e0 + q * 4]); \
        } \
    } while (0)

    Y_LOAD(0, 0);
    CP_COMMIT();
    Y_LOAD(1, 1);
    CP_COMMIT();
    for (int c = 0; c < 32; c++) {
        CP_WAIT1();
        __syncthreads();
        // convert W stage -> bf16 tile (each thread 4x8 floats)
        {
            const float* src = sWf + (c & 1) * Y_FST;
            __nv_bfloat16* dst = sWh + (c & 1) * Y_WT;
            #pragma unroll
            for (int i = 0; i < 4; i++) {
                int idx = t + i * 256;
                int row = idx >> 5, q = idx & 31;    // 32 rows x 32 groups of 8
                const float* sp = src + row * YLDWF + q * 8;
                float4 v0 = *reinterpret_cast<const float4*>(sp);
                float4 v1 = *reinterpret_cast<const float4*>(sp + 4);
                uint32_t hs[8];
                hs[0] = (uint32_t)__bfloat16_as_ushort(__float2bfloat16_rn(v0.x));
                hs[1] = (uint32_t)__bfloat16_as_ushort(__float2bfloat16_rn(v0.y));
                hs[2] = (uint32_t)__bfloat16_as_ushort(__float2bfloat16_rn(v0.z));
                hs[3] = (uint32_t)__bfloat16_as_ushort(__float2bfloat16_rn(v0.w));
                hs[4] = (uint32_t)__bfloat16_as_ushort(__float2bfloat16_rn(v1.x));
                hs[5] = (uint32_t)__bfloat16_as_ushort(__float2bfloat16_rn(v1.y));
                hs[6] = (uint32_t)__bfloat16_as_ushort(__float2bfloat16_rn(v1.z));
                hs[7] = (uint32_t)__bfloat16_as_ushort(__float2bfloat16_rn(v1.w));
                uint4 hi = {hs[0] | (hs[1] << 16), hs[2] | (hs[3] << 16),
                            hs[4] | (hs[5] << 16), hs[6] | (hs[7] << 16)};
                *reinterpret_cast<uint4*>(&dst[row * LDW + q * 8]) = hi;
            }
        }
        // A tile: 16 rows x 32 k, 4-seg sum * ainv, convert
        if (t < 128) {
            size_t off = abase + c * 32;
            float4 v0 = *reinterpret_cast<const float4*>(&g_xsp[off]);
            #pragma unroll
            for (int seg = 1; seg < 4; seg++) {
                float4 w0 = *reinterpret_cast<const float4*>(
                    &g_xsp[(size_t)seg * BB * NP * DD + off]);
                v0.x += w0.x; v0.y += w0.y; v0.z += w0.z; v0.w += w0.w;
            }
            uint32_t h0 = (uint32_t)__bfloat16_as_ushort(__float2bfloat16_rn(v0.x * ainv));
            uint32_t h1 = (uint32_t)__bfloat16_as_ushort(__float2bfloat16_rn(v0.y * ainv));
            uint32_t h2 = (uint32_t)__bfloat16_as_ushort(__float2bfloat16_rn(v0.z * ainv));
            uint32_t h3 = (uint32_t)__bfloat16_as_ushort(__float2bfloat16_rn(v0.w * ainv));
            uint2 pk = {h0 | (h1 << 16), h2 | (h3 << 16)};
            *reinterpret_cast<uint2*>(&sAh[(c & 1) * Y_AT + arow * LDK + aq * 4]) = pk;
        }
        __syncthreads();
        if (c + 2 < 32) { Y_LOAD(c + 2, c & 1); }
        CP_COMMIT();
        // mma on tile (c&1)
        __nv_bfloat16* tW = sWh + (c & 1) * Y_WT;
        __nv_bfloat16* tA = sAh + (c & 1) * Y_AT;
        #pragma unroll
        for (int ks = 0; ks < 2; ks++) {
            uint32_t ah[4], bh[4][2];
            {
                int off = a_row * LDK + ks * 16 + a_col;
                ldsm_x4(ah[0], ah[1], ah[2], ah[3], smem_u32(&tA[off]));
            }
            #pragma unroll
            for (int p = 0; p < 2; p++) {
                int nb = wid * 32 + p * 16 + aB_col;
                int off = (ks * 16 + aB_row) * LDW + nb;
                uint32_t r0, r1, r2, r3;
                ldsm_x4t(r0, r1, r2, r3, smem_u32(&tW[off]));
                bh[p * 2][0] = r0; bh[p * 2][1] = r1;
                bh[p * 2 + 1][0] = r2; bh[p * 2 + 1][1] = r3;
            }
            #pragma unroll
            for (int n = 0; n < 4; n++)
                mma_bf16(acc[n], ah, bh[n]);
        }
    }
    int r0 = lane >> 2, c0 = (lane & 3) * 2;
    #pragma unroll
    for (int n = 0; n < 4; n++) {
        int e = e0 + wid * 32 + n * 8 + c0;
        float2 bv = *reinterpret_cast<const float2*>(&bias[nexp * DD + e]);
        #pragma unroll
        for (int h = 0; h < 2; h++) {
            int row = r0 + h * 8;
            int bb = row >> 1, p = row & 1;
            float v0 = acc[n][h * 2 + 0] + bv.x;
            float v1 = acc[n][h * 2 + 1] + bv.y;
            size_t o = ((size_t)bb * NP + nexp * 2 + p) * DD + e;
            *reinterpret_cast<__nv_bfloat162*>(&g_ysh[o]) =
                __halves2bfloat162(__float2bfloat16_rn(v0), __float2bfloat16_rn(v1));
        }
    }
}

// ===========================================================================
// K7 (mma, cp.async 3-stage): y[m][d] = rsinv[m]*sum_np E[m][np]*ys[np][d] + x[m][d]
#define C_ASZ (128 * LDA)
#define C_BSZ (32 * LDE)
#define C_SST (C_ASZ + C_BSZ)
__global__ __launch_bounds__(256) void k_combine_mma(const float* __restrict__ x,
                                                     float* __restrict__ y) {
    extern __shared__ __nv_bfloat16 sm_c[];
    int t = threadIdx.x, lane = t & 31, wid = t >> 5;
    int b = blockIdx.z;
    int tokbase = b * MM + blockIdx.x * 128;
    int d0 = blockIdx.y * 128;
    int wm = wid & 1, wn = wid >> 1;
    float acc[4][4][4];
    #pragma unroll
    for (int a = 0; a < 4; a++)
        #pragma unroll
        for (int n = 0; n < 4; n++)
            #pragma unroll
            for (int q = 0; q < 4; q++) acc[a][n][q] = 0.f;

    int a_row = lane & 15;
    int a_col = (lane >> 4) * 8;
    int aB_row = (lane & 7) + ((lane >> 3) & 1) * 8;
    int aB_col = (lane >> 4) * 8;

    #define C_LOAD(c, s) do { \
        __nv_bfloat16* base = sm_c + (s) * C_SST; \
        _Pragma("unroll") \
        for (int i = 0; i < 2; i++) { \
            int idx = t + i * 256; \
            int row = idx >> 2, q = idx & 3; \
            size_t ge = (size_t)(tokbase + row) * NP + (c) * 32 + q * 8; \
            cp_async16(smem_u32(base + row * LDA + q * 8), &g_Eh[ge]); \
            int rowb = idx >> 4, qb = idx & 15; \
            size_t gy = ((size_t)b * NP + (c) * 32 + rowb) * DD + d0 + qb * 8; \
            cp_async16(smem_u32(base + C_ASZ + rowb * LDE + qb * 8), &g_ysh[gy]); \
        } \
    } while (0)

    C_LOAD(0, 0);
    CP_COMMIT();
    C_LOAD(1, 1);
    CP_COMMIT();
    for (int c = 0; c < 4; c++) {
        CP_WAIT1();
        __syncthreads();
        if (c + 2 < 4) C_LOAD(c + 2, (c + 2) % 3);
        CP_COMMIT();
        __nv_bfloat16* sAh = sm_c + (c % 3) * C_SST;
        __nv_bfloat16* sBh = sAh + C_ASZ;
        #pragma unroll
        for (int ks = 0; ks < 2; ks++) {
            uint32_t ah[4][4], bh[4][2];
            #pragma unroll
            for (int a = 0; a < 4; a++) {
                int off = (wm * 64 + a * 16 + a_row) * LDA + ks * 16 + a_col;
                ldsm_x4(ah[a][0], ah[a][1], ah[a][2], ah[a][3], smem_u32(&sAh[off]));
            }
            #pragma unroll
            for (int p = 0; p < 2; p++) {
                int nb = wn * 32 + p * 16 + aB_col;
                int off = (ks * 16 + aB_row) * LDE + nb;
                uint32_t r0, r1, r2, r3;
                ldsm_x4t(r0, r1, r2, r3, smem_u32(&sBh[off]));
                bh[p * 2][0] = r0; bh[p * 2][1] = r1;
                bh[p * 2 + 1][0] = r2; bh[p * 2 + 1][1] = r3;
            }
            #pragma unroll
            for (int a = 0; a < 4; a++)
                #pragma unroll
                for (int n = 0; n < 4; n++)
                    mma_bf16(acc[a][n], ah[a], bh[n]);
        }
    }
    int r0 = lane >> 2, c0 = (lane & 3) * 2;
    #pragma unroll
    for (int a = 0; a < 4; a++) {
        int m0 = tokbase + wm * 64 + a * 16 + r0;
        float rs0 = g_rsinv[m0];
        float rs1 = g_rsinv[m0 + 8];
        #pragma unroll
        for (int n = 0; n < 4; n++) {
            int d = d0 + wn * 32 + n * 8 + c0;
            size_t i0 = (size_t)m0 * DD + d;
            size_t i1 = (size_t)(m0 + 8) * DD + d;
            float2 xv0 = *reinterpret_cast<const float2*>(&x[i0]);
            float2 xv1 = *reinterpret_cast<const float2*>(&x[i1]);
            *reinterpret_cast<float2*>(&y[i0]) =
                make_float2(acc[a][n][0] * rs0 + xv0.x, acc[a][n][1] * rs0 + xv0.y);
            *reinterpret_cast<float2*>(&y[i1]) =
                make_float2(acc[a][n][2] * rs1 + xv1.x, acc[a][n][3] * rs1 + xv1.y);
        }
    }
}

// ---------------------------------------------------------------------------
extern "C" void kernel_launch(void* const* d_in, const int* in_sizes, int n_in,
                              void* d_out, int out_size) {
    const float* x     = (const float*)d_in[0];  // [8,4096,1024]
    const float* phi   = (const float*)d_in[1];  // [1024,64,2]
    const float* scale = (const float*)d_in[2];  // [1]
    const float* W     = (const float*)d_in[3];  // [64,1024,1024]
    const float* bias  = (const float*)d_in[4];  // [64,1024]
    float* y = (float*)d_out;                    // [8,4096,1024]

    const int smem_logits  = 3 * L_SST * 2;                             // 61440
    const int smem_xs      = 3 * X_SST * 2;                             // 52224
    const int smem_ys      = 2 * Y_FST * 4 + 2 * Y_WT * 2 + 2 * Y_AT * 2; // 104448
    const int smem_combine = 3 * C_SST * 2;                             // 56832
    cudaFuncSetAttribute(k_logits_mma, cudaFuncAttributeMaxDynamicSharedMemorySize, smem_logits);
    cudaFuncSetAttribute(k_xs_mma, cudaFuncAttributeMaxDynamicSharedMemorySize, smem_xs);
    cudaFuncSetAttribute(k_ys_mma, cudaFuncAttributeMaxDynamicSharedMemorySize, smem_ys);
    cudaFuncSetAttribute(k_combine_mma, cudaFuncAttributeMaxDynamicSharedMemorySize, smem_combine);

    k_phinorm<<<NP, 256>>>(phi, scale);
    k_rinv<<<BM / 8, 256>>>(x);
    k_logits_mma<<<BM / 128, 256, smem_logits>>>();
    k_xs_mma<<<dim3(8, BB, 4), 256, smem_xs>>>();
    k_ys_mma<<<dim3(4, NEXP), 256, smem_ys>>>(W, bias);
    k_combine_mma<<<dim3(32, 8, BB), 256, smem_combine>>>(x, y);
}

// round 12
// speedup vs baseline: 1.5937x; 1.0075x over previous
#include <cuda_runtime.h>
#include <cuda_bf16.h>
#include <math.h>
#include <stdint.h>

// Problem constants
#define BB 8
#define MM 4096
#define DD 1024
#define NEXP 64
#define NP 128            // NEXP * PP
#define BM (BB * MM)      // 32768 tokens
#define LOG2E 1.4426950408889634f

static __device__ __constant__ float c_eps = 1e-12f;

// ---- scratch (device globals; no allocation allowed) ----
__device__ __align__(16) __nv_bfloat16 g_phinth[NP * DD];       // phin^T [np][d]
__device__ __align__(16) __nv_bfloat16 g_xh[(size_t)BM * DD];   // x bf16 [tok][d]
__device__ __align__(16) __nv_bfloat16 g_Eh[(size_t)BM * NP];   // E bf16 [tok][np]
__device__ __align__(16) __nv_bfloat16 g_ysh[BB * NP * DD];     // ys bf16 [b*NP+np][d]
__device__ __align__(16) __nv_bfloat16 g_xspb[(size_t)4 * BB * NP * DD]; // bf16 partial slot inputs
__device__ float g_rinv[BM];              // per-token (1/TEMP)/max(||x||,eps)
__device__ float g_part[256 * NP];        // per-mtile column partial sums
__device__ float g_rsinv[BM];             // 1/rowsum (combine denominators)

// ============================ helpers =====================================
__device__ __forceinline__ uint32_t smem_u32(const void* p) {
    uint32_t a;
    asm("{ .reg .u64 t; cvta.to.shared.u64 t, %1; cvt.u32.u64 %0, t; }"
        : "=r"(a) : "l"(p));
    return a;
}
__device__ __forceinline__ void cp_async16(uint32_t saddr, const void* gptr) {
    asm volatile("cp.async.cg.shared.global [%0], [%1], 16;"
                 :: "r"(saddr), "l"(gptr));
}
#define CP_COMMIT() asm volatile("cp.async.commit_group;" ::: "memory")
#define CP_WAIT1()  asm volatile("cp.async.wait_group 1;" ::: "memory")
__device__ __forceinline__ void ldsm_x4(uint32_t& r0, uint32_t& r1, uint32_t& r2,
                                        uint32_t& r3, uint32_t a) {
    asm volatile("ldmatrix.sync.aligned.m8n8.x4.shared.b16 {%0,%1,%2,%3}, [%4];"
                 : "=r"(r0), "=r"(r1), "=r"(r2), "=r"(r3) : "r"(a));
}
__device__ __forceinline__ void ldsm_x4t(uint32_t& r0, uint32_t& r1, uint32_t& r2,
                                         uint32_t& r3, uint32_t a) {
    asm volatile("ldmatrix.sync.aligned.m8n8.x4.trans.shared.b16 {%0,%1,%2,%3}, [%4];"
                 : "=r"(r0), "=r"(r1), "=r"(r2), "=r"(r3) : "r"(a));
}
__device__ __forceinline__ void mma_bf16(float* d, const uint32_t* a, const uint32_t* b) {
    asm volatile(
        "mma.sync.aligned.m16n8k16.row.col.f32.bf16.bf16.f32 "
        "{%0,%1,%2,%3}, {%4,%5,%6,%7}, {%8,%9}, {%0,%1,%2,%3};"
        : "+f"(d[0]), "+f"(d[1]), "+f"(d[2]), "+f"(d[3])
        : "r"(a[0]), "r"(a[1]), "r"(a[2]), "r"(a[3]), "r"(b[0]), "r"(b[1]));
}
__device__ __forceinline__ float ex2f(float x) {
    float r;
    asm("ex2.approx.f32 %0, %1;" : "=f"(r) : "f"(x));
    return r;
}
__device__ __forceinline__ float warpReduceSum(float v) {
    v += __shfl_down_sync(0xffffffffu, v, 16);
    v += __shfl_down_sync(0xffffffffu, v, 8);
    v += __shfl_down_sync(0xffffffffu, v, 4);
    v += __shfl_down_sync(0xffffffffu, v, 2);
    v += __shfl_down_sync(0xffffffffu, v, 1);
    return v;
}

// ===========================================================================
// K1: phin^T bf16
__global__ void k_phinorm(const float* __restrict__ phi, const float* __restrict__ scale) {
    int np = blockIdx.x;
    int t = threadIdx.x;
    float s = 0.f;
    for (int d = t; d < DD; d += 256) {
        float v = phi[d * NP + np];
        s += v * v;
    }
    __shared__ float red[8];
    s = warpReduceSum(s);
    if ((t & 31) == 0) red[t >> 5] = s;
    __syncthreads();
    if (t < 32) {
        float v = (t < 8) ? red[t] : 0.f;
        v = warpReduceSum(v);
        if (t == 0) red[0] = scale[0] / fmaxf(sqrtf(v), c_eps);
    }
    __syncthreads();
    float rn = red[0];
    for (int d = t; d < DD; d += 256)
        g_phinth[np * DD + d] = __float2bfloat16_rn(phi[d * NP + np] * rn);
}

// K2: row norms + x -> bf16. Warp per token.
__global__ void k_rinv(const float* __restrict__ x) {
    int w = threadIdx.x >> 5;
    int lane = threadIdx.x & 31;
    int tok = blockIdx.x * 8 + w;
    const float4* xr = reinterpret_cast<const float4*>(x + (size_t)tok * DD);
    float s = 0.f;
    #pragma unroll
    for (int i = 0; i < 8; i++) {
        float4 v = xr[lane + i * 32];
        s += v.x * v.x + v.y * v.y + v.z * v.z + v.w * v.w;
        __nv_bfloat162 p0 = __halves2bfloat162(__float2bfloat16_rn(v.x), __float2bfloat16_rn(v.y));
        __nv_bfloat162 p1 = __halves2bfloat162(__float2bfloat16_rn(v.z), __float2bfloat16_rn(v.w));
        size_t off = (size_t)tok * DD + (lane + i * 32) * 4;
        *reinterpret_cast<__nv_bfloat162*>(&g_xh[off])     = p0;
        *reinterpret_cast<__nv_bfloat162*>(&g_xh[off + 2]) = p1;
    }
    s = warpReduceSum(s);
    if (lane == 0) g_rinv[tok] = 10.0f / fmaxf(sqrtf(s), c_eps);  // 1/TEMP
}

// ===========================================================================
// K3 (mma, cp.async 3-stage): E = exp2((x . phin) * rinv * log2e), bf16 out.
// CTA 128m x 128n, K chunks of 32. Fused rowsum + column partials.
#define LDA 40
#define L_AST (128 * LDA)
#define L_SST (2 * L_AST)
__global__ __launch_bounds__(256) void k_logits_mma() {
    extern __shared__ __nv_bfloat16 sm_l[];
    int t = threadIdx.x, lane = t & 31, wid = t >> 5;
    int tok0 = blockIdx.x * 128;
    int wm = wid & 1, wn = wid >> 1;
    float acc[4][4][4];
    #pragma unroll
    for (int a = 0; a < 4; a++)
        #pragma unroll
        for (int n = 0; n < 4; n++)
            #pragma unroll
            for (int q = 0; q < 4; q++) acc[a][n][q] = 0.f;

    int a_row = lane & 15;
    int a_col = (lane >> 4) * 8;
    int b_row = (lane & 7) + ((lane >> 4) << 3);
    int b_col = ((lane >> 3) & 1) * 8;

    #define L_LOAD(c, s) do { \
        __nv_bfloat16* base = sm_l + (s) * L_SST; \
        _Pragma("unroll") \
        for (int i = 0; i < 2; i++) { \
            int idx = t + i * 256; \
            int row = idx >> 2, q = idx & 3; \
            size_t ga = (size_t)(tok0 + row) * DD + (c) * 32 + q * 8; \
            size_t gb = (size_t)row * DD + (c) * 32 + q * 8; \
            int so = row * LDA + q * 8; \
            cp_async16(smem_u32(base + so), &g_xh[ga]); \
            cp_async16(smem_u32(base + L_AST + so), &g_phinth[gb]); \
        } \
    } while (0)

    L_LOAD(0, 0);
    CP_COMMIT();
    L_LOAD(1, 1);
    CP_COMMIT();
    for (int c = 0; c < 32; c++) {
        CP_WAIT1();
        __syncthreads();
        if (c + 2 < 32) L_LOAD(c + 2, (c + 2) % 3);
        CP_COMMIT();
        __nv_bfloat16* sAh = sm_l + (c % 3) * L_SST;
        __nv_bfloat16* sBh = sAh + L_AST;
        #pragma unroll
        for (int ks = 0; ks < 2; ks++) {
            uint32_t ah[4][4], bh[4][2];
            #pragma unroll
            for (int a = 0; a < 4; a++) {
                int off = (wm * 64 + a * 16 + a_row) * LDA + ks * 16 + a_col;
                ldsm_x4(ah[a][0], ah[a][1], ah[a][2], ah[a][3], smem_u32(&sAh[off]));
            }
            #pragma unroll
            for (int p = 0; p < 2; p++) {
                int off = (wn * 32 + p * 16 + b_row) * LDA + ks * 16 + b_col;
                uint32_t r0, r1, r2, r3;
                ldsm_x4(r0, r1, r2, r3, smem_u32(&sBh[off]));
                bh[p * 2][0] = r0; bh[p * 2][1] = r1;
                bh[p * 2 + 1][0] = r2; bh[p * 2 + 1][1] = r3;
            }
            #pragma unroll
            for (int a = 0; a < 4; a++)
                #pragma unroll
                for (int n = 0; n < 4; n++)
                    mma_bf16(acc[a][n], ah[a], bh[n]);
        }
    }
    // epilogue: exp2, store bf16; accumulate row/col sums (fp32, pre-rounding)
    int r0 = lane >> 2, c0 = (lane & 3) * 2;
    float rsum[4][2];
    float csum[4][2];
    #pragma unroll
    for (int a = 0; a < 4; a++) { rsum[a][0] = 0.f; rsum[a][1] = 0.f; }
    #pragma unroll
    for (int n = 0; n < 4; n++) { csum[n][0] = 0.f; csum[n][1] = 0.f; }
    __syncthreads();
    #pragma unroll
    for (int a = 0; a < 4; a++) {
        int row = tok0 + wm * 64 + a * 16 + r0;
        float rv0 = g_rinv[row] * LOG2E;
        float rv1 = g_rinv[row + 8] * LOG2E;
        #pragma unroll
        for (int n = 0; n < 4; n++) {
            int col = wn * 32 + n * 8 + c0;
            float e0 = ex2f(acc[a][n][0] * rv0), e1 = ex2f(acc[a][n][1] * rv0);
            float e2 = ex2f(acc[a][n][2] * rv1), e3 = ex2f(acc[a][n][3] * rv1);
            rsum[a][0] += e0 + e1;
            rsum[a][1] += e2 + e3;
            csum[n][0] += e0 + e2;
            csum[n][1] += e1 + e3;
            *reinterpret_cast<__nv_bfloat162*>(&g_Eh[(size_t)row * NP + col]) =
                __halves2bfloat162(__float2bfloat16_rn(e0), __float2bfloat16_rn(e1));
            *reinterpret_cast<__nv_bfloat162*>(&g_Eh[(size_t)(row + 8) * NP + col]) =
                __halves2bfloat162(__float2bfloat16_rn(e2), __float2bfloat16_rn(e3));
        }
    }
    float* srow = reinterpret_cast<float*>(sm_l);   // [4 wn][128 rows]
    float* scol = srow + 4 * 128;                   // [2 wm][128 cols]
    __syncthreads();
    #pragma unroll
    for (int a = 0; a < 4; a++)
        #pragma unroll
        for (int h = 0; h < 2; h++) {
            float v = rsum[a][h];
            v += __shfl_xor_sync(0xffffffffu, v, 1);
            v += __shfl_xor_sync(0xffffffffu, v, 2);
            if ((lane & 3) == 0)
                srow[wn * 128 + wm * 64 + a * 16 + h * 8 + r0] = v;
        }
    #pragma unroll
    for (int n = 0; n < 4; n++)
        #pragma unroll
        for (int q1 = 0; q1 < 2; q1++) {
            float v = csum[n][q1];
            v += __shfl_xor_sync(0xffffffffu, v, 4);
            v += __shfl_xor_sync(0xffffffffu, v, 8);
            v += __shfl_xor_sync(0xffffffffu, v, 16);
            if (lane < 4)
                scol[wm * 128 + wn * 32 + n * 8 + lane * 2 + q1] = v;
        }
    __syncthreads();
    if (t < 128) {
        float rs = srow[t] + srow[128 + t] + srow[256 + t] + srow[384 + t];
        g_rsinv[tok0 + t] = 1.0f / rs;
        g_part[blockIdx.x * NP + t] = scol[t] + scol[128 + t];
    }
}

// ===========================================================================
// K5 (mma, cp.async 3-stage): xspb[seg][b][np][d] = sum_{m in seg} E[m][np]*x[m][d]
// CTA 128np x 64d, grid (16 dtiles, 8 b, 4 seg) = 512 CTAs. bf16 output.
#define LDE 136
#define LDX 72
#define X_EST (32 * LDE)
#define X_XST (32 * LDX)
#define X_SST (X_EST + X_XST)
__global__ __launch_bounds__(256) void k_xs_mma() {
    extern __shared__ __nv_bfloat16 sm_x[];
    int t = threadIdx.x, lane = t & 31, wid = t >> 5;
    int d0 = blockIdx.x * 64;
    int b = blockIdx.y;
    int seg = blockIdx.z;
    int base = b * MM + seg * 1024;
    int wm = wid >> 1;   // 0..3 np group (32 each)
    int wn = wid & 1;    // 0..1 d group (32 each)
    float acc[2][4][4];
    #pragma unroll
    for (int a = 0; a < 2; a++)
        #pragma unroll
        for (int n = 0; n < 4; n++)
            #pragma unroll
            for (int q = 0; q < 4; q++) acc[a][n][q] = 0.f;

    int aA_col = ((lane >> 3) & 1) * 8;
    int aA_row = (lane & 7) + (lane >> 4) * 8;
    int aB_row = (lane & 7) + ((lane >> 3) & 1) * 8;
    int aB_col = (lane >> 4) * 8;

    #define X_LOAD(c, s) do { \
        __nv_bfloat16* bb_ = sm_x + (s) * X_SST; \
        _Pragma("unroll") \
        for (int i = 0; i < 2; i++) { \
            int idx = t + i * 256; \
            int row = idx >> 4, q = idx & 15; \
            size_t ge = (size_t)(base + (c) * 32 + row) * NP + q * 8; \
            cp_async16(smem_u32(bb_ + row * LDE + q * 8), &g_Eh[ge]); \
        } \
        { \
            int row = t >> 3, q = t & 7; \
            size_t gx = (size_t)(base + (c) * 32 + row) * DD + d0 + q * 8; \
            cp_async16(smem_u32(bb_ + X_EST + row * LDX + q * 8), &g_xh[gx]); \
        } \
    } while (0)

    X_LOAD(0, 0);
    CP_COMMIT();
    X_LOAD(1, 1);
    CP_COMMIT();
    for (int c = 0; c < 32; c++) {
        CP_WAIT1();
        __syncthreads();
        if (c + 2 < 32) X_LOAD(c + 2, (c + 2) % 3);
        CP_COMMIT();
        __nv_bfloat16* sEh = sm_x + (c % 3) * X_SST;
        __nv_bfloat16* sXh = sEh + X_EST;
        #pragma unroll
        for (int ks = 0; ks < 2; ks++) {
            uint32_t ah[2][4], bh[4][2];
            #pragma unroll
            for (int a = 0; a < 2; a++) {
                int npb = wm * 32 + a * 16 + aA_col;
                int off = (ks * 16 + aA_row) * LDE + npb;
                ldsm_x4t(ah[a][0], ah[a][1], ah[a][2], ah[a][3], smem_u32(&sEh[off]));
            }
            #pragma unroll
            for (int p = 0; p < 2; p++) {
                int nb = wn * 32 + p * 16 + aB_col;
                int off = (ks * 16 + aB_row) * LDX + nb;
                uint32_t r0, r1, r2, r3;
                ldsm_x4t(r0, r1, r2, r3, smem_u32(&sXh[off]));
                bh[p * 2][0] = r0; bh[p * 2][1] = r1;
                bh[p * 2 + 1][0] = r2; bh[p * 2 + 1][1] = r3;
            }
            #pragma unroll
            for (int a = 0; a < 2; a++)
                #pragma unroll
                for (int n = 0; n < 4; n++)
                    mma_bf16(acc[a][n], ah[a], bh[n]);
        }
    }
    int r0 = lane >> 2, c0 = (lane & 3) * 2;
    #pragma unroll
    for (int a = 0; a < 2; a++) {
        int np = wm * 32 + a * 16 + r0;
        #pragma unroll
        for (int n = 0; n < 4; n++) {
            int d = d0 + wn * 32 + n * 8 + c0;
            size_t o0 = (((size_t)seg * BB + b) * NP + np) * DD + d;
            size_t o1 = (((size_t)seg * BB + b) * NP + np + 8) * DD + d;
            *reinterpret_cast<__nv_bfloat162*>(&g_xspb[o0]) =
                __halves2bfloat162(__float2bfloat16_rn(acc[a][n][0]),
                                   __float2bfloat16_rn(acc[a][n][1]));
            *reinterpret_cast<__nv_bfloat162*>(&g_xspb[o1]) =
                __halves2bfloat162(__float2bfloat16_rn(acc[a][n][2]),
                                   __float2bfloat16_rn(acc[a][n][3]));
        }
    }
}

// ===========================================================================
// K6 (mma, cp.async W staging): ys[(b,p)][e] = sum_d xs*W + bias.
// K chunks of 32; W staged fp32 via cp.async (2 stages), converted from smem.
// Colsum reduce folded in (reads g_part directly); A from bf16 xspb.
#define LDW 264
#define LDK 40
#define YLDWF 264                         // fp32 stage row stride (floats)
#define Y_FST (32 * YLDWF)                // floats per W stage
#define Y_WT (32 * LDW)                   // bf16 elems per W tile
#define Y_AT (16 * LDK)                   // bf16 elems per A tile
__global__ __launch_bounds__(256) void k_ys_mma(const float* __restrict__ W,
                                                const float* __restrict__ bias) {
    extern __shared__ char sm_raw_y[];
    float* sWf = reinterpret_cast<float*>(sm_raw_y);                 // 2 stages fp32
    __nv_bfloat16* sWh = reinterpret_cast<__nv_bfloat16*>(sm_raw_y + 2 * Y_FST * 4); // 2 tiles
    __nv_bfloat16* sAh = sWh + 2 * Y_WT;                             // 2 tiles
    int t = threadIdx.x, lane = t & 31, wid = t >> 5;
    int nexp = blockIdx.y;
    int e0 = blockIdx.x * 256;
    float acc[4][4];
    #pragma unroll
    for (int n = 0; n < 4; n++)
        #pragma unroll
        for (int q = 0; q < 4; q++) acc[n][q] = 0.f;

    int a_row = lane & 15;
    int a_col = (lane >> 4) * 8;
    int aB_row = (lane & 7) + ((lane >> 3) & 1) * 8;
    int aB_col = (lane >> 4) * 8;

    // folded colsum: per-thread A row state (t<128)
    int arow = t >> 3, aq = t & 7;        // row 0..15, col-group 0..7 (4 elems)
    int abb = arow >> 1, ap = arow & 1;
    float ainv = 0.f;
    if (t < 128) {
        int npi = nexp * 2 + ap;
        float cs = 0.f;
        #pragma unroll
        for (int i = 0; i < 32; i++)
            cs += g_part[(abb * 32 + i) * NP + npi];
        ainv = 1.0f / cs;
    }
    size_t abase = ((size_t)abb * NP + nexp * 2 + ap) * DD + aq * 4;

    // W stage load: 32 k-rows x 256 e = 2048 float4; 8 per thread
    #define Y_LOAD(c, s) do { \
        float* dst = sWf + (s) * Y_FST; \
        _Pragma("unroll") \
        for (int i = 0; i < 8; i++) { \
            int idx = t + i * 256; \
            int row = idx >> 6, q = idx & 63; \
            cp_async16(smem_u32(dst + row * YLDWF + q * 4), \
                       &W[((size_t)nexp * DD + (c) * 32 + row) * DD + e0 + q * 4]); \
        } \
    } while (0)

    Y_LOAD(0, 0);
    CP_COMMIT();
    Y_LOAD(1, 1);
    CP_COMMIT();
    for (int c = 0; c < 32; c++) {
        CP_WAIT1();
        __syncthreads();
        // convert W stage -> bf16 tile (each thread 4x8 floats)
        {
            const float* src = sWf + (c & 1) * Y_FST;
            __nv_bfloat16* dst = sWh + (c & 1) * Y_WT;
            #pragma unroll
            for (int i = 0; i < 4; i++) {
                int idx = t + i * 256;
                int row = idx >> 5, q = idx & 31;    // 32 rows x 32 groups of 8
                const float* sp = src + row * YLDWF + q * 8;
                float4 v0 = *reinterpret_cast<const float4*>(sp);
                float4 v1 = *reinterpret_cast<const float4*>(sp + 4);
                uint32_t hs[8];
                hs[0] = (uint32_t)__bfloat16_as_ushort(__float2bfloat16_rn(v0.x));
                hs[1] = (uint32_t)__bfloat16_as_ushort(__float2bfloat16_rn(v0.y));
                hs[2] = (uint32_t)__bfloat16_as_ushort(__float2bfloat16_rn(v0.z));
                hs[3] = (uint32_t)__bfloat16_as_ushort(__float2bfloat16_rn(v0.w));
                hs[4] = (uint32_t)__bfloat16_as_ushort(__float2bfloat16_rn(v1.x));
                hs[5] = (uint32_t)__bfloat16_as_ushort(__float2bfloat16_rn(v1.y));
                hs[6] = (uint32_t)__bfloat16_as_ushort(__float2bfloat16_rn(v1.z));
                hs[7] = (uint32_t)__bfloat16_as_ushort(__float2bfloat16_rn(v1.w));
                uint4 hi = {hs[0] | (hs[1] << 16), hs[2] | (hs[3] << 16),
                            hs[4] | (hs[5] << 16), hs[6] | (hs[7] << 16)};
                *reinterpret_cast<uint4*>(&dst[row * LDW + q * 8]) = hi;
            }
        }
        // A tile: 16 rows x 32 k, 4-seg bf16 sum * ainv, convert
        if (t < 128) {
            size_t off = abase + c * 32;
            float s0 = 0.f, s1 = 0.f, s2 = 0.f, s3 = 0.f;
            #pragma unroll
            for (int seg = 0; seg < 4; seg++) {
                uint2 pk = *reinterpret_cast<const uint2*>(
                    &g_xspb[(size_t)seg * BB * NP * DD + off]);
                __nv_bfloat162 p0 = *reinterpret_cast<const __nv_bfloat162*>(&pk.x);
                __nv_bfloat162 p1 = *reinterpret_cast<const __nv_bfloat162*>(&pk.y);
                s0 += __bfloat162float(p0.x); s1 += __bfloat162float(p0.y);
                s2 += __bfloat162float(p1.x); s3 += __bfloat162float(p1.y);
            }
            uint32_t h0 = (uint32_t)__bfloat16_as_ushort(__float2bfloat16_rn(s0 * ainv));
            uint32_t h1 = (uint32_t)__bfloat16_as_ushort(__float2bfloat16_rn(s1 * ainv));
            uint32_t h2 = (uint32_t)__bfloat16_as_ushort(__float2bfloat16_rn(s2 * ainv));
            uint32_t h3 = (uint32_t)__bfloat16_as_ushort(__float2bfloat16_rn(s3 * ainv));
            uint2 pk = {h0 | (h1 << 16), h2 | (h3 << 16)};
            *reinterpret_cast<uint2*>(&sAh[(c & 1) * Y_AT + arow * LDK + aq * 4]) = pk;
        }
        __syncthreads();
        if (c + 2 < 32) { Y_LOAD(c + 2, c & 1); }
        CP_COMMIT();
        // mma on tile (c&1)
        __nv_bfloat16* tW = sWh + (c & 1) * Y_WT;
        __nv_bfloat16* tA = sAh + (c & 1) * Y_AT;
        #pragma unroll
        for (int ks = 0; ks < 2; ks++) {
            uint32_t ah[4], bh[4][2];
            {
                int off = a_row * LDK + ks * 16 + a_col;
                ldsm_x4(ah[0], ah[1], ah[2], ah[3], smem_u32(&tA[off]));
            }
            #pragma unroll
            for (int p = 0; p < 2; p++) {
                int nb = wid * 32 + p * 16 + aB_col;
                int off = (ks * 16 + aB_row) * LDW + nb;
                uint32_t r0, r1, r2, r3;
                ldsm_x4t(r0, r1, r2, r3, smem_u32(&tW[off]));
                bh[p * 2][0] = r0; bh[p * 2][1] = r1;
                bh[p * 2 + 1][0] = r2; bh[p * 2 + 1][1] = r3;
            }
            #pragma unroll
            for (int n = 0; n < 4; n++)
                mma_bf16(acc[n], ah, bh[n]);
        }
    }
    int r0 = lane >> 2, c0 = (lane & 3) * 2;
    #pragma unroll
    for (int n = 0; n < 4; n++) {
        int e = e0 + wid * 32 + n * 8 + c0;
        float2 bv = *reinterpret_cast<const float2*>(&bias[nexp * DD + e]);
        #pragma unroll
        for (int h = 0; h < 2; h++) {
            int row = r0 + h * 8;
            int bb = row >> 1, p = row & 1;
            float v0 = acc[n][h * 2 + 0] + bv.x;
            float v1 = acc[n][h * 2 + 1] + bv.y;
            size_t o = ((size_t)bb * NP + nexp * 2 + p) * DD + e;
            *reinterpret_cast<__nv_bfloat162*>(&g_ysh[o]) =
                __halves2bfloat162(__float2bfloat16_rn(v0), __float2bfloat16_rn(v1));
        }
    }
}

// ===========================================================================
// K7 (mma, cp.async 3-stage): y[m][d] = rsinv[m]*sum_np E[m][np]*ys[np][d] + x[m][d]
#define C_ASZ (128 * LDA)
#define C_BSZ (32 * LDE)
#define C_SST (C_ASZ + C_BSZ)
__global__ __launch_bounds__(256) void k_combine_mma(const float* __restrict__ x,
                                                     float* __restrict__ y) {
    extern __shared__ __nv_bfloat16 sm_c[];
    int t = threadIdx.x, lane = t & 31, wid = t >> 5;
    int b = blockIdx.z;
    int tokbase = b * MM + blockIdx.x * 128;
    int d0 = blockIdx.y * 128;
    int wm = wid & 1, wn = wid >> 1;
    float acc[4][4][4];
    #pragma unroll
    for (int a = 0; a < 4; a++)
        #pragma unroll
        for (int n = 0; n < 4; n++)
            #pragma unroll
            for (int q = 0; q < 4; q++) acc[a][n][q] = 0.f;

    int a_row = lane & 15;
    int a_col = (lane >> 4) * 8;
    int aB_row = (lane & 7) + ((lane >> 3) & 1) * 8;
    int aB_col = (lane >> 4) * 8;

    #define C_LOAD(c, s) do { \
        __nv_bfloat16* base = sm_c + (s) * C_SST; \
        _Pragma("unroll") \
        for (int i = 0; i < 2; i++) { \
            int idx = t + i * 256; \
            int row = idx >> 2, q = idx & 3; \
            size_t ge = (size_t)(tokbase + row) * NP + (c) * 32 + q * 8; \
            cp_async16(smem_u32(base + row * LDA + q * 8), &g_Eh[ge]); \
            int rowb = idx >> 4, qb = idx & 15; \
            size_t gy = ((size_t)b * NP + (c) * 32 + rowb) * DD + d0 + qb * 8; \
            cp_async16(smem_u32(base + C_ASZ + rowb * LDE + qb * 8), &g_ysh[gy]); \
        } \
    } while (0)

    C_LOAD(0, 0);
    CP_COMMIT();
    C_LOAD(1, 1);
    CP_COMMIT();
    for (int c = 0; c < 4; c++) {
        CP_WAIT1();
        __syncthreads();
        if (c + 2 < 4) C_LOAD(c + 2, (c + 2) % 3);
        CP_COMMIT();
        __nv_bfloat16* sAh = sm_c + (c % 3) * C_SST;
        __nv_bfloat16* sBh = sAh + C_ASZ;
        #pragma unroll
        for (int ks = 0; ks < 2; ks++) {
            uint32_t ah[4][4], bh[4][2];
            #pragma unroll
            for (int a = 0; a < 4; a++) {
                int off = (wm * 64 + a * 16 + a_row) * LDA + ks * 16 + a_col;
                ldsm_x4(ah[a][0], ah[a][1], ah[a][2], ah[a][3], smem_u32(&sAh[off]));
            }
            #pragma unroll
            for (int p = 0; p < 2; p++) {
                int nb = wn * 32 + p * 16 + aB_col;
                int off = (ks * 16 + aB_row) * LDE + nb;
                uint32_t r0, r1, r2, r3;
                ldsm_x4t(r0, r1, r2, r3, smem_u32(&sBh[off]));
                bh[p * 2][0] = r0; bh[p * 2][1] = r1;
                bh[p * 2 + 1][0] = r2; bh[p * 2 + 1][1] = r3;
            }
            #pragma unroll
            for (int a = 0; a < 4; a++)
                #pragma unroll
                for (int n = 0; n < 4; n++)
                    mma_bf16(acc[a][n], ah[a], bh[n]);
        }
    }
    int r0 = lane >> 2, c0 = (lane & 3) * 2;
    #pragma unroll
    for (int a = 0; a < 4; a++) {
        int m0 = tokbase + wm * 64 + a * 16 + r0;
        float rs0 = g_rsinv[m0];
        float rs1 = g_rsinv[m0 + 8];
        #pragma unroll
        for (int n = 0; n < 4; n++) {
            int d = d0 + wn * 32 + n * 8 + c0;
            size_t i0 = (size_t)m0 * DD + d;
            size_t i1 = (size_t)(m0 + 8) * DD + d;
            float2 xv0 = *reinterpret_cast<const float2*>(&x[i0]);
            float2 xv1 = *reinterpret_cast<const float2*>(&x[i1]);
            *reinterpret_cast<float2*>(&y[i0]) =
                make_float2(acc[a][n][0] * rs0 + xv0.x, acc[a][n][1] * rs0 + xv0.y);
            *reinterpret_cast<float2*>(&y[i1]) =
                make_float2(acc[a][n][2] * rs1 + xv1.x, acc[a][n][3] * rs1 + xv1.y);
        }
    }
}

// ---------------------------------------------------------------------------
extern "C" void kernel_launch(void* const* d_in, const int* in_sizes, int n_in,
                              void* d_out, int out_size) {
    const float* x     = (const float*)d_in[0];  // [8,4096,1024]
    const float* phi   = (const float*)d_in[1];  // [1024,64,2]
    const float* scale = (const float*)d_in[2];  // [1]
    const float* W     = (const float*)d_in[3];  // [64,1024,1024]
    const float* bias  = (const float*)d_in[4];  // [64,1024]
    float* y = (float*)d_out;                    // [8,4096,1024]

    const int smem_logits  = 3 * L_SST * 2;                             // 61440
    const int smem_xs      = 3 * X_SST * 2;                             // 39936
    const int smem_ys      = 2 * Y_FST * 4 + 2 * Y_WT * 2 + 2 * Y_AT * 2; // 104448
    const int smem_combine = 3 * C_SST * 2;                             // 56832
    cudaFuncSetAttribute(k_logits_mma, cudaFuncAttributeMaxDynamicSharedMemorySize, smem_logits);
    cudaFuncSetAttribute(k_xs_mma, cudaFuncAttributeMaxDynamicSharedMemorySize, smem_xs);
    cudaFuncSetAttribute(k_ys_mma, cudaFuncAttributeMaxDynamicSharedMemorySize, smem_ys);
    cudaFuncSetAttribute(k_combine_mma, cudaFuncAttributeMaxDynamicSharedMemorySize, smem_combine);

    k_phinorm<<<NP, 256>>>(phi, scale);
    k_rinv<<<BM / 8, 256>>>(x);
    k_logits_mma<<<BM / 128, 256, smem_logits>>>();
    k_xs_mma<<<dim3(16, BB, 4), 256, smem_xs>>>();
    k_ys_mma<<<dim3(4, NEXP), 256, smem_ys>>>(W, bias);
    k_combine_mma<<<dim3(32, 8, BB), 256, smem_combine>>>(x, y);
}

// round 13
// speedup vs baseline: 1.6199x; 1.0165x over previous
#include <cuda_runtime.h>
#include <cuda_bf16.h>
#include <math.h>
#include <stdint.h>

// Problem constants
#define BB 8
#define MM 4096
#define DD 1024
#define NEXP 64
#define NP 128            // NEXP * PP
#define BM (BB * MM)      // 32768 tokens
#define LOG2E 1.4426950408889634f

static __device__ __constant__ float c_eps = 1e-12f;

// ---- scratch (device globals; no allocation allowed) ----
__device__ __align__(16) __nv_bfloat16 g_phinth[NP * DD];       // phin^T [np][d]
__device__ __align__(16) __nv_bfloat16 g_xh[(size_t)BM * DD];   // x bf16 [tok][d]
__device__ __align__(16) __nv_bfloat16 g_Eh[(size_t)BM * NP];   // E bf16 [tok][np]
__device__ __align__(16) __nv_bfloat16 g_ysh[BB * NP * DD];     // ys bf16 [b*NP+np][d]
__device__ __align__(16) __nv_bfloat16 g_xspb[(size_t)4 * BB * NP * DD]; // bf16 partial slot inputs
__device__ float g_rinv[BM];              // per-token (1/TEMP)/max(||x||,eps)
__device__ float g_part[256 * NP];        // per-mtile column partial sums
__device__ float g_rsinv[BM];             // 1/rowsum (combine denominators)

// ============================ helpers =====================================
__device__ __forceinline__ uint32_t smem_u32(const void* p) {
    uint32_t a;
    asm("{ .reg .u64 t; cvta.to.shared.u64 t, %1; cvt.u32.u64 %0, t; }"
        : "=r"(a) : "l"(p));
    return a;
}
__device__ __forceinline__ void cp_async16(uint32_t saddr, const void* gptr) {
    asm volatile("cp.async.cg.shared.global [%0], [%1], 16;"
                 :: "r"(saddr), "l"(gptr));
}
#define CP_COMMIT() asm volatile("cp.async.commit_group;" ::: "memory")
#define CP_WAIT1()  asm volatile("cp.async.wait_group 1;" ::: "memory")
#define CP_WAIT2()  asm volatile("cp.async.wait_group 2;" ::: "memory")
__device__ __forceinline__ void ldsm_x4(uint32_t& r0, uint32_t& r1, uint32_t& r2,
                                        uint32_t& r3, uint32_t a) {
    asm volatile("ldmatrix.sync.aligned.m8n8.x4.shared.b16 {%0,%1,%2,%3}, [%4];"
                 : "=r"(r0), "=r"(r1), "=r"(r2), "=r"(r3) : "r"(a));
}
__device__ __forceinline__ void ldsm_x4t(uint32_t& r0, uint32_t& r1, uint32_t& r2,
                                         uint32_t& r3, uint32_t a) {
    asm volatile("ldmatrix.sync.aligned.m8n8.x4.trans.shared.b16 {%0,%1,%2,%3}, [%4];"
                 : "=r"(r0), "=r"(r1), "=r"(r2), "=r"(r3) : "r"(a));
}
__device__ __forceinline__ void mma_bf16(float* d, const uint32_t* a, const uint32_t* b) {
    asm volatile(
        "mma.sync.aligned.m16n8k16.row.col.f32.bf16.bf16.f32 "
        "{%0,%1,%2,%3}, {%4,%5,%6,%7}, {%8,%9}, {%0,%1,%2,%3};"
        : "+f"(d[0]), "+f"(d[1]), "+f"(d[2]), "+f"(d[3])
        : "r"(a[0]), "r"(a[1]), "r"(a[2]), "r"(a[3]), "r"(b[0]), "r"(b[1]));
}
__device__ __forceinline__ float ex2f(float x) {
    float r;
    asm("ex2.approx.f32 %0, %1;" : "=f"(r) : "f"(x));
    return r;
}
__device__ __forceinline__ float warpReduceSum(float v) {
    v += __shfl_down_sync(0xffffffffu, v, 16);
    v += __shfl_down_sync(0xffffffffu, v, 8);
    v += __shfl_down_sync(0xffffffffu, v, 4);
    v += __shfl_down_sync(0xffffffffu, v, 2);
    v += __shfl_down_sync(0xffffffffu, v, 1);
    return v;
}

// ===========================================================================
// K1: phin^T bf16
__global__ void k_phinorm(const float* __restrict__ phi, const float* __restrict__ scale) {
    int np = blockIdx.x;
    int t = threadIdx.x;
    float s = 0.f;
    for (int d = t; d < DD; d += 256) {
        float v = phi[d * NP + np];
        s += v * v;
    }
    __shared__ float red[8];
    s = warpReduceSum(s);
    if ((t & 31) == 0) red[t >> 5] = s;
    __syncthreads();
    if (t < 32) {
        float v = (t < 8) ? red[t] : 0.f;
        v = warpReduceSum(v);
        if (t == 0) red[0] = scale[0] / fmaxf(sqrtf(v), c_eps);
    }
    __syncthreads();
    float rn = red[0];
    for (int d = t; d < DD; d += 256)
        g_phinth[np * DD + d] = __float2bfloat16_rn(phi[d * NP + np] * rn);
}

// K2: row norms + x -> bf16. Warp per token.
__global__ void k_rinv(const float* __restrict__ x) {
    int w = threadIdx.x >> 5;
    int lane = threadIdx.x & 31;
    int tok = blockIdx.x * 8 + w;
    const float4* xr = reinterpret_cast<const float4*>(x + (size_t)tok * DD);
    float s = 0.f;
    #pragma unroll
    for (int i = 0; i < 8; i++) {
        float4 v = xr[lane + i * 32];
        s += v.x * v.x + v.y * v.y + v.z * v.z + v.w * v.w;
        __nv_bfloat162 p0 = __halves2bfloat162(__float2bfloat16_rn(v.x), __float2bfloat16_rn(v.y));
        __nv_bfloat162 p1 = __halves2bfloat162(__float2bfloat16_rn(v.z), __float2bfloat16_rn(v.w));
        size_t off = (size_t)tok * DD + (lane + i * 32) * 4;
        *reinterpret_cast<__nv_bfloat162*>(&g_xh[off])     = p0;
        *reinterpret_cast<__nv_bfloat162*>(&g_xh[off + 2]) = p1;
    }
    s = warpReduceSum(s);
    if (lane == 0) g_rinv[tok] = 10.0f / fmaxf(sqrtf(s), c_eps);  // 1/TEMP
}

// ===========================================================================
// K3 (mma, cp.async 4-stage deep pipeline): E = exp2((x.phin)*rinv*log2e).
// CTA 128m x 128n, K chunks of 32. Fused rowsum + column partials.
#define LDA 40
#define L_AST (128 * LDA)
#define L_SST (2 * L_AST)
__global__ __launch_bounds__(256) void k_logits_mma() {
    extern __shared__ __nv_bfloat16 sm_l[];
    int t = threadIdx.x, lane = t & 31, wid = t >> 5;
    int tok0 = blockIdx.x * 128;
    int wm = wid & 1, wn = wid >> 1;
    float acc[4][4][4];
    #pragma unroll
    for (int a = 0; a < 4; a++)
        #pragma unroll
        for (int n = 0; n < 4; n++)
            #pragma unroll
            for (int q = 0; q < 4; q++) acc[a][n][q] = 0.f;

    int a_row = lane & 15;
    int a_col = (lane >> 4) * 8;
    int b_row = (lane & 7) + ((lane >> 4) << 3);
    int b_col = ((lane >> 3) & 1) * 8;

    #define L_LOAD(c, s) do { \
        __nv_bfloat16* base = sm_l + (s) * L_SST; \
        _Pragma("unroll") \
        for (int i = 0; i < 2; i++) { \
            int idx = t + i * 256; \
            int row = idx >> 2, q = idx & 3; \
            size_t ga = (size_t)(tok0 + row) * DD + (c) * 32 + q * 8; \
            size_t gb = (size_t)row * DD + (c) * 32 + q * 8; \
            int so = row * LDA + q * 8; \
            cp_async16(smem_u32(base + so), &g_xh[ga]); \
            cp_async16(smem_u32(base + L_AST + so), &g_phinth[gb]); \
        } \
    } while (0)

    L_LOAD(0, 0); CP_COMMIT();
    L_LOAD(1, 1); CP_COMMIT();
    L_LOAD(2, 2); CP_COMMIT();
    for (int c = 0; c < 32; c++) {
        CP_WAIT2();
        __syncthreads();
        if (c + 3 < 32) L_LOAD(c + 3, (c + 3) & 3);
        CP_COMMIT();
        __nv_bfloat16* sAh = sm_l + (c & 3) * L_SST;
        __nv_bfloat16* sBh = sAh + L_AST;
        #pragma unroll
        for (int ks = 0; ks < 2; ks++) {
            uint32_t ah[4][4], bh[4][2];
            #pragma unroll
            for (int a = 0; a < 4; a++) {
                int off = (wm * 64 + a * 16 + a_row) * LDA + ks * 16 + a_col;
                ldsm_x4(ah[a][0], ah[a][1], ah[a][2], ah[a][3], smem_u32(&sAh[off]));
            }
            #pragma unroll
            for (int p = 0; p < 2; p++) {
                int off = (wn * 32 + p * 16 + b_row) * LDA + ks * 16 + b_col;
                uint32_t r0, r1, r2, r3;
                ldsm_x4(r0, r1, r2, r3, smem_u32(&sBh[off]));
                bh[p * 2][0] = r0; bh[p * 2][1] = r1;
                bh[p * 2 + 1][0] = r2; bh[p * 2 + 1][1] = r3;
            }
            #pragma unroll
            for (int a = 0; a < 4; a++)
                #pragma unroll
                for (int n = 0; n < 4; n++)
                    mma_bf16(acc[a][n], ah[a], bh[n]);
        }
    }
    // epilogue: exp2, store bf16; accumulate row/col sums (fp32, pre-rounding)
    int r0 = lane >> 2, c0 = (lane & 3) * 2;
    float rsum[4][2];
    float csum[4][2];
    #pragma unroll
    for (int a = 0; a < 4; a++) { rsum[a][0] = 0.f; rsum[a][1] = 0.f; }
    #pragma unroll
    for (int n = 0; n < 4; n++) { csum[n][0] = 0.f; csum[n][1] = 0.f; }
    __syncthreads();
    #pragma unroll
    for (int a = 0; a < 4; a++) {
        int row = tok0 + wm * 64 + a * 16 + r0;
        float rv0 = g_rinv[row] * LOG2E;
        float rv1 = g_rinv[row + 8] * LOG2E;
        #pragma unroll
        for (int n = 0; n < 4; n++) {
            int col = wn * 32 + n * 8 + c0;
            float e0 = ex2f(acc[a][n][0] * rv0), e1 = ex2f(acc[a][n][1] * rv0);
            float e2 = ex2f(acc[a][n][2] * rv1), e3 = ex2f(acc[a][n][3] * rv1);
            rsum[a][0] += e0 + e1;
            rsum[a][1] += e2 + e3;
            csum[n][0] += e0 + e2;
            csum[n][1] += e1 + e3;
            *reinterpret_cast<__nv_bfloat162*>(&g_Eh[(size_t)row * NP + col]) =
                __halves2bfloat162(__float2bfloat16_rn(e0), __float2bfloat16_rn(e1));
            *reinterpret_cast<__nv_bfloat162*>(&g_Eh[(size_t)(row + 8) * NP + col]) =
                __halves2bfloat162(__float2bfloat16_rn(e2), __float2bfloat16_rn(e3));
        }
    }
    float* srow = reinterpret_cast<float*>(sm_l);   // [4 wn][128 rows]
    float* scol = srow + 4 * 128;                   // [2 wm][128 cols]
    __syncthreads();
    #pragma unroll
    for (int a = 0; a < 4; a++)
        #pragma unroll
        for (int h = 0; h < 2; h++) {
            float v = rsum[a][h];
            v += __shfl_xor_sync(0xffffffffu, v, 1);
            v += __shfl_xor_sync(0xffffffffu, v, 2);
            if ((lane & 3) == 0)
                srow[wn * 128 + wm * 64 + a * 16 + h * 8 + r0] = v;
        }
    #pragma unroll
    for (int n = 0; n < 4; n++)
        #pragma unroll
        for (int q1 = 0; q1 < 2; q1++) {
            float v = csum[n][q1];
            v += __shfl_xor_sync(0xffffffffu, v, 4);
            v += __shfl_xor_sync(0xffffffffu, v, 8);
            v += __shfl_xor_sync(0xffffffffu, v, 16);
            if (lane < 4)
                scol[wm * 128 + wn * 32 + n * 8 + lane * 2 + q1] = v;
        }
    __syncthreads();
    if (t < 128) {
        float rs = srow[t] + srow[128 + t] + srow[256 + t] + srow[384 + t];
        g_rsinv[tok0 + t] = 1.0f / rs;
        g_part[blockIdx.x * NP + t] = scol[t] + scol[128 + t];
    }
}

// ===========================================================================
// K5 (mma, cp.async 4-stage deep pipeline):
// xspb[seg][b][np][d] = sum_{m in seg} E[m][np]*x[m][d].  CTA 128np x 128d.
#define LDE 136
#define X_AST (32 * LDE)
#define X_SST (2 * X_AST)
__global__ __launch_bounds__(256) void k_xs_mma() {
    extern __shared__ __nv_bfloat16 sm_x[];
    int t = threadIdx.x, lane = t & 31, wid = t >> 5;
    int d0 = blockIdx.x * 128;
    int b = blockIdx.y;
    int seg = blockIdx.z;
    int base = b * MM + seg * 1024;
    int wm = wid & 1, wn = wid >> 1;
    float acc[4][4][4];
    #pragma unroll
    for (int a = 0; a < 4; a++)
        #pragma unroll
        for (int n = 0; n < 4; n++)
            #pragma unroll
            for (int q = 0; q < 4; q++) acc[a][n][q] = 0.f;

    int aA_col = ((lane >> 3) & 1) * 8;
    int aA_row = (lane & 7) + (lane >> 4) * 8;
    int aB_row = (lane & 7) + ((lane >> 3) & 1) * 8;
    int aB_col = (lane >> 4) * 8;

    #define X_LOAD(c, s) do { \
        __nv_bfloat16* bb_ = sm_x + (s) * X_SST; \
        _Pragma("unroll") \
        for (int i = 0; i < 2; i++) { \
            int idx = t + i * 256; \
            int row = idx >> 4, q = idx & 15; \
            size_t ge = (size_t)(base + (c) * 32 + row) * NP + q * 8; \
            size_t gx = (size_t)(base + (c) * 32 + row) * DD + d0 + q * 8; \
            int so = row * LDE + q * 8; \
            cp_async16(smem_u32(bb_ + so), &g_Eh[ge]); \
            cp_async16(smem_u32(bb_ + X_AST + so), &g_xh[gx]); \
        } \
    } while (0)

    X_LOAD(0, 0); CP_COMMIT();
    X_LOAD(1, 1); CP_COMMIT();
    X_LOAD(2, 2); CP_COMMIT();
    for (int c = 0; c < 32; c++) {
        CP_WAIT2();
        __syncthreads();
        if (c + 3 < 32) X_LOAD(c + 3, (c + 3) & 3);
        CP_COMMIT();
        __nv_bfloat16* sEh = sm_x + (c & 3) * X_SST;
        __nv_bfloat16* sXh = sEh + X_AST;
        #pragma unroll
        for (int ks = 0; ks < 2; ks++) {
            uint32_t ah[4][4], bh[4][2];
            #pragma unroll
            for (int a = 0; a < 4; a++) {
                int npb = wm * 64 + a * 16 + aA_col;
                int off = (ks * 16 + aA_row) * LDE + npb;
                ldsm_x4t(ah[a][0], ah[a][1], ah[a][2], ah[a][3], smem_u32(&sEh[off]));
            }
            #pragma unroll
            for (int p = 0; p < 2; p++) {
                int nb = wn * 32 + p * 16 + aB_col;
                int off = (ks * 16 + aB_row) * LDE + nb;
                uint32_t r0, r1, r2, r3;
                ldsm_x4t(r0, r1, r2, r3, smem_u32(&sXh[off]));
                bh[p * 2][0] = r0; bh[p * 2][1] = r1;
                bh[p * 2 + 1][0] = r2; bh[p * 2 + 1][1] = r3;
            }
            #pragma unroll
            for (int a = 0; a < 4; a++)
                #pragma unroll
                for (int n = 0; n < 4; n++)
                    mma_bf16(acc[a][n], ah[a], bh[n]);
        }
    }
    int r0 = lane >> 2, c0 = (lane & 3) * 2;
    #pragma unroll
    for (int a = 0; a < 4; a++) {
        int np = wm * 64 + a * 16 + r0;
        #pragma unroll
        for (int n = 0; n < 4; n++) {
            int d = d0 + wn * 32 + n * 8 + c0;
            size_t o0 = (((size_t)seg * BB + b) * NP + np) * DD + d;
            size_t o1 = (((size_t)seg * BB + b) * NP + np + 8) * DD + d;
            *reinterpret_cast<__nv_bfloat162*>(&g_xspb[o0]) =
                __halves2bfloat162(__float2bfloat16_rn(acc[a][n][0]),
                                   __float2bfloat16_rn(acc[a][n][1]));
            *reinterpret_cast<__nv_bfloat162*>(&g_xspb[o1]) =
                __halves2bfloat162(__float2bfloat16_rn(acc[a][n][2]),
                                   __float2bfloat16_rn(acc[a][n][3]));
        }
    }
}

// ===========================================================================
// K6 (mma, cp.async W staging): ys[(b,p)][e] = sum_d xs*W + bias.
// K chunks of 32; W staged fp32 via cp.async (2 stages), converted from smem.
// Colsum reduce folded in (reads g_part directly); A from bf16 xspb.
#define LDW 264
#define LDK 40
#define YLDWF 264                         // fp32 stage row stride (floats)
#define Y_FST (32 * YLDWF)                // floats per W stage
#define Y_WT (32 * LDW)                   // bf16 elems per W tile
#define Y_AT (16 * LDK)                   // bf16 elems per A tile
__global__ __launch_bounds__(256) void k_ys_mma(const float* __restrict__ W,
                                                const float* __restrict__ bias) {
    extern __shared__ char sm_raw_y[];
    float* sWf = reinterpret_cast<float*>(sm_raw_y);                 // 2 stages fp32
    __nv_bfloat16* sWh = reinterpret_cast<__nv_bfloat16*>(sm_raw_y + 2 * Y_FST * 4); // 2 tiles
    __nv_bfloat16* sAh = sWh + 2 * Y_WT;                             // 2 tiles
    int t = threadIdx.x, lane = t & 31, wid = t >> 5;
    int nexp = blockIdx.y;
    int e0 = blockIdx.x * 256;
    float acc[4][4];
    #pragma unroll
    for (int n = 0; n < 4; n++)
        #pragma unroll
        for (int q = 0; q < 4; q++) acc[n][q] = 0.f;

    int a_row = lane & 15;
    int a_col = (lane >> 4) * 8;
    int aB_row = (lane & 7) + ((lane >> 3) & 1) * 8;
    int aB_col = (lane >> 4) * 8;

    // folded colsum: per-thread A row state (t<128)
    int arow = t >> 3, aq = t & 7;        // row 0..15, col-group 0..7 (4 elems)
    int abb = arow >> 1, ap = arow & 1;
    float ainv = 0.f;
    if (t < 128) {
        int npi = nexp * 2 + ap;
        float cs = 0.f;
        #pragma unroll
        for (int i = 0; i < 32; i++)
            cs += g_part[(abb * 32 + i) * NP + npi];
        ainv = 1.0f / cs;
    }
    size_t abase = ((size_t)abb * NP + nexp * 2 + ap) * DD + aq * 4;

    // W stage load: 32 k-rows x 256 e = 2048 float4; 8 per thread
    #define Y_LOAD(c, s) do { \
        float* dst = sWf + (s) * Y_FST; \
        _Pragma("unroll") \
        for (int i = 0; i < 8; i++) { \
            int idx = t + i * 256; \
            int row = idx >> 6, q = idx & 63; \
            cp_async16(smem_u32(dst + row * YLDWF + q * 4), \
                       &W[((size_t)nexp * DD + (c) * 32 + row) * DD + e0 + q * 4]); \
        } \
    } while (0)

    Y_LOAD(0, 0);
    CP_COMMIT();
    Y_LOAD(1, 1);
    CP_COMMIT();
    for (int c = 0; c < 32; c++) {
        CP_WAIT1();
        __syncthreads();
        // convert W stage -> bf16 tile (each thread 4x8 floats)
        {
            const float* src = sWf + (c & 1) * Y_FST;
            __nv_bfloat16* dst = sWh + (c & 1) * Y_WT;
            #pragma unroll
            for (int i = 0; i < 4; i++) {
                int idx = t + i * 256;
                int row = idx >> 5, q = idx & 31;    // 32 rows x 32 groups of 8
                const float* sp = src + row * YLDWF + q * 8;
                float4 v0 = *reinterpret_cast<const float4*>(sp);
                float4 v1 = *reinterpret_cast<const float4*>(sp + 4);
                uint32_t hs[8];
                hs[0] = (uint32_t)__bfloat16_as_ushort(__float2bfloat16_rn(v0.x));
                hs[1] = (uint32_t)__bfloat16_as_ushort(__float2bfloat16_rn(v0.y));
                hs[2] = (uint32_t)__bfloat16_as_ushort(__float2bfloat16_rn(v0.z));
                hs[3] = (uint32_t)__bfloat16_as_ushort(__float2bfloat16_rn(v0.w));
                hs[4] = (uint32_t)__bfloat16_as_ushort(__float2bfloat16_rn(v1.x));
                hs[5] = (uint32_t)__bfloat16_as_ushort(__float2bfloat16_rn(v1.y));
                hs[6] = (uint32_t)__bfloat16_as_ushort(__float2bfloat16_rn(v1.z));
                hs[7] = (uint32_t)__bfloat16_as_ushort(__float2bfloat16_rn(v1.w));
                uint4 hi = {hs[0] | (hs[1] << 16), hs[2] | (hs[3] << 16),
                            hs[4] | (hs[5] << 16), hs[6] | (hs[7] << 16)};
                *reinterpret_cast<uint4*>(&dst[row * LDW + q * 8]) = hi;
            }
        }
        // A tile: 16 rows x 32 k, 4-seg bf16 sum * ainv, convert
        if (t < 128) {
            size_t off = abase + c * 32;
            float s0 = 0.f, s1 = 0.f, s2 = 0.f, s3 = 0.f;
            #pragma unroll
            for (int seg = 0; seg < 4; seg++) {
                uint2 pk = *reinterpret_cast<const uint2*>(
                    &g_xspb[(size_t)seg * BB * NP * DD + off]);
                __nv_bfloat162 p0 = *reinterpret_cast<const __nv_bfloat162*>(&pk.x);
                __nv_bfloat162 p1 = *reinterpret_cast<const __nv_bfloat162*>(&pk.y);
                s0 += __bfloat162float(p0.x); s1 += __bfloat162float(p0.y);
                s2 += __bfloat162float(p1.x); s3 += __bfloat162float(p1.y);
            }
            uint32_t h0 = (uint32_t)__bfloat16_as_ushort(__float2bfloat16_rn(s0 * ainv));
            uint32_t h1 = (uint32_t)__bfloat16_as_ushort(__float2bfloat16_rn(s1 * ainv));
            uint32_t h2 = (uint32_t)__bfloat16_as_ushort(__float2bfloat16_rn(s2 * ainv));
            uint32_t h3 = (uint32_t)__bfloat16_as_ushort(__float2bfloat16_rn(s3 * ainv));
            uint2 pk = {h0 | (h1 << 16), h2 | (h3 << 16)};
            *reinterpret_cast<uint2*>(&sAh[(c & 1) * Y_AT + arow * LDK + aq * 4]) = pk;
        }
        __syncthreads();
        if (c + 2 < 32) { Y_LOAD(c + 2, c & 1); }
        CP_COMMIT();
        // mma on tile (c&1)
        __nv_bfloat16* tW = sWh + (c & 1) * Y_WT;
        __nv_bfloat16* tA = sAh + (c & 1) * Y_AT;
        #pragma unroll
        for (int ks = 0; ks < 2; ks++) {
            uint32_t ah[4], bh[4][2];
            {
                int off = a_row * LDK + ks * 16 + a_col;
                ldsm_x4(ah[0], ah[1], ah[2], ah[3], smem_u32(&tA[off]));
            }
            #pragma unroll
            for (int p = 0; p < 2; p++) {
                int nb = wid * 32 + p * 16 + aB_col;
                int off = (ks * 16 + aB_row) * LDW + nb;
                uint32_t r0, r1, r2, r3;
                ldsm_x4t(r0, r1, r2, r3, smem_u32(&tW[off]));
                bh[p * 2][0] = r0; bh[p * 2][1] = r1;
                bh[p * 2 + 1][0] = r2; bh[p * 2 + 1][1] = r3;
            }
            #pragma unroll
            for (int n = 0; n < 4; n++)
                mma_bf16(acc[n], ah, bh[n]);
        }
    }
    int r0 = lane >> 2, c0 = (lane & 3) * 2;
    #pragma unroll
    for (int n = 0; n < 4; n++) {
        int e = e0 + wid * 32 + n * 8 + c0;
        float2 bv = *reinterpret_cast<const float2*>(&bias[nexp * DD + e]);
        #pragma unroll
        for (int h = 0; h < 2; h++) {
            int row = r0 + h * 8;
            int bb = row >> 1, p = row & 1;
            float v0 = acc[n][h * 2 + 0] + bv.x;
            float v1 = acc[n][h * 2 + 1] + bv.y;
            size_t o = ((size_t)bb * NP + nexp * 2 + p) * DD + e;
            *reinterpret_cast<__nv_bfloat162*>(&g_ysh[o]) =
                __halves2bfloat162(__float2bfloat16_rn(v0), __float2bfloat16_rn(v1));
        }
    }
}

// ===========================================================================
// K7 (mma, cp.async 3-stage): y[m][d] = rsinv[m]*sum_np E[m][np]*ys[np][d] + x[m][d]
#define C_ASZ (128 * LDA)
#define C_BSZ (32 * LDE)
#define C_SST (C_ASZ + C_BSZ)
__global__ __launch_bounds__(256) void k_combine_mma(const float* __restrict__ x,
                                                     float* __restrict__ y) {
    extern __shared__ __nv_bfloat16 sm_c[];
    int t = threadIdx.x, lane = t & 31, wid = t >> 5;
    int b = blockIdx.z;
    int tokbase = b * MM + blockIdx.x * 128;
    int d0 = blockIdx.y * 128;
    int wm = wid & 1, wn = wid >> 1;
    float acc[4][4][4];
    #pragma unroll
    for (int a = 0; a < 4; a++)
        #pragma unroll
        for (int n = 0; n < 4; n++)
            #pragma unroll
            for (int q = 0; q < 4; q++) acc[a][n][q] = 0.f;

    int a_row = lane & 15;
    int a_col = (lane >> 4) * 8;
    int aB_row = (lane & 7) + ((lane >> 3) & 1) * 8;
    int aB_col = (lane >> 4) * 8;

    #define C_LOAD(c, s) do { \
        __nv_bfloat16* base = sm_c + (s) * C_SST; \
        _Pragma("unroll") \
        for (int i = 0; i < 2; i++) { \
            int idx = t + i * 256; \
            int row = idx >> 2, q = idx & 3; \
            size_t ge = (size_t)(tokbase + row) * NP + (c) * 32 + q * 8; \
            cp_async16(smem_u32(base + row * LDA + q * 8), &g_Eh[ge]); \
            int rowb = idx >> 4, qb = idx & 15; \
            size_t gy = ((size_t)b * NP + (c) * 32 + rowb) * DD + d0 + qb * 8; \
            cp_async16(smem_u32(base + C_ASZ + rowb * LDE + qb * 8), &g_ysh[gy]); \
        } \
    } while (0)

    C_LOAD(0, 0);
    CP_COMMIT();
    C_LOAD(1, 1);
    CP_COMMIT();
    for (int c = 0; c < 4; c++) {
        CP_WAIT1();
        __syncthreads();
        if (c + 2 < 4) C_LOAD(c + 2, (c + 2) % 3);
        CP_COMMIT();
        __nv_bfloat16* sAh = sm_c + (c % 3) * C_SST;
        __nv_bfloat16* sBh = sAh + C_ASZ;
        #pragma unroll
        for (int ks = 0; ks < 2; ks++) {
            uint32_t ah[4][4], bh[4][2];
            #pragma unroll
            for (int a = 0; a < 4; a++) {
                int off = (wm * 64 + a * 16 + a_row) * LDA + ks * 16 + a_col;
                ldsm_x4(ah[a][0], ah[a][1], ah[a][2], ah[a][3], smem_u32(&sAh[off]));
            }
            #pragma unroll
            for (int p = 0; p < 2; p++) {
                int nb = wn * 32 + p * 16 + aB_col;
                int off = (ks * 16 + aB_row) * LDE + nb;
                uint32_t r0, r1, r2, r3;
                ldsm_x4t(r0, r1, r2, r3, smem_u32(&sBh[off]));
                bh[p * 2][0] = r0; bh[p * 2][1] = r1;
                bh[p * 2 + 1][0] = r2; bh[p * 2 + 1][1] = r3;
            }
            #pragma unroll
            for (int a = 0; a < 4; a++)
                #pragma unroll
                for (int n = 0; n < 4; n++)
                    mma_bf16(acc[a][n], ah[a], bh[n]);
        }
    }
    int r0 = lane >> 2, c0 = (lane & 3) * 2;
    #pragma unroll
    for (int a = 0; a < 4; a++) {
        int m0 = tokbase + wm * 64 + a * 16 + r0;
        float rs0 = g_rsinv[m0];
        float rs1 = g_rsinv[m0 + 8];
        #pragma unroll
        for (int n = 0; n < 4; n++) {
            int d = d0 + wn * 32 + n * 8 + c0;
            size_t i0 = (size_t)m0 * DD + d;
            size_t i1 = (size_t)(m0 + 8) * DD + d;
            float2 xv0 = *reinterpret_cast<const float2*>(&x[i0]);
            float2 xv1 = *reinterpret_cast<const float2*>(&x[i1]);
            *reinterpret_cast<float2*>(&y[i0]) =
                make_float2(acc[a][n][0] * rs0 + xv0.x, acc[a][n][1] * rs0 + xv0.y);
            *reinterpret_cast<float2*>(&y[i1]) =
                make_float2(acc[a][n][2] * rs1 + xv1.x, acc[a][n][3] * rs1 + xv1.y);
        }
    }
}

// ---------------------------------------------------------------------------
extern "C" void kernel_launch(void* const* d_in, const int* in_sizes, int n_in,
                              void* d_out, int out_size) {
    const float* x     = (const float*)d_in[0];  // [8,4096,1024]
    const float* phi   = (const float*)d_in[1];  // [1024,64,2]
    const float* scale = (const float*)d_in[2];  // [1]
    const float* W     = (const float*)d_in[3];  // [64,1024,1024]
    const float* bias  = (const float*)d_in[4];  // [64,1024]
    float* y = (float*)d_out;                    // [8,4096,1024]

    const int smem_logits  = 4 * L_SST * 2;                             // 81920
    const int smem_xs      = 4 * X_SST * 2;                             // 69632
    const int smem_ys      = 2 * Y_FST * 4 + 2 * Y_WT * 2 + 2 * Y_AT * 2; // 104448
    const int smem_combine = 3 * C_SST * 2;                             // 56832
    cudaFuncSetAttribute(k_logits_mma, cudaFuncAttributeMaxDynamicSharedMemorySize, smem_logits);
    cudaFuncSetAttribute(k_xs_mma, cudaFuncAttributeMaxDynamicSharedMemorySize, smem_xs);
    cudaFuncSetAttribute(k_ys_mma, cudaFuncAttributeMaxDynamicSharedMemorySize, smem_ys);
    cudaFuncSetAttribute(k_combine_mma, cudaFuncAttributeMaxDynamicSharedMemorySize, smem_combine);

    k_phinorm<<<NP, 256>>>(phi, scale);
    k_rinv<<<BM / 8, 256>>>(x);
    k_logits_mma<<<BM / 128, 256, smem_logits>>>();
    k_xs_mma<<<dim3(8, BB, 4), 256, smem_xs>>>();
    k_ys_mma<<<dim3(4, NEXP), 256, smem_ys>>>(W, bias);
    k_combine_mma<<<dim3(32, 8, BB), 256, smem_combine>>>(x, y);
}

// round 14
// speedup vs baseline: 1.6615x; 1.0257x over previous
#include <cuda_runtime.h>
#include <cuda_bf16.h>
#include <math.h>
#include <stdint.h>

// Problem constants
#define BB 8
#define MM 4096
#define DD 1024
#define NEXP 64
#define NP 128            // NEXP * PP
#define BM (BB * MM)      // 32768 tokens
#define LOG2E 1.4426950408889634f

static __device__ __constant__ float c_eps = 1e-12f;

// ---- scratch (device globals; no allocation allowed) ----
__device__ __align__(16) __nv_bfloat16 g_phinth[NP * DD];       // phin^T [np][d]
__device__ __align__(16) __nv_bfloat16 g_xh[(size_t)BM * DD];   // x bf16 [tok][d]
__device__ __align__(16) __nv_bfloat16 g_Eh[(size_t)BM * NP];   // E bf16 [tok][np]
__device__ __align__(16) __nv_bfloat16 g_ysh[BB * NP * DD];     // ys bf16 [b*NP+np][d]
__device__ __align__(16) __nv_bfloat16 g_xspb[(size_t)4 * BB * NP * DD]; // bf16 partial slot inputs
__device__ float g_rinv[BM];              // per-token (1/TEMP)/max(||x||,eps)
__device__ float g_part[256 * NP];        // per-mtile column partial sums
__device__ float g_rsinv[BM];             // 1/rowsum (combine denominators)

// ============================ helpers =====================================
__device__ __forceinline__ uint32_t smem_u32(const void* p) {
    uint32_t a;
    asm("{ .reg .u64 t; cvta.to.shared.u64 t, %1; cvt.u32.u64 %0, t; }"
        : "=r"(a) : "l"(p));
    return a;
}
__device__ __forceinline__ void cp_async16(uint32_t saddr, const void* gptr) {
    asm volatile("cp.async.cg.shared.global [%0], [%1], 16;"
                 :: "r"(saddr), "l"(gptr));
}
#define CP_COMMIT() asm volatile("cp.async.commit_group;" ::: "memory")
#define CP_WAIT1()  asm volatile("cp.async.wait_group 1;" ::: "memory")
__device__ __forceinline__ void ldsm_x4(uint32_t& r0, uint32_t& r1, uint32_t& r2,
                                        uint32_t& r3, uint32_t a) {
    asm volatile("ldmatrix.sync.aligned.m8n8.x4.shared.b16 {%0,%1,%2,%3}, [%4];"
                 : "=r"(r0), "=r"(r1), "=r"(r2), "=r"(r3) : "r"(a));
}
__device__ __forceinline__ void ldsm_x4t(uint32_t& r0, uint32_t& r1, uint32_t& r2,
                                         uint32_t& r3, uint32_t a) {
    asm volatile("ldmatrix.sync.aligned.m8n8.x4.trans.shared.b16 {%0,%1,%2,%3}, [%4];"
                 : "=r"(r0), "=r"(r1), "=r"(r2), "=r"(r3) : "r"(a));
}
__device__ __forceinline__ void mma_bf16(float* d, const uint32_t* a, const uint32_t* b) {
    asm volatile(
        "mma.sync.aligned.m16n8k16.row.col.f32.bf16.bf16.f32 "
        "{%0,%1,%2,%3}, {%4,%5,%6,%7}, {%8,%9}, {%0,%1,%2,%3};"
        : "+f"(d[0]), "+f"(d[1]), "+f"(d[2]), "+f"(d[3])
        : "r"(a[0]), "r"(a[1]), "r"(a[2]), "r"(a[3]), "r"(b[0]), "r"(b[1]));
}
__device__ __forceinline__ float ex2f(float x) {
    float r;
    asm("ex2.approx.f32 %0, %1;" : "=f"(r) : "f"(x));
    return r;
}
__device__ __forceinline__ float warpReduceSum(float v) {
    v += __shfl_down_sync(0xffffffffu, v, 16);
    v += __shfl_down_sync(0xffffffffu, v, 8);
    v += __shfl_down_sync(0xffffffffu, v, 4);
    v += __shfl_down_sync(0xffffffffu, v, 2);
    v += __shfl_down_sync(0xffffffffu, v, 1);
    return v;
}

// ===========================================================================
// K1: phin^T bf16
__global__ void k_phinorm(const float* __restrict__ phi, const float* __restrict__ scale) {
    int np = blockIdx.x;
    int t = threadIdx.x;
    float s = 0.f;
    for (int d = t; d < DD; d += 256) {
        float v = phi[d * NP + np];
        s += v * v;
    }
    __shared__ float red[8];
    s = warpReduceSum(s);
    if ((t & 31) == 0) red[t >> 5] = s;
    __syncthreads();
    if (t < 32) {
        float v = (t < 8) ? red[t] : 0.f;
        v = warpReduceSum(v);
        if (t == 0) red[0] = scale[0] / fmaxf(sqrtf(v), c_eps);
    }
    __syncthreads();
    float rn = red[0];
    for (int d = t; d < DD; d += 256)
        g_phinth[np * DD + d] = __float2bfloat16_rn(phi[d * NP + np] * rn);
}

// K2: row norms + x -> bf16. Warp per token.
__global__ void k_rinv(const float* __restrict__ x) {
    int w = threadIdx.x >> 5;
    int lane = threadIdx.x & 31;
    int tok = blockIdx.x * 8 + w;
    const float4* xr = reinterpret_cast<const float4*>(x + (size_t)tok * DD);
    float s = 0.f;
    #pragma unroll
    for (int i = 0; i < 8; i++) {
        float4 v = xr[lane + i * 32];
        s += v.x * v.x + v.y * v.y + v.z * v.z + v.w * v.w;
        __nv_bfloat162 p0 = __halves2bfloat162(__float2bfloat16_rn(v.x), __float2bfloat16_rn(v.y));
        __nv_bfloat162 p1 = __halves2bfloat162(__float2bfloat16_rn(v.z), __float2bfloat16_rn(v.w));
        size_t off = (size_t)tok * DD + (lane + i * 32) * 4;
        *reinterpret_cast<__nv_bfloat162*>(&g_xh[off])     = p0;
        *reinterpret_cast<__nv_bfloat162*>(&g_xh[off + 2]) = p1;
    }
    s = warpReduceSum(s);
    if (lane == 0) g_rinv[tok] = 10.0f / fmaxf(sqrtf(s), c_eps);  // 1/TEMP
}

// ===========================================================================
// K3 (mma, cp.async 3-stage, k-chunk=64): E = exp2((x.phin)*rinv*log2e).
// CTA 128m x 128n, 16 chunks of 64. Fused rowsum + column partials.
#define LDA 72
#define L_AST (128 * LDA)
#define L_SST (2 * L_AST)
__global__ __launch_bounds__(256, 2) void k_logits_mma() {
    extern __shared__ __nv_bfloat16 sm_l[];
    int t = threadIdx.x, lane = t & 31, wid = t >> 5;
    int tok0 = blockIdx.x * 128;
    int wm = wid & 1, wn = wid >> 1;
    float acc[4][4][4];
    #pragma unroll
    for (int a = 0; a < 4; a++)
        #pragma unroll
        for (int n = 0; n < 4; n++)
            #pragma unroll
            for (int q = 0; q < 4; q++) acc[a][n][q] = 0.f;

    int a_row = lane & 15;
    int a_col = (lane >> 4) * 8;
    int b_row = (lane & 7) + ((lane >> 4) << 3);
    int b_col = ((lane >> 3) & 1) * 8;

    #define L_LOAD(c, s) do { \
        __nv_bfloat16* base = sm_l + (s) * L_SST; \
        _Pragma("unroll") \
        for (int i = 0; i < 4; i++) { \
            int idx = t + i * 256; \
            int row = idx >> 3, q = idx & 7; \
            size_t ga = (size_t)(tok0 + row) * DD + (c) * 64 + q * 8; \
            size_t gb = (size_t)row * DD + (c) * 64 + q * 8; \
            int so = row * LDA + q * 8; \
            cp_async16(smem_u32(base + so), &g_xh[ga]); \
            cp_async16(smem_u32(base + L_AST + so), &g_phinth[gb]); \
        } \
    } while (0)

    L_LOAD(0, 0); CP_COMMIT();
    L_LOAD(1, 1); CP_COMMIT();
    for (int c = 0; c < 16; c++) {
        CP_WAIT1();
        __syncthreads();
        if (c + 2 < 16) L_LOAD(c + 2, (c + 2) % 3);
        CP_COMMIT();
        __nv_bfloat16* sAh = sm_l + (c % 3) * L_SST;
        __nv_bfloat16* sBh = sAh + L_AST;
        #pragma unroll
        for (int ks = 0; ks < 4; ks++) {
            uint32_t ah[4][4], bh[4][2];
            #pragma unroll
            for (int a = 0; a < 4; a++) {
                int off = (wm * 64 + a * 16 + a_row) * LDA + ks * 16 + a_col;
                ldsm_x4(ah[a][0], ah[a][1], ah[a][2], ah[a][3], smem_u32(&sAh[off]));
            }
            #pragma unroll
            for (int p = 0; p < 2; p++) {
                int off = (wn * 32 + p * 16 + b_row) * LDA + ks * 16 + b_col;
                uint32_t r0, r1, r2, r3;
                ldsm_x4(r0, r1, r2, r3, smem_u32(&sBh[off]));
                bh[p * 2][0] = r0; bh[p * 2][1] = r1;
                bh[p * 2 + 1][0] = r2; bh[p * 2 + 1][1] = r3;
            }
            #pragma unroll
            for (int a = 0; a < 4; a++)
                #pragma unroll
                for (int n = 0; n < 4; n++)
                    mma_bf16(acc[a][n], ah[a], bh[n]);
        }
    }
    // epilogue: exp2, store bf16; accumulate row/col sums (fp32, pre-rounding)
    int r0 = lane >> 2, c0 = (lane & 3) * 2;
    float rsum[4][2];
    float csum[4][2];
    #pragma unroll
    for (int a = 0; a < 4; a++) { rsum[a][0] = 0.f; rsum[a][1] = 0.f; }
    #pragma unroll
    for (int n = 0; n < 4; n++) { csum[n][0] = 0.f; csum[n][1] = 0.f; }
    __syncthreads();
    #pragma unroll
    for (int a = 0; a < 4; a++) {
        int row = tok0 + wm * 64 + a * 16 + r0;
        float rv0 = g_rinv[row] * LOG2E;
        float rv1 = g_rinv[row + 8] * LOG2E;
        #pragma unroll
        for (int n = 0; n < 4; n++) {
            int col = wn * 32 + n * 8 + c0;
            float e0 = ex2f(acc[a][n][0] * rv0), e1 = ex2f(acc[a][n][1] * rv0);
            float e2 = ex2f(acc[a][n][2] * rv1), e3 = ex2f(acc[a][n][3] * rv1);
            rsum[a][0] += e0 + e1;
            rsum[a][1] += e2 + e3;
            csum[n][0] += e0 + e2;
            csum[n][1] += e1 + e3;
            *reinterpret_cast<__nv_bfloat162*>(&g_Eh[(size_t)row * NP + col]) =
                __halves2bfloat162(__float2bfloat16_rn(e0), __float2bfloat16_rn(e1));
            *reinterpret_cast<__nv_bfloat162*>(&g_Eh[(size_t)(row + 8) * NP + col]) =
                __halves2bfloat162(__float2bfloat16_rn(e2), __float2bfloat16_rn(e3));
        }
    }
    float* srow = reinterpret_cast<float*>(sm_l);   // [4 wn][128 rows]
    float* scol = srow + 4 * 128;                   // [2 wm][128 cols]
    __syncthreads();
    #pragma unroll
    for (int a = 0; a < 4; a++)
        #pragma unroll
        for (int h = 0; h < 2; h++) {
            float v = rsum[a][h];
            v += __shfl_xor_sync(0xffffffffu, v, 1);
            v += __shfl_xor_sync(0xffffffffu, v, 2);
            if ((lane & 3) == 0)
                srow[wn * 128 + wm * 64 + a * 16 + h * 8 + r0] = v;
        }
    #pragma unroll
    for (int n = 0; n < 4; n++)
        #pragma unroll
        for (int q1 = 0; q1 < 2; q1++) {
            float v = csum[n][q1];
            v += __shfl_xor_sync(0xffffffffu, v, 4);
            v += __shfl_xor_sync(0xffffffffu, v, 8);
            v += __shfl_xor_sync(0xffffffffu, v, 16);
            if (lane < 4)
                scol[wm * 128 + wn * 32 + n * 8 + lane * 2 + q1] = v;
        }
    __syncthreads();
    if (t < 128) {
        float rs = srow[t] + srow[128 + t] + srow[256 + t] + srow[384 + t];
        g_rsinv[tok0 + t] = 1.0f / rs;
        g_part[blockIdx.x * NP + t] = scol[t] + scol[128 + t];
    }
}

// ===========================================================================
// K5 (mma, cp.async 3-stage, k-chunk=64):
// xspb[seg][b][np][d] = sum_{m in seg} E[m][np]*x[m][d].  CTA 128np x 128d.
#define LDE 136
#define X_AST (64 * LDE)
#define X_SST (2 * X_AST)
__global__ __launch_bounds__(256, 2) void k_xs_mma() {
    extern __shared__ __nv_bfloat16 sm_x[];
    int t = threadIdx.x, lane = t & 31, wid = t >> 5;
    int d0 = blockIdx.x * 128;
    int b = blockIdx.y;
    int seg = blockIdx.z;
    int base = b * MM + seg * 1024;
    int wm = wid & 1, wn = wid >> 1;
    float acc[4][4][4];
    #pragma unroll
    for (int a = 0; a < 4; a++)
        #pragma unroll
        for (int n = 0; n < 4; n++)
            #pragma unroll
            for (int q = 0; q < 4; q++) acc[a][n][q] = 0.f;

    int aA_col = ((lane >> 3) & 1) * 8;
    int aA_row = (lane & 7) + (lane >> 4) * 8;
    int aB_row = (lane & 7) + ((lane >> 3) & 1) * 8;
    int aB_col = (lane >> 4) * 8;

    #define X_LOAD(c, s) do { \
        __nv_bfloat16* bb_ = sm_x + (s) * X_SST; \
        _Pragma("unroll") \
        for (int i = 0; i < 4; i++) { \
            int idx = t + i * 256; \
            int row = idx >> 4, q = idx & 15; \
            size_t ge = (size_t)(base + (c) * 64 + row) * NP + q * 8; \
            size_t gx = (size_t)(base + (c) * 64 + row) * DD + d0 + q * 8; \
            int so = row * LDE + q * 8; \
            cp_async16(smem_u32(bb_ + so), &g_Eh[ge]); \
            cp_async16(smem_u32(bb_ + X_AST + so), &g_xh[gx]); \
        } \
    } while (0)

    X_LOAD(0, 0); CP_COMMIT();
    X_LOAD(1, 1); CP_COMMIT();
    for (int c = 0; c < 16; c++) {
        CP_WAIT1();
        __syncthreads();
        if (c + 2 < 16) X_LOAD(c + 2, (c + 2) % 3);
        CP_COMMIT();
        __nv_bfloat16* sEh = sm_x + (c % 3) * X_SST;
        __nv_bfloat16* sXh = sEh + X_AST;
        #pragma unroll
        for (int ks = 0; ks < 4; ks++) {
            uint32_t ah[4][4], bh[4][2];
            #pragma unroll
            for (int a = 0; a < 4; a++) {
                int npb = wm * 64 + a * 16 + aA_col;
                int off = (ks * 16 + aA_row) * LDE + npb;
                ldsm_x4t(ah[a][0], ah[a][1], ah[a][2], ah[a][3], smem_u32(&sEh[off]));
            }
            #pragma unroll
            for (int p = 0; p < 2; p++) {
                int nb = wn * 32 + p * 16 + aB_col;
                int off = (ks * 16 + aB_row) * LDE + nb;
                uint32_t r0, r1, r2, r3;
                ldsm_x4t(r0, r1, r2, r3, smem_u32(&sXh[off]));
                bh[p * 2][0] = r0; bh[p * 2][1] = r1;
                bh[p * 2 + 1][0] = r2; bh[p * 2 + 1][1] = r3;
            }
            #pragma unroll
            for (int a = 0; a < 4; a++)
                #pragma unroll
                for (int n = 0; n < 4; n++)
                    mma_bf16(acc[a][n], ah[a], bh[n]);
        }
    }
    int r0 = lane >> 2, c0 = (lane & 3) * 2;
    #pragma unroll
    for (int a = 0; a < 4; a++) {
        int np = wm * 64 + a * 16 + r0;
        #pragma unroll
        for (int n = 0; n < 4; n++) {
            int d = d0 + wn * 32 + n * 8 + c0;
            size_t o0 = (((size_t)seg * BB + b) * NP + np) * DD + d;
            size_t o1 = (((size_t)seg * BB + b) * NP + np + 8) * DD + d;
            *reinterpret_cast<__nv_bfloat162*>(&g_xspb[o0]) =
                __halves2bfloat162(__float2bfloat16_rn(acc[a][n][0]),
                                   __float2bfloat16_rn(acc[a][n][1]));
            *reinterpret_cast<__nv_bfloat162*>(&g_xspb[o1]) =
                __halves2bfloat162(__float2bfloat16_rn(acc[a][n][2]),
                                   __float2bfloat16_rn(acc[a][n][3]));
        }
    }
}

// ===========================================================================
// K6 (mma, cp.async W staging): ys[(b,p)][e] = sum_d xs*W + bias.
// K chunks of 32; W staged fp32 via cp.async (2 stages), converted from smem.
// Colsum reduce folded in (reads g_part directly); A from bf16 xspb.
#define LDW 264
#define LDK 40
#define YLDWF 264                         // fp32 stage row stride (floats)
#define Y_FST (32 * YLDWF)                // floats per W stage
#define Y_WT (32 * LDW)                   // bf16 elems per W tile
#define Y_AT (16 * LDK)                   // bf16 elems per A tile
__global__ __launch_bounds__(256) void k_ys_mma(const float* __restrict__ W,
                                                const float* __restrict__ bias) {
    extern __shared__ char sm_raw_y[];
    float* sWf = reinterpret_cast<float*>(sm_raw_y);                 // 2 stages fp32
    __nv_bfloat16* sWh = reinterpret_cast<__nv_bfloat16*>(sm_raw_y + 2 * Y_FST * 4); // 2 tiles
    __nv_bfloat16* sAh = sWh + 2 * Y_WT;                             // 2 tiles
    int t = threadIdx.x, lane = t & 31, wid = t >> 5;
    int nexp = blockIdx.y;
    int e0 = blockIdx.x * 256;
    float acc[4][4];
    #pragma unroll
    for (int n = 0; n < 4; n++)
        #pragma unroll
        for (int q = 0; q < 4; q++) acc[n][q] = 0.f;

    int a_row = lane & 15;
    int a_col = (lane >> 4) * 8;
    int aB_row = (lane & 7) + ((lane >> 3) & 1) * 8;
    int aB_col = (lane >> 4) * 8;

    // folded colsum: per-thread A row state (t<128)
    int arow = t >> 3, aq = t & 7;        // row 0..15, col-group 0..7 (4 elems)
    int abb = arow >> 1, ap = arow & 1;
    float ainv = 0.f;
    if (t < 128) {
        int npi = nexp * 2 + ap;
        float cs = 0.f;
        #pragma unroll
        for (int i = 0; i < 32; i++)
            cs += g_part[(abb * 32 + i) * NP + npi];
        ainv = 1.0f / cs;
    }
    size_t abase = ((size_t)abb * NP + nexp * 2 + ap) * DD + aq * 4;

    // W stage load: 32 k-rows x 256 e = 2048 float4; 8 per thread
    #define Y_LOAD(c, s) do { \
        float* dst = sWf + (s) * Y_FST; \
        _Pragma("unroll") \
        for (int i = 0; i < 8; i++) { \
            int idx = t + i * 256; \
            int row = idx >> 6, q = idx & 63; \
            cp_async16(smem_u32(dst + row * YLDWF + q * 4), \
                       &W[((size_t)nexp * DD + (c) * 32 + row) * DD + e0 + q * 4]); \
        } \
    } while (0)

    Y_LOAD(0, 0);
    CP_COMMIT();
    Y_LOAD(1, 1);
    CP_COMMIT();
    for (int c = 0; c < 32; c++) {
        CP_WAIT1();
        __syncthreads();
        // convert W stage -> bf16 tile (each thread 4x8 floats)
        {
            const float* src = sWf + (c & 1) * Y_FST;
            __nv_bfloat16* dst = sWh + (c & 1) * Y_WT;
            #pragma unroll
            for (int i = 0; i < 4; i++) {
                int idx = t + i * 256;
                int row = idx >> 5, q = idx & 31;    // 32 rows x 32 groups of 8
                const float* sp = src + row * YLDWF + q * 8;
                float4 v0 = *reinterpret_cast<const float4*>(sp);
                float4 v1 = *reinterpret_cast<const float4*>(sp + 4);
                uint32_t hs[8];
                hs[0] = (uint32_t)__bfloat16_as_ushort(__float2bfloat16_rn(v0.x));
                hs[1] = (uint32_t)__bfloat16_as_ushort(__float2bfloat16_rn(v0.y));
                hs[2] = (uint32_t)__bfloat16_as_ushort(__float2bfloat16_rn(v0.z));
                hs[3] = (uint32_t)__bfloat16_as_ushort(__float2bfloat16_rn(v0.w));
                hs[4] = (uint32_t)__bfloat16_as_ushort(__float2bfloat16_rn(v1.x));
                hs[5] = (uint32_t)__bfloat16_as_ushort(__float2bfloat16_rn(v1.y));
                hs[6] = (uint32_t)__bfloat16_as_ushort(__float2bfloat16_rn(v1.z));
                hs[7] = (uint32_t)__bfloat16_as_ushort(__float2bfloat16_rn(v1.w));
                uint4 hi = {hs[0] | (hs[1] << 16), hs[2] | (hs[3] << 16),
                            hs[4] | (hs[5] << 16), hs[6] | (hs[7] << 16)};
                *reinterpret_cast<uint4*>(&dst[row * LDW + q * 8]) = hi;
            }
        }
        // A tile: 16 rows x 32 k, 4-seg bf16 sum * ainv, convert
        if (t < 128) {
            size_t off = abase + c * 32;
            float s0 = 0.f, s1 = 0.f, s2 = 0.f, s3 = 0.f;
            #pragma unroll
            for (int seg = 0; seg < 4; seg++) {
                uint2 pk = *reinterpret_cast<const uint2*>(
                    &g_xspb[(size_t)seg * BB * NP * DD + off]);
                __nv_bfloat162 p0 = *reinterpret_cast<const __nv_bfloat162*>(&pk.x);
                __nv_bfloat162 p1 = *reinterpret_cast<const __nv_bfloat162*>(&pk.y);
                s0 += __bfloat162float(p0.x); s1 += __bfloat162float(p0.y);
                s2 += __bfloat162float(p1.x); s3 += __bfloat162float(p1.y);
            }
            uint32_t h0 = (uint32_t)__bfloat16_as_ushort(__float2bfloat16_rn(s0 * ainv));
            uint32_t h1 = (uint32_t)__bfloat16_as_ushort(__float2bfloat16_rn(s1 * ainv));
            uint32_t h2 = (uint32_t)__bfloat16_as_ushort(__float2bfloat16_rn(s2 * ainv));
            uint32_t h3 = (uint32_t)__bfloat16_as_ushort(__float2bfloat16_rn(s3 * ainv));
            uint2 pk = {h0 | (h1 << 16), h2 | (h3 << 16)};
            *reinterpret_cast<uint2*>(&sAh[(c & 1) * Y_AT + arow * LDK + aq * 4]) = pk;
        }
        __syncthreads();
        if (c + 2 < 32) { Y_LOAD(c + 2, c & 1); }
        CP_COMMIT();
        // mma on tile (c&1)
        __nv_bfloat16* tW = sWh + (c & 1) * Y_WT;
        __nv_bfloat16* tA = sAh + (c & 1) * Y_AT;
        #pragma unroll
        for (int ks = 0; ks < 2; ks++) {
            uint32_t ah[4], bh[4][2];
            {
                int off = a_row * LDK + ks * 16 + a_col;
                ldsm_x4(ah[0], ah[1], ah[2], ah[3], smem_u32(&tA[off]));
            }
            #pragma unroll
            for (int p = 0; p < 2; p++) {
                int nb = wid * 32 + p * 16 + aB_col;
                int off = (ks * 16 + aB_row) * LDW + nb;
                uint32_t r0, r1, r2, r3;
                ldsm_x4t(r0, r1, r2, r3, smem_u32(&tW[off]));
                bh[p * 2][0] = r0; bh[p * 2][1] = r1;
                bh[p * 2 + 1][0] = r2; bh[p * 2 + 1][1] = r3;
            }
            #pragma unroll
            for (int n = 0; n < 4; n++)
                mma_bf16(acc[n], ah, bh[n]);
        }
    }
    int r0 = lane >> 2, c0 = (lane & 3) * 2;
    #pragma unroll
    for (int n = 0; n < 4; n++) {
        int e = e0 + wid * 32 + n * 8 + c0;
        float2 bv = *reinterpret_cast<const float2*>(&bias[nexp * DD + e]);
        #pragma unroll
        for (int h = 0; h < 2; h++) {
            int row = r0 + h * 8;
            int bb = row >> 1, p = row & 1;
            float v0 = acc[n][h * 2 + 0] + bv.x;
            float v1 = acc[n][h * 2 + 1] + bv.y;
            size_t o = ((size_t)bb * NP + nexp * 2 + p) * DD + e;
            *reinterpret_cast<__nv_bfloat162*>(&g_ysh[o]) =
                __halves2bfloat162(__float2bfloat16_rn(v0), __float2bfloat16_rn(v1));
        }
    }
}

// ===========================================================================
// K7 (mma, cp.async 3-stage): y[m][d] = rsinv[m]*sum_np E[m][np]*ys[np][d] + x[m][d]
#define CLDA 40
#define C_ASZ (128 * CLDA)
#define C_BSZ (32 * LDE)
#define C_SST (C_ASZ + C_BSZ)
__global__ __launch_bounds__(256) void k_combine_mma(const float* __restrict__ x,
                                                     float* __restrict__ y) {
    extern __shared__ __nv_bfloat16 sm_c[];
    int t = threadIdx.x, lane = t & 31, wid = t >> 5;
    int b = blockIdx.z;
    int tokbase = b * MM + blockIdx.x * 128;
    int d0 = blockIdx.y * 128;
    int wm = wid & 1, wn = wid >> 1;
    float acc[4][4][4];
    #pragma unroll
    for (int a = 0; a < 4; a++)
        #pragma unroll
        for (int n = 0; n < 4; n++)
            #pragma unroll
            for (int q = 0; q < 4; q++) acc[a][n][q] = 0.f;

    int a_row = lane & 15;
    int a_col = (lane >> 4) * 8;
    int aB_row = (lane & 7) + ((lane >> 3) & 1) * 8;
    int aB_col = (lane >> 4) * 8;

    #define C_LOAD(c, s) do { \
        __nv_bfloat16* base = sm_c + (s) * C_SST; \
        _Pragma("unroll") \
        for (int i = 0; i < 2; i++) { \
            int idx = t + i * 256; \
            int row = idx >> 2, q = idx & 3; \
            size_t ge = (size_t)(tokbase + row) * NP + (c) * 32 + q * 8; \
            cp_async16(smem_u32(base + row * CLDA + q * 8), &g_Eh[ge]); \
            int rowb = idx >> 4, qb = idx & 15; \
            size_t gy = ((size_t)b * NP + (c) * 32 + rowb) * DD + d0 + qb * 8; \
            cp_async16(smem_u32(base + C_ASZ + rowb * LDE + qb * 8), &g_ysh[gy]); \
        } \
    } while (0)

    C_LOAD(0, 0);
    CP_COMMIT();
    C_LOAD(1, 1);
    CP_COMMIT();
    for (int c = 0; c < 4; c++) {
        CP_WAIT1();
        __syncthreads();
        if (c + 2 < 4) C_LOAD(c + 2, (c + 2) % 3);
        CP_COMMIT();
        __nv_bfloat16* sAh = sm_c + (c % 3) * C_SST;
        __nv_bfloat16* sBh = sAh + C_ASZ;
        #pragma unroll
        for (int ks = 0; ks < 2; ks++) {
            uint32_t ah[4][4], bh[4][2];
            #pragma unroll
            for (int a = 0; a < 4; a++) {
                int off = (wm * 64 + a * 16 + a_row) * CLDA + ks * 16 + a_col;
                ldsm_x4(ah[a][0], ah[a][1], ah[a][2], ah[a][3], smem_u32(&sAh[off]));
            }
            #pragma unroll
            for (int p = 0; p < 2; p++) {
                int nb = wn * 32 + p * 16 + aB_col;
                int off = (ks * 16 + aB_row) * LDE + nb;
                uint32_t r0, r1, r2, r3;
                ldsm_x4t(r0, r1, r2, r3, smem_u32(&sBh[off]));
                bh[p * 2][0] = r0; bh[p * 2][1] = r1;
                bh[p * 2 + 1][0] = r2; bh[p * 2 + 1][1] = r3;
            }
            #pragma unroll
            for (int a = 0; a < 4; a++)
                #pragma unroll
                for (int n = 0; n < 4; n++)
                    mma_bf16(acc[a][n], ah[a], bh[n]);
        }
    }
    int r0 = lane >> 2, c0 = (lane & 3) * 2;
    #pragma unroll
    for (int a = 0; a < 4; a++) {
        int m0 = tokbase + wm * 64 + a * 16 + r0;
        float rs0 = g_rsinv[m0];
        float rs1 = g_rsinv[m0 + 8];
        #pragma unroll
        for (int n = 0; n < 4; n++) {
            int d = d0 + wn * 32 + n * 8 + c0;
            size_t i0 = (size_t)m0 * DD + d;
            size_t i1 = (size_t)(m0 + 8) * DD + d;
            float2 xv0 = *reinterpret_cast<const float2*>(&x[i0]);
            float2 xv1 = *reinterpret_cast<const float2*>(&x[i1]);
            *reinterpret_cast<float2*>(&y[i0]) =
                make_float2(acc[a][n][0] * rs0 + xv0.x, acc[a][n][1] * rs0 + xv0.y);
            *reinterpret_cast<float2*>(&y[i1]) =
                make_float2(acc[a][n][2] * rs1 + xv1.x, acc[a][n][3] * rs1 + xv1.y);
        }
    }
}

// ---------------------------------------------------------------------------
extern "C" void kernel_launch(void* const* d_in, const int* in_sizes, int n_in,
                              void* d_out, int out_size) {
    const float* x     = (const float*)d_in[0];  // [8,4096,1024]
    const float* phi   = (const float*)d_in[1];  // [1024,64,2]
    const float* scale = (const float*)d_in[2];  // [1]
    const float* W     = (const float*)d_in[3];  // [64,1024,1024]
    const float* bias  = (const float*)d_in[4];  // [64,1024]
    float* y = (float*)d_out;                    // [8,4096,1024]

    const int smem_logits  = 3 * L_SST * 2;                             // 110592
    const int smem_xs      = 3 * X_SST * 2;                             // 104448
    const int smem_ys      = 2 * Y_FST * 4 + 2 * Y_WT * 2 + 2 * Y_AT * 2; // 104448
    const int smem_combine = 3 * C_SST * 2;                             // 56832
    cudaFuncSetAttribute(k_logits_mma, cudaFuncAttributeMaxDynamicSharedMemorySize, smem_logits);
    cudaFuncSetAttribute(k_xs_mma, cudaFuncAttributeMaxDynamicSharedMemorySize, smem_xs);
    cudaFuncSetAttribute(k_ys_mma, cudaFuncAttributeMaxDynamicSharedMemorySize, smem_ys);
    cudaFuncSetAttribute(k_combine_mma, cudaFuncAttributeMaxDynamicSharedMemorySize, smem_combine);

    k_phinorm<<<NP, 256>>>(phi, scale);
    k_rinv<<<BM / 8, 256>>>(x);
    k_logits_mma<<<BM / 128, 256, smem_logits>>>();
    k_xs_mma<<<dim3(8, BB, 4), 256, smem_xs>>>();
    k_ys_mma<<<dim3(4, NEXP), 256, smem_ys>>>(W, bias);
    k_combine_mma<<<dim3(32, 8, BB), 256, smem_combine>>>(x, y);
}